// round 7
// baseline (speedup 1.0000x reference)
#include <cuda_runtime.h>
#include <cuda_bf16.h>
#include <math.h>
#include <stdint.h>

// ---------------------------------------------------------------------------
// Problem constants
// ---------------------------------------------------------------------------
#define SEQ_LEN   8
#define D_MODEL   2048
#define OUT_DIM   1152
#define WAY       5
#define SHOT      5
#define N_SUPPORT 25
#define N_QUERIES 200
#define N_TOTAL   225
#define L_TUP     28
#define TWO_D     4096
#define NSTACK    4608          // 4 * OUT_DIM (k h0, k h1, v h0, v h1)
#define ROWS_X    1800          // N_TOTAL * SEQ_LEN
#define ROWS_Q    5600          // N_QUERIES * L_TUP
#define ROWS_S    700           // N_SUPPORT * L_TUP
#define SEG       140           // SHOT * L_TUP
#define PLANE     32256         // L_TUP * OUT_DIM

// hi/lo widths (per-part K; rows store [hi(KH) | lo(KH)])
#define KH_BIG    2048
#define KH_SC     1152
#define KH_PR     160           // 140 padded to 160 (multiple of 16)

__constant__ int c_t0[L_TUP] = {0,0,0,0,0,0,0,1,1,1,1,1,1,2,2,2,2,2,3,3,3,3,4,4,4,5,5,6};
__constant__ int c_t1[L_TUP] = {1,2,3,4,5,6,7,2,3,4,5,6,7,3,4,5,6,7,4,5,6,7,5,6,7,6,7,7};

// ---------------------------------------------------------------------------
// Scratch (device globals; no allocation allowed)
// ---------------------------------------------------------------------------
__device__ __nv_bfloat16  g_Xhl[(size_t)ROWS_X * 2 * KH_BIG];
__device__ __nv_bfloat16  g_Whl[(size_t)NSTACK * 2 * KH_BIG];
__device__ float          g_P[(size_t)ROWS_X * NSTACK];
__device__ float          g_vs_s[ROWS_S * OUT_DIM];
__device__ float          g_vs_q[ROWS_Q * OUT_DIM];
__device__ __nv_bfloat16  g_KQhl[(size_t)ROWS_Q * 2 * KH_SC];
__device__ __nv_bfloat16  g_KShl[(size_t)ROWS_S * 2 * KH_SC];
__device__ float          g_S[(size_t)ROWS_Q * ROWS_S];
__device__ __nv_bfloat16  g_Ahl[(size_t)WAY * ROWS_Q * 2 * KH_PR];
__device__ __nv_bfloat16  g_Vhl[(size_t)WAY * OUT_DIM * 2 * KH_PR];
__device__ float          g_proto[(size_t)WAY * ROWS_Q * OUT_DIM];

// ---------------------------------------------------------------------------
// Helpers
// ---------------------------------------------------------------------------
__device__ __forceinline__ uint32_t smem_u32(const void* p) {
    uint32_t a;
    asm("{ .reg .u64 t; cvta.to.shared.u64 t, %1; cvt.u32.u64 %0, t; }"
        : "=r"(a) : "l"(p));
    return a;
}

#define CP16(dst, src) \
    asm volatile("cp.async.cg.shared.global [%0], [%1], 16;" :: "r"(dst), "l"(src))
#define CP_COMMIT() asm volatile("cp.async.commit_group;" ::: "memory")
#define CP_WAIT(n)  asm volatile("cp.async.wait_group %0;" :: "n"(n) : "memory")

__device__ __forceinline__ void split2(float x, __nv_bfloat16& hi, __nv_bfloat16& lo) {
    hi = __float2bfloat16(x);
    lo = __float2bfloat16(x - __bfloat162float(hi));
}

// swizzled 16B-chunk offset within a 128rows x 16cols bf16 tile (4KB)
__device__ __forceinline__ uint32_t tswz(int row, int cq) {
    return (uint32_t)(row * 32 + ((cq ^ ((row >> 2) & 1)) << 4));
}

#define LDMX4(d0,d1,d2,d3,addr) \
    asm volatile("ldmatrix.sync.aligned.m8n8.x4.shared.b16 {%0,%1,%2,%3}, [%4];" \
        : "=r"(d0), "=r"(d1), "=r"(d2), "=r"(d3) : "r"(addr))

#define MMA16816(acc, a, b) \
    asm volatile("mma.sync.aligned.m16n8k16.row.col.f32.bf16.bf16.f32 " \
        "{%0,%1,%2,%3}, {%4,%5,%6,%7}, {%8,%9}, {%0,%1,%2,%3};" \
        : "+f"((acc)[0]), "+f"((acc)[1]), "+f"((acc)[2]), "+f"((acc)[3]) \
        : "r"((a)[0]), "r"((a)[1]), "r"((a)[2]), "r"((a)[3]), \
          "r"((b)[0]), "r"((b)[1]))

// ---------------------------------------------------------------------------
// Split-aware bf16 GEMM:
//   C[M,N] = alpha * (Ahi*Bhi + Ahi*Blo + Alo*Bhi)     (lo*lo term dropped)
// A, B rows store [hi(KH) | lo(KH)] bf16 K-major. 128x128 CTA tile, BK=16,
// 4-stage cp.async pipeline (stage = Ahi|Alo|Bhi|Blo tiles, 4KB each),
// single barrier per super-chunk, 8 warps (2x4), warp tile 64x32,
// register fragment reuse (Ahi reused for t1/t2, Bhi for t1/t3).
// Batched over blockIdx.z via strides. 2 CTAs/SM. KH multiple of 16.
// OOB rows clamped (their outputs never stored).
//
// ldmatrix lane mapping used here: frow = lane&15, fcq = lane>>4, so the
// four 8x8 matrices arrive as (rows0-7,k0-7),(rows8-15,k0-7),
// (rows0-7,k8-15),(rows8-15,k8-15). For A that is exactly {a0,a1,a2,a3}.
// For B (two n-groups per x4) it is {b[n][0], b[n+1][0], b[n][1], b[n+1][1]}.
// ---------------------------------------------------------------------------
__global__ __launch_bounds__(256, 2)
void gemm_split(const __nv_bfloat16* __restrict__ A, const __nv_bfloat16* __restrict__ B,
                float* __restrict__ C, int M, int N, int KH, float alpha,
                size_t aStride, size_t bStride, size_t cStride)
{
    __shared__ uint4 sbuf[4][1024];    // 4 stages x 16KB

    A += (size_t)blockIdx.z * aStride;
    B += (size_t)blockIdx.z * bStride;
    C += (size_t)blockIdx.z * cStride;

    const int tid  = threadIdx.x;
    const int lane = tid & 31;
    const int wid  = tid >> 5;
    const int wm   = wid >> 2;         // 0..1
    const int wn   = wid & 3;          // 0..3
    const int row0 = blockIdx.y * 128;
    const int col0 = blockIdx.x * 128;
    const int lda  = 2 * KH;

    // loader mapping: thread t -> tile row t>>1, 16B chunk t&1
    const int lrow = tid >> 1;
    const int lcq  = tid & 1;
    const uint32_t lsw = tswz(lrow, lcq);
    int ra = row0 + lrow; if (ra > M - 1) ra = M - 1;
    int rb = col0 + lrow; if (rb > N - 1) rb = N - 1;
    const __nv_bfloat16* gA = A + (size_t)ra * lda + lcq * 8;
    const __nv_bfloat16* gB = B + (size_t)rb * lda + lcq * 8;

    const int NC = KH >> 4;            // super-chunks of 16 K-columns

    auto issue = [&](int stage, int c) {
        uint32_t base = smem_u32(&sbuf[stage][0]);
        CP16(base +          lsw, gA + c * 16);           // A hi
        CP16(base + 4096u +  lsw, gA + KH + c * 16);      // A lo
        CP16(base + 8192u +  lsw, gB + c * 16);           // B hi
        CP16(base + 12288u + lsw, gB + KH + c * 16);      // B lo
        CP_COMMIT();
    };

    float acc[4][4][4];
    #pragma unroll
    for (int mi = 0; mi < 4; mi++)
        #pragma unroll
        for (int ni = 0; ni < 4; ni++)
            #pragma unroll
            for (int e = 0; e < 4; e++) acc[mi][ni][e] = 0.f;

    const int frow = lane & 15;        // fragment row within 16
    const int fcq  = lane >> 4;        // fragment 16B chunk (k half)

    auto compute = [&](int stage) {
        uint32_t base = smem_u32(&sbuf[stage][0]);

        // A-hi fragments (kept live through t1, t2)
        uint32_t af[4][4];
        #pragma unroll
        for (int mi = 0; mi < 4; mi++) {
            int row = wm * 64 + mi * 16 + frow;
            LDMX4(af[mi][0], af[mi][1], af[mi][2], af[mi][3], base + tswz(row, fcq));
        }
        // B-hi fragments (kept live through t1, t3)
        // matrices arrive (n rows0-7,k0-7),(n rows8-15,k0-7),(rows0-7,k8-15),(rows8-15,k8-15)
        uint32_t bh[4][2];
        #pragma unroll
        for (int nh = 0; nh < 2; nh++) {
            int row = wn * 32 + nh * 16 + frow;
            LDMX4(bh[2*nh][0], bh[2*nh+1][0], bh[2*nh][1], bh[2*nh+1][1],
                  base + 8192u + tswz(row, fcq));
        }
        // t1 = Ahi * Bhi
        #pragma unroll
        for (int mi = 0; mi < 4; mi++)
            #pragma unroll
            for (int ni = 0; ni < 4; ni++)
                MMA16816(acc[mi][ni], af[mi], bh[ni]);
        // B-lo fragments
        {
            uint32_t bl[4][2];
            #pragma unroll
            for (int nh = 0; nh < 2; nh++) {
                int row = wn * 32 + nh * 16 + frow;
                LDMX4(bl[2*nh][0], bl[2*nh+1][0], bl[2*nh][1], bl[2*nh+1][1],
                      base + 12288u + tswz(row, fcq));
            }
            // t2 = Ahi * Blo  (reuses af)
            #pragma unroll
            for (int mi = 0; mi < 4; mi++)
                #pragma unroll
                for (int ni = 0; ni < 4; ni++)
                    MMA16816(acc[mi][ni], af[mi], bl[ni]);
        }
        // A-lo fragments
        {
            uint32_t al[4][4];
            #pragma unroll
            for (int mi = 0; mi < 4; mi++) {
                int row = wm * 64 + mi * 16 + frow;
                LDMX4(al[mi][0], al[mi][1], al[mi][2], al[mi][3],
                      base + 4096u + tswz(row, fcq));
            }
            // t3 = Alo * Bhi  (reuses bh)
            #pragma unroll
            for (int mi = 0; mi < 4; mi++)
                #pragma unroll
                for (int ni = 0; ni < 4; ni++)
                    MMA16816(acc[mi][ni], al[mi], bh[ni]);
        }
    };

    // 4-stage pipeline: wait -> barrier -> issue(c+3) -> compute(c)
    issue(0, 0);
    if (NC > 1) issue(1, 1);
    if (NC > 2) issue(2, 2);
    for (int c = 0; c < NC; c++) {
        if (c + 2 < NC)      CP_WAIT(2);
        else if (c + 1 < NC) CP_WAIT(1);
        else                 CP_WAIT(0);
        __syncthreads();
        if (c + 3 < NC) issue((c + 3) & 3, c + 3);
        compute(c & 3);
    }

    // epilogue: float2 stores
    const int g  = lane >> 2;
    const int tg = lane & 3;
    #pragma unroll
    for (int mi = 0; mi < 4; mi++) {
        int rr0 = row0 + wm * 64 + mi * 16 + g;
        int rr1 = rr0 + 8;
        #pragma unroll
        for (int ni = 0; ni < 4; ni++) {
            int cc = col0 + wn * 32 + ni * 8 + tg * 2;
            if (cc < N) {
                if (rr0 < M) {
                    float2 v = make_float2(alpha * acc[mi][ni][0], alpha * acc[mi][ni][1]);
                    *(float2*)(C + (size_t)rr0 * N + cc) = v;
                }
                if (rr1 < M) {
                    float2 v = make_float2(alpha * acc[mi][ni][2], alpha * acc[mi][ni][3]);
                    *(float2*)(C + (size_t)rr1 * N + cc) = v;
                }
            }
        }
    }
}

// ---------------------------------------------------------------------------
// Fused: X = [support; queries] + PE -> [hi | lo] layout
// ---------------------------------------------------------------------------
__global__ void conv_pe_hilo(const float* __restrict__ support,
                             const float* __restrict__ queries)
{
    int e = blockIdx.x * blockDim.x + threadIdx.x;
    if (e >= ROWS_X * D_MODEL) return;
    int n = e / (SEQ_LEN * D_MODEL);
    int rem = e % (SEQ_LEN * D_MODEL);
    int s = rem / D_MODEL, d = rem % D_MODEL;
    const float c = -9.210340371976184f / (float)D_MODEL;
    float div = expf((float)(2 * (d >> 1)) * c);
    float arg = (float)s * div;
    float pe = ((d & 1) ? cosf(arg) : sinf(arg)) * 0.1f;
    float x = ((n < N_SUPPORT) ? support[e]
                               : queries[e - N_SUPPORT * SEQ_LEN * D_MODEL]) + pe;
    __nv_bfloat16 hi, lo; split2(x, hi, lo);
    int row = e / D_MODEL;
    __nv_bfloat16* o = g_Xhl + (size_t)row * (2 * KH_BIG);
    o[d] = hi; o[KH_BIG + d] = lo;
}

// stacked weights -> [hi | lo]
__global__ void convW_kernel(const float* __restrict__ k_w, const float* __restrict__ v_w)
{
    int e = blockIdx.x * blockDim.x + threadIdx.x;
    if (e >= NSTACK * D_MODEL) return;
    int j = e / D_MODEL, k = e % D_MODEL;
    int part = j / OUT_DIM, o = j % OUT_DIM;
    const float* w = (part < 2) ? k_w : v_w;
    float x = w[(size_t)o * TWO_D + (part & 1) * D_MODEL + k];
    __nv_bfloat16 hi, lo; split2(x, hi, lo);
    __nv_bfloat16* dst = g_Whl + (size_t)j * (2 * KH_BIG);
    dst[k] = hi; dst[KH_BIG + k] = lo;
}

// vs_s^T slices -> [WAY][OUT_DIM][hi(160) | lo(160)], pad 140..159 zero
__global__ void conv_vsT_kernel()
{
    int e = blockIdx.x * blockDim.x + threadIdx.x;
    const int total = WAY * OUT_DIM * KH_PR;
    if (e >= total) return;
    int w = e / (OUT_DIM * KH_PR);
    int rem = e % (OUT_DIM * KH_PR);
    int d = rem / KH_PR, j = rem % KH_PR;
    __nv_bfloat16 hi = __float2bfloat16(0.f), lo = hi;
    if (j < SEG) {
        float x = g_vs_s[(size_t)(w * SEG + j) * OUT_DIM + d];
        split2(x, hi, lo);
    }
    __nv_bfloat16* dst = g_Vhl + ((size_t)w * OUT_DIM + d) * (2 * KH_PR);
    dst[j] = hi; dst[KH_PR + j] = lo;
}

// ---------------------------------------------------------------------------
// assemble tuple features + LayerNorm(k) -> [hi | lo] bf16, plain v float.
// ---------------------------------------------------------------------------
__global__ __launch_bounds__(256)
void assemble_kernel(const float* __restrict__ k_b, const float* __restrict__ v_b,
                     const float* __restrict__ ln_g, const float* __restrict__ ln_b)
{
    int rl = blockIdx.x;
    int n = rl / L_TUP, l = rl % L_TUP;
    int t0 = c_t0[l], t1 = c_t1[l];
    const float* P0 = g_P + (size_t)(n * SEQ_LEN + t0) * NSTACK;
    const float* P1 = g_P + (size_t)(n * SEQ_LEN + t1) * NSTACK;

    __nv_bfloat16* kd;
    float* vsd;
    if (n < N_SUPPORT) {
        kd  = g_KShl + (size_t)(n * L_TUP + l) * (2 * KH_SC);
        vsd = g_vs_s + (size_t)(n * L_TUP + l) * OUT_DIM;
    } else {
        int m = n - N_SUPPORT;
        kd  = g_KQhl + (size_t)(m * L_TUP + l) * (2 * KH_SC);
        vsd = g_vs_q + (size_t)(m * L_TUP + l) * OUT_DIM;
    }

    __shared__ float kbuf[OUT_DIM];
    float s = 0.f, s2 = 0.f;
    for (int o = threadIdx.x; o < OUT_DIM; o += blockDim.x) {
        float kv = P0[o] + P1[OUT_DIM + o] + k_b[o];
        kbuf[o] = kv; s += kv; s2 += kv * kv;
        vsd[o] = P0[2 * OUT_DIM + o] + P1[3 * OUT_DIM + o] + v_b[o];
    }
    int lane = threadIdx.x & 31, wid = threadIdx.x >> 5;
    #pragma unroll
    for (int off = 16; off; off >>= 1) {
        s  += __shfl_xor_sync(0xffffffffu, s,  off);
        s2 += __shfl_xor_sync(0xffffffffu, s2, off);
    }
    __shared__ float ws[8], ws2[8], sm_mean, sm_rstd;
    if (lane == 0) { ws[wid] = s; ws2[wid] = s2; }
    __syncthreads();
    if (threadIdx.x == 0) {
        float S = 0.f, S2 = 0.f;
        #pragma unroll
        for (int w = 0; w < 8; w++) { S += ws[w]; S2 += ws2[w]; }
        float mean = S / (float)OUT_DIM;
        float var  = S2 / (float)OUT_DIM - mean * mean;
        sm_mean = mean; sm_rstd = rsqrtf(var + 1e-5f);
    }
    __syncthreads();
    float mean = sm_mean, rstd = sm_rstd;
    for (int o = threadIdx.x; o < OUT_DIM; o += blockDim.x) {
        float y = (kbuf[o] - mean) * rstd * ln_g[o] + ln_b[o];
        __nv_bfloat16 hi, lo; split2(y, hi, lo);
        kd[o] = hi;
        kd[KH_SC + o] = lo;
    }
}

// ---------------------------------------------------------------------------
// per-row blockwise softmax; writes [hi(160) | lo(160)] attn directly.
// ---------------------------------------------------------------------------
__global__ __launch_bounds__(160)
void softmax_kernel()
{
    int row = blockIdx.x;
    int warp = threadIdx.x >> 5, lane = threadIdx.x & 31;
    const float* p = g_S + (size_t)row * ROWS_S + warp * SEG;
    float v[5]; float mx = -INFINITY;
    #pragma unroll
    for (int i = 0; i < 5; i++) {
        int c = lane + 32 * i;
        v[i] = (c < SEG) ? p[c] : -INFINITY;
        mx = fmaxf(mx, v[i]);
    }
    #pragma unroll
    for (int off = 16; off; off >>= 1)
        mx = fmaxf(mx, __shfl_xor_sync(0xffffffffu, mx, off));
    float sm = 0.f;
    #pragma unroll
    for (int i = 0; i < 5; i++) {
        int c = lane + 32 * i;
        v[i] = (c < SEG) ? expf(v[i] - mx) : 0.f;
        sm += v[i];
    }
    #pragma unroll
    for (int off = 16; off; off >>= 1)
        sm += __shfl_xor_sync(0xffffffffu, sm, off);
    float inv = 1.f / sm;

    __nv_bfloat16* a = g_Ahl + ((size_t)warp * ROWS_Q + row) * (2 * KH_PR);
    #pragma unroll
    for (int i = 0; i < 5; i++) {
        int c = lane + 32 * i;
        if (c < SEG) {
            float x = v[i] * inv;
            __nv_bfloat16 hi, lo; split2(x, hi, lo);
            a[c] = hi;
            a[KH_PR + c] = lo;
        }
    }
    if (lane < KH_PR - SEG) {          // zero pad 140..159 in both parts
        __nv_bfloat16 z = __float2bfloat16(0.f);
        a[SEG + lane] = z;
        a[KH_PR + SEG + lane] = z;
    }
}

// ---------------------------------------------------------------------------
// per-query Gram matrix + distances -> sim, ori
// ---------------------------------------------------------------------------
__global__ __launch_bounds__(256)
void finalize_kernel(float* __restrict__ out)
{
    int q = blockIdx.x;
    const float* v = g_vs_q + (size_t)q * PLANE;
    const float* pp[WAY];
    #pragma unroll
    for (int w = 0; w < WAY; w++)
        pp[w] = g_proto + (size_t)w * ROWS_Q * OUT_DIM + (size_t)q * PLANE;

    float acc[21];
    #pragma unroll
    for (int i = 0; i < 21; i++) acc[i] = 0.f;

    for (int i = threadIdx.x; i < PLANE; i += blockDim.x) {
        float vv = v[i];
        float a0 = pp[0][i], a1 = pp[1][i], a2 = pp[2][i], a3 = pp[3][i], a4 = pp[4][i];
        acc[0]  += a0 * a0;  acc[1]  += a0 * a1;  acc[2]  += a0 * a2;
        acc[3]  += a0 * a3;  acc[4]  += a0 * a4;
        acc[5]  += a1 * a1;  acc[6]  += a1 * a2;  acc[7]  += a1 * a3;  acc[8]  += a1 * a4;
        acc[9]  += a2 * a2;  acc[10] += a2 * a3;  acc[11] += a2 * a4;
        acc[12] += a3 * a3;  acc[13] += a3 * a4;
        acc[14] += a4 * a4;
        acc[15] += vv * a0;  acc[16] += vv * a1;  acc[17] += vv * a2;
        acc[18] += vv * a3;  acc[19] += vv * a4;
        acc[20] += vv * vv;
    }

    int lane = threadIdx.x & 31, wid = threadIdx.x >> 5;
    __shared__ float part[21][8];
    #pragma unroll
    for (int i = 0; i < 21; i++) {
        float a = acc[i];
        #pragma unroll
        for (int off = 16; off; off >>= 1)
            a += __shfl_xor_sync(0xffffffffu, a, off);
        if (lane == 0) part[i][wid] = a;
    }
    __syncthreads();
    __shared__ float tot[21];
    if (threadIdx.x < 21) {
        float sSum = 0.f;
        #pragma unroll
        for (int w = 0; w < 8; w++) sSum += part[threadIdx.x][w];
        tot[threadIdx.x] = sSum;
    }
    __syncthreads();
    if (threadIdx.x == 0) {
        float G[WAY][WAY];
        int t = 0;
        for (int a = 0; a < WAY; a++)
            for (int b = a; b < WAY; b++) { G[a][b] = tot[t]; G[b][a] = tot[t]; t++; }
        float D[WAY];
        for (int w = 0; w < WAY; w++) D[w] = tot[15 + w];
        float VV = tot[20];
        float nrm[WAY];
        for (int w = 0; w < WAY; w++) nrm[w] = sqrtf(G[w][w]);
        for (int a = 0; a < WAY; a++)
            for (int b = 0; b < WAY; b++)
                out[q * WAY * WAY + a * WAY + b] =
                    G[a][b] / fmaxf(nrm[a] * nrm[b], 1e-8f);
        for (int w = 0; w < WAY; w++)
            out[N_QUERIES * WAY * WAY + q * WAY + w] =
                -(VV - 2.f * D[w] + G[w][w]) / (float)L_TUP;
    }
}

// ---------------------------------------------------------------------------
// Launch
// ---------------------------------------------------------------------------
extern "C" void kernel_launch(void* const* d_in, const int* in_sizes, int n_in,
                              void* d_out, int out_size)
{
    const float* support = (const float*)d_in[0];
    const float* queries = (const float*)d_in[2];
    const float* k_w  = (const float*)d_in[3];
    const float* k_b  = (const float*)d_in[4];
    const float* v_w  = (const float*)d_in[5];
    const float* v_b  = (const float*)d_in[6];
    const float* ln_g = (const float*)d_in[7];
    const float* ln_b = (const float*)d_in[8];
    float* out = (float*)d_out;

    float *P, *S, *proto;
    __nv_bfloat16 *Xhl, *Whl, *KQhl, *KShl, *Ahl, *Vhl;
    cudaGetSymbolAddress((void**)&Xhl,   g_Xhl);
    cudaGetSymbolAddress((void**)&Whl,   g_Whl);
    cudaGetSymbolAddress((void**)&P,     g_P);
    cudaGetSymbolAddress((void**)&KQhl,  g_KQhl);
    cudaGetSymbolAddress((void**)&KShl,  g_KShl);
    cudaGetSymbolAddress((void**)&S,     g_S);
    cudaGetSymbolAddress((void**)&Ahl,   g_Ahl);
    cudaGetSymbolAddress((void**)&Vhl,   g_Vhl);
    cudaGetSymbolAddress((void**)&proto, g_proto);

    // 1. fused PE + hi/lo conversion; weight conversion
    conv_pe_hilo<<<(ROWS_X * D_MODEL + 255) / 256, 256>>>(support, queries);
    convW_kernel<<<(NSTACK * D_MODEL + 255) / 256, 256>>>(k_w, v_w);
    // 2. P = X @ Wt^T  [1800, 4608], KH=2048
    {
        dim3 grid(NSTACK / 128, (ROWS_X + 127) / 128, 1);
        gemm_split<<<grid, 256>>>(Xhl, Whl, P, ROWS_X, NSTACK, KH_BIG, 1.0f, 0, 0, 0);
    }
    // 3. assemble -> KQhl/KShl (hi|lo bf16) + vs float
    assemble_kernel<<<N_TOTAL * L_TUP, 256>>>(k_b, v_b, ln_g, ln_b);
    // 4. scores = ks_q @ ks_s^T / sqrt(OUT_DIM)  [5600, 700], KH=1152
    {
        dim3 grid((ROWS_S + 127) / 128, (ROWS_Q + 127) / 128, 1);
        gemm_split<<<grid, 256>>>(KQhl, KShl, S, ROWS_Q, ROWS_S, KH_SC,
                                  1.0f / sqrtf((float)OUT_DIM), 0, 0, 0);
    }
    // 5. softmax -> g_Ahl directly
    softmax_kernel<<<ROWS_Q, 160>>>();
    // 6. vs_s^T hi/lo for proto GEMM
    conv_vsT_kernel<<<(WAY * OUT_DIM * KH_PR + 255) / 256, 256>>>();
    // 7. proto[w] = attn_w @ vs_w  [5600, 1152], KH=160 — batched over z
    {
        dim3 grid(OUT_DIM / 128, (ROWS_Q + 127) / 128, WAY);
        gemm_split<<<grid, 256>>>(Ahl, Vhl, proto, ROWS_Q, OUT_DIM, KH_PR, 1.0f,
                                  (size_t)ROWS_Q * 2 * KH_PR,
                                  (size_t)OUT_DIM * 2 * KH_PR,
                                  (size_t)ROWS_Q * OUT_DIM);
    }
    // 8. finalize
    finalize_kernel<<<N_QUERIES, 256>>>(out);
}

// round 9
// speedup vs baseline: 1.0032x; 1.0032x over previous
#include <cuda_runtime.h>
#include <cuda_bf16.h>
#include <math.h>
#include <stdint.h>

// ---------------------------------------------------------------------------
// Problem constants
// ---------------------------------------------------------------------------
#define SEQ_LEN   8
#define D_MODEL   2048
#define OUT_DIM   1152
#define WAY       5
#define SHOT      5
#define N_SUPPORT 25
#define N_QUERIES 200
#define N_TOTAL   225
#define L_TUP     28
#define TWO_D     4096
#define NSTACK    4608          // 4 * OUT_DIM (k h0, k h1, v h0, v h1)
#define ROWS_X    1800          // N_TOTAL * SEQ_LEN
#define ROWS_Q    5600          // N_QUERIES * L_TUP
#define ROWS_S    700           // N_SUPPORT * L_TUP
#define SEG       140           // SHOT * L_TUP
#define PLANE     32256         // L_TUP * OUT_DIM

// hi/lo-split K sizes (3x concatenated: A=(hi,hi,lo), B=(hi,lo,hi))
#define KBIG      6144          // 3 * 2048   (mult of 64)
#define KSC       3456          // 3 * 1152   (mult of 64)
#define KPR       448           // 3*140=420 padded to 448 (mult of 32)

__constant__ int c_t0[L_TUP] = {0,0,0,0,0,0,0,1,1,1,1,1,1,2,2,2,2,2,3,3,3,3,4,4,4,5,5,6};
__constant__ int c_t1[L_TUP] = {1,2,3,4,5,6,7,2,3,4,5,6,7,3,4,5,6,7,4,5,6,7,5,6,7,6,7,7};

// ---------------------------------------------------------------------------
// Scratch (device globals; no allocation allowed)
// ---------------------------------------------------------------------------
__device__ __nv_bfloat16  g_Xhl[(size_t)ROWS_X * KBIG];     // A-layout (hi,hi,lo)
__device__ __nv_bfloat16  g_Whl[(size_t)NSTACK * KBIG];     // B-layout (hi,lo,hi)
__device__ float          g_P[(size_t)ROWS_X * NSTACK];
__device__ float          g_vs_s[ROWS_S * OUT_DIM];
__device__ float          g_vs_q[ROWS_Q * OUT_DIM];
__device__ __nv_bfloat16  g_KQhl[(size_t)ROWS_Q * KSC];     // A-layout (from assemble)
__device__ __nv_bfloat16  g_KShl[(size_t)ROWS_S * KSC];     // B-layout (from assemble)
__device__ float          g_S[(size_t)ROWS_Q * ROWS_S];     // scores (read-only after gemm)
__device__ __nv_bfloat16  g_Ahl[(size_t)WAY * ROWS_Q * KPR];   // attn (from softmax)
__device__ __nv_bfloat16  g_Vhl[(size_t)WAY * OUT_DIM * KPR];  // vs_s^T slices, B-layout
__device__ float          g_proto[(size_t)WAY * ROWS_Q * OUT_DIM];

// ---------------------------------------------------------------------------
// Helpers
// ---------------------------------------------------------------------------
__device__ __forceinline__ uint32_t smem_u32(const void* p) {
    uint32_t a;
    asm("{ .reg .u64 t; cvta.to.shared.u64 t, %1; cvt.u32.u64 %0, t; }"
        : "=r"(a) : "l"(p));
    return a;
}

#define CP16(dst, src) \
    asm volatile("cp.async.cg.shared.global [%0], [%1], 16;" :: "r"(dst), "l"(src))
#define CP_COMMIT() asm volatile("cp.async.commit_group;" ::: "memory")
#define CP_WAIT(n)  asm volatile("cp.async.wait_group %0;" :: "n"(n) : "memory")

__device__ __forceinline__ void split2(float x, __nv_bfloat16& hi, __nv_bfloat16& lo) {
    hi = __float2bfloat16(x);
    lo = __float2bfloat16(x - __bfloat162float(hi));
}

#define LDMX4(d0,d1,d2,d3,addr) \
    asm volatile("ldmatrix.sync.aligned.m8n8.x4.shared.b16 {%0,%1,%2,%3}, [%4];" \
        : "=r"(d0), "=r"(d1), "=r"(d2), "=r"(d3) : "r"(addr))

#define MMA16816(acc, a, b) \
    asm volatile("mma.sync.aligned.m16n8k16.row.col.f32.bf16.bf16.f32 " \
        "{%0,%1,%2,%3}, {%4,%5,%6,%7}, {%8,%9}, {%0,%1,%2,%3};" \
        : "+f"((acc)[0]), "+f"((acc)[1]), "+f"((acc)[2]), "+f"((acc)[3]) \
        : "r"((a)[0]), "r"((a)[1]), "r"((a)[2]), "r"((a)[3]), \
          "r"((b)[0]), "r"((b)[1]))

// ===========================================================================
// gemm64: BK=64 bf16 GEMM, C[M,N] = alpha * A[M,K] * B[N,K]^T
// 128x128 CTA tile, 3-stage cp.async pipeline over 32KB stages (A 16KB +
// B 16KB, rows of 128B, SW swizzle cq^(row&7)), single barrier per chunk,
// 8 warps (2x4), warp tile 64x32 via m16n8k16 (R5-proven lane mapping).
// Dynamic smem 96KB, 2 CTAs/SM. K must be a multiple of 64. OOB rows
// clamped (their outputs never stored).
// ===========================================================================
__global__ __launch_bounds__(256, 2)
void gemm64(const __nv_bfloat16* __restrict__ A, const __nv_bfloat16* __restrict__ B,
            float* __restrict__ C, int M, int N, int K, float alpha)
{
    extern __shared__ uint4 dynbuf[];          // 3 stages x 32KB

    const int tid  = threadIdx.x;
    const int lane = tid & 31;
    const int wid  = tid >> 5;
    const int wm   = wid >> 2;                 // 0..1
    const int wn   = wid & 3;                  // 0..3
    const int row0 = blockIdx.y * 128;
    const int col0 = blockIdx.x * 128;

    // loader: thread t -> tile row t>>1, 64B half (t&1); 4 x CP16 each for A,B
    const int lrow = tid >> 1;
    const int half = tid & 1;
    const int lsr  = lrow & 7;                 // swizzle key
    uint32_t swoff[4];
    #pragma unroll
    for (int i = 0; i < 4; i++)
        swoff[i] = (uint32_t)(((lrow << 3) + ((half * 4 + i) ^ lsr)) << 4);
    int ra = row0 + lrow; if (ra > M - 1) ra = M - 1;
    int rb = col0 + lrow; if (rb > N - 1) rb = N - 1;
    const __nv_bfloat16* gA = A + (size_t)ra * K + half * 32;
    const __nv_bfloat16* gB = B + (size_t)rb * K + half * 32;

    const int NC = K >> 6;                     // chunks of 64 K-columns

    auto issue = [&](int stage, int c) {
        uint32_t base = smem_u32(dynbuf) + (uint32_t)stage * 32768u;
        #pragma unroll
        for (int i = 0; i < 4; i++) {
            CP16(base +           swoff[i], gA + c * 64 + i * 8);
            CP16(base + 16384u +  swoff[i], gB + c * 64 + i * 8);
        }
        CP_COMMIT();
    };

    float acc[4][4][4];
    #pragma unroll
    for (int mi = 0; mi < 4; mi++)
        #pragma unroll
        for (int ni = 0; ni < 4; ni++)
            #pragma unroll
            for (int e = 0; e < 4; e++) acc[mi][ni][e] = 0.f;

    const int q = lane >> 3;                   // 0..3 (ldmatrix quad)
    const int r = lane & 7;

    // swizzled byte address of (row, 16B-chunk scq) within a 128x128B tile
    auto taddr = [&](uint32_t base, int row, int scq) -> uint32_t {
        return base + (uint32_t)(((row << 3) + (scq ^ (row & 7))) << 4);
    };

    auto compute = [&](int stage) {
        uint32_t abase = smem_u32(dynbuf) + (uint32_t)stage * 32768u;
        uint32_t bbase = abase + 16384u;
        #pragma unroll
        for (int ks = 0; ks < 4; ks++) {
            uint32_t af[4][4];
            #pragma unroll
            for (int mi = 0; mi < 4; mi++) {
                int row = wm * 64 + mi * 16 + r + (q & 1) * 8;
                int scq = ks * 2 + (q >> 1);
                LDMX4(af[mi][0], af[mi][1], af[mi][2], af[mi][3],
                      taddr(abase, row, scq));
            }
            uint32_t bf[4][2];
            #pragma unroll
            for (int nh = 0; nh < 2; nh++) {
                int ni  = nh * 2 + (q >> 1);
                int row = wn * 32 + ni * 8 + r;
                int scq = ks * 2 + (q & 1);
                LDMX4(bf[nh*2][0], bf[nh*2][1], bf[nh*2+1][0], bf[nh*2+1][1],
                      taddr(bbase, row, scq));
            }
            #pragma unroll
            for (int mi = 0; mi < 4; mi++)
                #pragma unroll
                for (int ni = 0; ni < 4; ni++)
                    MMA16816(acc[mi][ni], af[mi], bf[ni]);
        }
    };

    // 3-stage pipeline: wait -> barrier -> issue(c+2) -> compute(c)
    issue(0, 0);
    if (NC > 1) issue(1, 1);
    for (int c = 0; c < NC; c++) {
        if (c + 1 < NC) CP_WAIT(1);
        else            CP_WAIT(0);
        __syncthreads();
        if (c + 2 < NC) {
            int st = c + 2; while (st >= 3) st -= 3;
            issue(st, c + 2);
        }
        int cs = c; while (cs >= 3) cs -= 3;
        compute(cs);
    }

    // epilogue: float2 stores
    const int g  = lane >> 2;
    const int tg = lane & 3;
    #pragma unroll
    for (int mi = 0; mi < 4; mi++) {
        int rr0 = row0 + wm * 64 + mi * 16 + g;
        int rr1 = rr0 + 8;
        #pragma unroll
        for (int ni = 0; ni < 4; ni++) {
            int cc = col0 + wn * 32 + ni * 8 + tg * 2;
            if (cc < N) {
                if (rr0 < M) {
                    float2 v = make_float2(alpha * acc[mi][ni][0], alpha * acc[mi][ni][1]);
                    *(float2*)(C + (size_t)rr0 * N + cc) = v;
                }
                if (rr1 < M) {
                    float2 v = make_float2(alpha * acc[mi][ni][2], alpha * acc[mi][ni][3]);
                    *(float2*)(C + (size_t)rr1 * N + cc) = v;
                }
            }
        }
    }
}

// ===========================================================================
// gemm_mma: R5-proven BK=32 kernel (used for the short-K proto GEMM).
// 128x128 CTA tile, 4-stage cp.async pipeline, batched over blockIdx.z.
// ===========================================================================
__global__ __launch_bounds__(256, 2)
void gemm_mma(const __nv_bfloat16* __restrict__ A, const __nv_bfloat16* __restrict__ B,
              float* __restrict__ C, int M, int N, int K, float alpha,
              size_t aStride, size_t bStride, size_t cStride)
{
    __shared__ uint4 sbuf[4][1024];    // per stage: [0..511]=A (8KB), [512..1023]=B

    A += (size_t)blockIdx.z * aStride;
    B += (size_t)blockIdx.z * bStride;
    C += (size_t)blockIdx.z * cStride;

    const int tid  = threadIdx.x;
    const int lane = tid & 31;
    const int wid  = tid >> 5;
    const int wm   = wid >> 2;
    const int wn   = wid & 3;
    const int row0 = blockIdx.y * 128;
    const int col0 = blockIdx.x * 128;

    int l_sw[2];
    const __nv_bfloat16 *gA[2], *gB[2];
    #pragma unroll
    for (int i = 0; i < 2; i++) {
        int ch  = tid + i * 256;
        int row = ch >> 2, cq = ch & 3;
        l_sw[i] = row * 4 + ((cq ^ (row >> 1)) & 3);
        int ra = row0 + row; if (ra > M - 1) ra = M - 1;
        int rb = col0 + row; if (rb > N - 1) rb = N - 1;
        gA[i] = A + (size_t)ra * K + cq * 8;
        gB[i] = B + (size_t)rb * K + cq * 8;
    }

    const int NC = K >> 5;

    auto issue = [&](int stage, int c) {
        uint32_t base = smem_u32(&sbuf[stage][0]);
        #pragma unroll
        for (int i = 0; i < 2; i++) {
            CP16(base +        l_sw[i] * 16, gA[i] + c * 32);
            CP16(base + 8192 + l_sw[i] * 16, gB[i] + c * 32);
        }
        CP_COMMIT();
    };

    float acc[4][4][4];
    #pragma unroll
    for (int mi = 0; mi < 4; mi++)
        #pragma unroll
        for (int ni = 0; ni < 4; ni++)
            #pragma unroll
            for (int e = 0; e < 4; e++) acc[mi][ni][e] = 0.f;

    const int q = lane >> 3;
    const int r = lane & 7;

    auto compute = [&](int stage) {
        uint32_t abase = smem_u32(&sbuf[stage][0]);
        uint32_t bbase = abase + 8192;
        #pragma unroll
        for (int ks = 0; ks < 2; ks++) {
            uint32_t af[4][4];
            #pragma unroll
            for (int mi = 0; mi < 4; mi++) {
                int row = wm * 64 + mi * 16 + r + (q & 1) * 8;
                int cq  = ks * 2 + (q >> 1);
                uint32_t ad = abase + (uint32_t)(row * 4 + ((cq ^ (row >> 1)) & 3)) * 16u;
                LDMX4(af[mi][0], af[mi][1], af[mi][2], af[mi][3], ad);
            }
            uint32_t bf[4][2];
            #pragma unroll
            for (int nh = 0; nh < 2; nh++) {
                int ni  = nh * 2 + (q >> 1);
                int row = wn * 32 + ni * 8 + r;
                int cq  = ks * 2 + (q & 1);
                uint32_t bd = bbase + (uint32_t)(row * 4 + ((cq ^ (row >> 1)) & 3)) * 16u;
                LDMX4(bf[nh*2][0], bf[nh*2][1], bf[nh*2+1][0], bf[nh*2+1][1], bd);
            }
            #pragma unroll
            for (int mi = 0; mi < 4; mi++)
                #pragma unroll
                for (int ni = 0; ni < 4; ni++)
                    MMA16816(acc[mi][ni], af[mi], bf[ni]);
        }
    };

    issue(0, 0);
    if (NC > 1) issue(1, 1);
    if (NC > 2) issue(2, 2);
    for (int c = 0; c < NC; c++) {
        if (c + 2 < NC)      CP_WAIT(2);
        else if (c + 1 < NC) CP_WAIT(1);
        else                 CP_WAIT(0);
        __syncthreads();
        if (c + 3 < NC) issue((c + 3) & 3, c + 3);
        compute(c & 3);
    }

    const int g  = lane >> 2;
    const int tg = lane & 3;
    #pragma unroll
    for (int mi = 0; mi < 4; mi++) {
        int rr0 = row0 + wm * 64 + mi * 16 + g;
        int rr1 = rr0 + 8;
        #pragma unroll
        for (int ni = 0; ni < 4; ni++) {
            int cc = col0 + wn * 32 + ni * 8 + tg * 2;
            if (cc < N) {
                if (rr0 < M) {
                    float2 v = make_float2(alpha * acc[mi][ni][0], alpha * acc[mi][ni][1]);
                    *(float2*)(C + (size_t)rr0 * N + cc) = v;
                }
                if (rr1 < M) {
                    float2 v = make_float2(alpha * acc[mi][ni][2], alpha * acc[mi][ni][3]);
                    *(float2*)(C + (size_t)rr1 * N + cc) = v;
                }
            }
        }
    }
}

// ---------------------------------------------------------------------------
// Fused: X = [support; queries] + PE, then hi/lo split -> A-layout (hi,hi,lo)
// ---------------------------------------------------------------------------
__global__ void conv_pe_hilo(const float* __restrict__ support,
                             const float* __restrict__ queries)
{
    int e = blockIdx.x * blockDim.x + threadIdx.x;
    if (e >= ROWS_X * D_MODEL) return;
    int n = e / (SEQ_LEN * D_MODEL);
    int rem = e % (SEQ_LEN * D_MODEL);
    int s = rem / D_MODEL, d = rem % D_MODEL;
    const float c = -9.210340371976184f / (float)D_MODEL;
    float div = expf((float)(2 * (d >> 1)) * c);
    float arg = (float)s * div;
    float pe = ((d & 1) ? cosf(arg) : sinf(arg)) * 0.1f;
    float x = ((n < N_SUPPORT) ? support[e]
                               : queries[e - N_SUPPORT * SEQ_LEN * D_MODEL]) + pe;
    __nv_bfloat16 hi, lo; split2(x, hi, lo);
    int row = e / D_MODEL;
    __nv_bfloat16* o = g_Xhl + (size_t)row * KBIG;
    o[d] = hi; o[D_MODEL + d] = hi; o[2 * D_MODEL + d] = lo;
}

// stacked weights -> B-layout (hi, lo, hi)
__global__ void convW_kernel(const float* __restrict__ k_w, const float* __restrict__ v_w)
{
    int e = blockIdx.x * blockDim.x + threadIdx.x;
    if (e >= NSTACK * D_MODEL) return;
    int j = e / D_MODEL, k = e % D_MODEL;
    int part = j / OUT_DIM, o = j % OUT_DIM;
    const float* w = (part < 2) ? k_w : v_w;
    float x = w[(size_t)o * TWO_D + (part & 1) * D_MODEL + k];
    __nv_bfloat16 hi, lo; split2(x, hi, lo);
    __nv_bfloat16* dst = g_Whl + (size_t)j * KBIG;
    dst[k] = hi; dst[D_MODEL + k] = lo; dst[2 * D_MODEL + k] = hi;
}

// vs_s^T slices -> B-layout [WAY][OUT_DIM][KPR] (hi, lo, hi), pad to 448 zero
__global__ void conv_vsT_kernel()
{
    int e = blockIdx.x * blockDim.x + threadIdx.x;
    const int total = WAY * OUT_DIM * KPR;
    if (e >= total) return;
    int w = e / (OUT_DIM * KPR);
    int rem = e % (OUT_DIM * KPR);
    int d = rem / KPR, j = rem % KPR;
    __nv_bfloat16 v = __float2bfloat16(0.f);
    if (j < 420) {
        int seg = j / SEG, jj = j - seg * SEG;
        float x = g_vs_s[(size_t)(w * SEG + jj) * OUT_DIM + d];
        __nv_bfloat16 hi, lo; split2(x, hi, lo);
        v = (seg == 1) ? lo : hi;
    }
    g_Vhl[e] = v;
}

// ---------------------------------------------------------------------------
// assemble tuple features + LayerNorm(k) -> split bf16 layouts, plain v.
// support rows -> KShl (B-layout hi,lo,hi); query rows -> KQhl (A-layout hi,hi,lo)
// ---------------------------------------------------------------------------
__global__ __launch_bounds__(256)
void assemble_kernel(const float* __restrict__ k_b, const float* __restrict__ v_b,
                     const float* __restrict__ ln_g, const float* __restrict__ ln_b)
{
    int rl = blockIdx.x;
    int n = rl / L_TUP, l = rl % L_TUP;
    int t0 = c_t0[l], t1 = c_t1[l];
    const float* P0 = g_P + (size_t)(n * SEQ_LEN + t0) * NSTACK;
    const float* P1 = g_P + (size_t)(n * SEQ_LEN + t1) * NSTACK;

    const bool isSup = (n < N_SUPPORT);
    __nv_bfloat16* kd;
    float* vsd;
    if (isSup) {
        kd  = g_KShl + (size_t)(n * L_TUP + l) * KSC;
        vsd = g_vs_s + (size_t)(n * L_TUP + l) * OUT_DIM;
    } else {
        int m = n - N_SUPPORT;
        kd  = g_KQhl + (size_t)(m * L_TUP + l) * KSC;
        vsd = g_vs_q + (size_t)(m * L_TUP + l) * OUT_DIM;
    }

    __shared__ float kbuf[OUT_DIM];
    float s = 0.f, s2 = 0.f;
    for (int o = threadIdx.x; o < OUT_DIM; o += blockDim.x) {
        float kv = P0[o] + P1[OUT_DIM + o] + k_b[o];
        kbuf[o] = kv; s += kv; s2 += kv * kv;
        vsd[o] = P0[2 * OUT_DIM + o] + P1[3 * OUT_DIM + o] + v_b[o];
    }
    int lane = threadIdx.x & 31, wid = threadIdx.x >> 5;
    #pragma unroll
    for (int off = 16; off; off >>= 1) {
        s  += __shfl_xor_sync(0xffffffffu, s,  off);
        s2 += __shfl_xor_sync(0xffffffffu, s2, off);
    }
    __shared__ float ws[8], ws2[8], sm_mean, sm_rstd;
    if (lane == 0) { ws[wid] = s; ws2[wid] = s2; }
    __syncthreads();
    if (threadIdx.x == 0) {
        float S = 0.f, S2 = 0.f;
        #pragma unroll
        for (int w = 0; w < 8; w++) { S += ws[w]; S2 += ws2[w]; }
        float mean = S / (float)OUT_DIM;
        float var  = S2 / (float)OUT_DIM - mean * mean;
        sm_mean = mean; sm_rstd = rsqrtf(var + 1e-5f);
    }
    __syncthreads();
    float mean = sm_mean, rstd = sm_rstd;
    for (int o = threadIdx.x; o < OUT_DIM; o += blockDim.x) {
        float y = (kbuf[o] - mean) * rstd * ln_g[o] + ln_b[o];
        __nv_bfloat16 hi, lo; split2(y, hi, lo);
        kd[o] = hi;
        kd[OUT_DIM + o]     = isSup ? lo : hi;
        kd[2 * OUT_DIM + o] = isSup ? hi : lo;
    }
}

// ---------------------------------------------------------------------------
// per-row blockwise softmax; writes hi/lo A-layout attn directly to g_Ahl.
// ---------------------------------------------------------------------------
__global__ __launch_bounds__(160)
void softmax_kernel()
{
    int row = blockIdx.x;
    int warp = threadIdx.x >> 5, lane = threadIdx.x & 31;
    const float* p = g_S + (size_t)row * ROWS_S + warp * SEG;
    float v[5]; float mx = -INFINITY;
    #pragma unroll
    for (int i = 0; i < 5; i++) {
        int c = lane + 32 * i;
        v[i] = (c < SEG) ? p[c] : -INFINITY;
        mx = fmaxf(mx, v[i]);
    }
    #pragma unroll
    for (int off = 16; off; off >>= 1)
        mx = fmaxf(mx, __shfl_xor_sync(0xffffffffu, mx, off));
    float sm = 0.f;
    #pragma unroll
    for (int i = 0; i < 5; i++) {
        int c = lane + 32 * i;
        v[i] = (c < SEG) ? expf(v[i] - mx) : 0.f;
        sm += v[i];
    }
    #pragma unroll
    for (int off = 16; off; off >>= 1)
        sm += __shfl_xor_sync(0xffffffffu, sm, off);
    float inv = 1.f / sm;

    __nv_bfloat16* a = g_Ahl + ((size_t)warp * ROWS_Q + row) * KPR;
    #pragma unroll
    for (int i = 0; i < 5; i++) {
        int c = lane + 32 * i;
        if (c < SEG) {
            float x = v[i] * inv;
            __nv_bfloat16 hi, lo; split2(x, hi, lo);
            a[c] = hi;
            a[SEG + c] = hi;
            a[2 * SEG + c] = lo;
        }
    }
    if (lane < KPR - 3 * SEG)          // zero pad 420..447
        a[3 * SEG + lane] = __float2bfloat16(0.f);
}

// ---------------------------------------------------------------------------
// per-query Gram matrix + distances -> sim, ori
// ---------------------------------------------------------------------------
__global__ __launch_bounds__(256)
void finalize_kernel(float* __restrict__ out)
{
    int q = blockIdx.x;
    const float* v = g_vs_q + (size_t)q * PLANE;
    const float* pp[WAY];
    #pragma unroll
    for (int w = 0; w < WAY; w++)
        pp[w] = g_proto + (size_t)w * ROWS_Q * OUT_DIM + (size_t)q * PLANE;

    float acc[21];
    #pragma unroll
    for (int i = 0; i < 21; i++) acc[i] = 0.f;

    for (int i = threadIdx.x; i < PLANE; i += blockDim.x) {
        float vv = v[i];
        float a0 = pp[0][i], a1 = pp[1][i], a2 = pp[2][i], a3 = pp[3][i], a4 = pp[4][i];
        acc[0]  += a0 * a0;  acc[1]  += a0 * a1;  acc[2]  += a0 * a2;
        acc[3]  += a0 * a3;  acc[4]  += a0 * a4;
        acc[5]  += a1 * a1;  acc[6]  += a1 * a2;  acc[7]  += a1 * a3;  acc[8]  += a1 * a4;
        acc[9]  += a2 * a2;  acc[10] += a2 * a3;  acc[11] += a2 * a4;
        acc[12] += a3 * a3;  acc[13] += a3 * a4;
        acc[14] += a4 * a4;
        acc[15] += vv * a0;  acc[16] += vv * a1;  acc[17] += vv * a2;
        acc[18] += vv * a3;  acc[19] += vv * a4;
        acc[20] += vv * vv;
    }

    int lane = threadIdx.x & 31, wid = threadIdx.x >> 5;
    __shared__ float part[21][8];
    #pragma unroll
    for (int i = 0; i < 21; i++) {
        float a = acc[i];
        #pragma unroll
        for (int off = 16; off; off >>= 1)
            a += __shfl_xor_sync(0xffffffffu, a, off);
        if (lane == 0) part[i][wid] = a;
    }
    __syncthreads();
    __shared__ float tot[21];
    if (threadIdx.x < 21) {
        float sSum = 0.f;
        #pragma unroll
        for (int w = 0; w < 8; w++) sSum += part[threadIdx.x][w];
        tot[threadIdx.x] = sSum;
    }
    __syncthreads();
    if (threadIdx.x == 0) {
        float G[WAY][WAY];
        int t = 0;
        for (int a = 0; a < WAY; a++)
            for (int b = a; b < WAY; b++) { G[a][b] = tot[t]; G[b][a] = tot[t]; t++; }
        float D[WAY];
        for (int w = 0; w < WAY; w++) D[w] = tot[15 + w];
        float VV = tot[20];
        float nrm[WAY];
        for (int w = 0; w < WAY; w++) nrm[w] = sqrtf(G[w][w]);
        for (int a = 0; a < WAY; a++)
            for (int b = 0; b < WAY; b++)
                out[q * WAY * WAY + a * WAY + b] =
                    G[a][b] / fmaxf(nrm[a] * nrm[b], 1e-8f);
        for (int w = 0; w < WAY; w++)
            out[N_QUERIES * WAY * WAY + q * WAY + w] =
                -(VV - 2.f * D[w] + G[w][w]) / (float)L_TUP;
    }
}

// ---------------------------------------------------------------------------
// Launch
// ---------------------------------------------------------------------------
extern "C" void kernel_launch(void* const* d_in, const int* in_sizes, int n_in,
                              void* d_out, int out_size)
{
    const float* support = (const float*)d_in[0];
    const float* queries = (const float*)d_in[2];
    const float* k_w  = (const float*)d_in[3];
    const float* k_b  = (const float*)d_in[4];
    const float* v_w  = (const float*)d_in[5];
    const float* v_b  = (const float*)d_in[6];
    const float* ln_g = (const float*)d_in[7];
    const float* ln_b = (const float*)d_in[8];
    float* out = (float*)d_out;

    float *P, *S, *proto;
    __nv_bfloat16 *Xhl, *Whl, *KQhl, *KShl, *Ahl, *Vhl;
    cudaGetSymbolAddress((void**)&Xhl,   g_Xhl);
    cudaGetSymbolAddress((void**)&Whl,   g_Whl);
    cudaGetSymbolAddress((void**)&P,     g_P);
    cudaGetSymbolAddress((void**)&KQhl,  g_KQhl);
    cudaGetSymbolAddress((void**)&KShl,  g_KShl);
    cudaGetSymbolAddress((void**)&S,     g_S);
    cudaGetSymbolAddress((void**)&Ahl,   g_Ahl);
    cudaGetSymbolAddress((void**)&Vhl,   g_Vhl);
    cudaGetSymbolAddress((void**)&proto, g_proto);

    cudaFuncSetAttribute(gemm64, cudaFuncAttributeMaxDynamicSharedMemorySize, 98304);

    // 1. fused PE + hi/lo conversion; weight conversion
    conv_pe_hilo<<<(ROWS_X * D_MODEL + 255) / 256, 256>>>(support, queries);
    convW_kernel<<<(NSTACK * D_MODEL + 255) / 256, 256>>>(k_w, v_w);
    // 2. P = X @ Wt^T  [1800, 4608], K=6144 (BK=64 kernel)
    {
        dim3 grid(NSTACK / 128, (ROWS_X + 127) / 128, 1);
        gemm64<<<grid, 256, 98304>>>(Xhl, Whl, P, ROWS_X, NSTACK, KBIG, 1.0f);
    }
    // 3. assemble -> KQhl/KShl (split bf16) + vs float
    assemble_kernel<<<N_TOTAL * L_TUP, 256>>>(k_b, v_b, ln_g, ln_b);
    // 4. scores = ks_q @ ks_s^T / sqrt(OUT_DIM)  [5600, 700], K=3456 (BK=64)
    {
        dim3 grid((ROWS_S + 127) / 128, (ROWS_Q + 127) / 128, 1);
        gemm64<<<grid, 256, 98304>>>(KQhl, KShl, S, ROWS_Q, ROWS_S, KSC,
                                     1.0f / sqrtf((float)OUT_DIM));
    }
    // 5. softmax -> g_Ahl directly
    softmax_kernel<<<ROWS_Q, 160>>>();
    // 6. vs_s^T hi/lo for proto GEMM
    conv_vsT_kernel<<<(WAY * OUT_DIM * KPR + 255) / 256, 256>>>();
    // 7. proto[w] = attn_w @ vs_w  [5600, 1152], K=448 — batched over z (BK=32)
    {
        dim3 grid(OUT_DIM / 128, (ROWS_Q + 127) / 128, WAY);
        gemm_mma<<<grid, 256>>>(Ahl, Vhl, proto, ROWS_Q, OUT_DIM, KPR, 1.0f,
                                (size_t)ROWS_Q * KPR,
                                (size_t)OUT_DIM * KPR,
                                (size_t)ROWS_Q * OUT_DIM);
    }
    // 8. finalize
    finalize_kernel<<<N_QUERIES, 256>>>(out);
}

// round 10
// speedup vs baseline: 1.2537x; 1.2496x over previous
#include <cuda_runtime.h>
#include <cuda_bf16.h>
#include <math.h>
#include <stdint.h>

// ---------------------------------------------------------------------------
// Problem constants
// ---------------------------------------------------------------------------
#define SEQ_LEN   8
#define D_MODEL   2048
#define OUT_DIM   1152
#define WAY       5
#define SHOT      5
#define N_SUPPORT 25
#define N_QUERIES 200
#define N_TOTAL   225
#define L_TUP     28
#define TWO_D     4096
#define NSTACK    4608          // 4 * OUT_DIM (k h0, k h1, v h0, v h1)
#define ROWS_X    1800          // N_TOTAL * SEQ_LEN
#define ROWS_Q    5600          // N_QUERIES * L_TUP
#define ROWS_S    700           // N_SUPPORT * L_TUP
#define SEG       140           // SHOT * L_TUP
#define PLANE     32256         // L_TUP * OUT_DIM

// hi/lo-split K sizes (3x concatenated: A=(hi,hi,lo), B=(hi,lo,hi))
#define KBIG      6144          // 3 * 2048
#define KSC       3456          // 3 * 1152
#define KPR       448           // 3*140=420 padded to 448 (mult of 32)

__constant__ int c_t0[L_TUP] = {0,0,0,0,0,0,0,1,1,1,1,1,1,2,2,2,2,2,3,3,3,3,4,4,4,5,5,6};
__constant__ int c_t1[L_TUP] = {1,2,3,4,5,6,7,2,3,4,5,6,7,3,4,5,6,7,4,5,6,7,5,6,7,6,7,7};

// ---------------------------------------------------------------------------
// Scratch (device globals; no allocation allowed)
// ---------------------------------------------------------------------------
__device__ __nv_bfloat16  g_Xhl[(size_t)ROWS_X * KBIG];     // A-layout (hi,hi,lo)
__device__ __nv_bfloat16  g_Whl[(size_t)NSTACK * KBIG];     // B-layout (hi,lo,hi)
__device__ float          g_P[(size_t)ROWS_X * NSTACK];
__device__ float          g_vs_s[ROWS_S * OUT_DIM];
__device__ float          g_vs_q[ROWS_Q * OUT_DIM];
__device__ __nv_bfloat16  g_KQhl[(size_t)ROWS_Q * KSC];     // A-layout (from assemble)
__device__ __nv_bfloat16  g_KShl[(size_t)ROWS_S * KSC];     // B-layout (from assemble)
__device__ float          g_S[(size_t)ROWS_Q * ROWS_S];     // scores (read-only after gemm)
__device__ __nv_bfloat16  g_Ahl[(size_t)WAY * ROWS_Q * KPR];   // attn (from softmax)
__device__ __nv_bfloat16  g_Vhl[(size_t)WAY * OUT_DIM * KPR];  // vs_s^T slices, B-layout
__device__ float          g_proto[(size_t)WAY * ROWS_Q * OUT_DIM];

// ---------------------------------------------------------------------------
// Helpers
// ---------------------------------------------------------------------------
__device__ __forceinline__ uint32_t smem_u32(const void* p) {
    uint32_t a;
    asm("{ .reg .u64 t; cvta.to.shared.u64 t, %1; cvt.u32.u64 %0, t; }"
        : "=r"(a) : "l"(p));
    return a;
}

#define CP16(dst, src) \
    asm volatile("cp.async.cg.shared.global [%0], [%1], 16;" :: "r"(dst), "l"(src))
#define CP_COMMIT() asm volatile("cp.async.commit_group;" ::: "memory")
#define CP_WAIT(n)  asm volatile("cp.async.wait_group %0;" :: "n"(n) : "memory")

__device__ __forceinline__ void split2(float x, __nv_bfloat16& hi, __nv_bfloat16& lo) {
    hi = __float2bfloat16(x);
    lo = __float2bfloat16(x - __bfloat162float(hi));
}

#define LDMX4(d0,d1,d2,d3,addr) \
    asm volatile("ldmatrix.sync.aligned.m8n8.x4.shared.b16 {%0,%1,%2,%3}, [%4];" \
        : "=r"(d0), "=r"(d1), "=r"(d2), "=r"(d3) : "r"(addr))

#define MMA16816(acc, a, b) \
    asm volatile("mma.sync.aligned.m16n8k16.row.col.f32.bf16.bf16.f32 " \
        "{%0,%1,%2,%3}, {%4,%5,%6,%7}, {%8,%9}, {%0,%1,%2,%3};" \
        : "+f"((acc)[0]), "+f"((acc)[1]), "+f"((acc)[2]), "+f"((acc)[3]) \
        : "r"((a)[0]), "r"((a)[1]), "r"((a)[2]), "r"((a)[3]), \
          "r"((b)[0]), "r"((b)[1]))

// ---------------------------------------------------------------------------
// mma.sync bf16 GEMM (R5-proven): C[M,N] = alpha * A[M,K] * B[N,K]^T
// 128x128 CTA tile, BK=32, 4-stage cp.async pipeline, single barrier per
// chunk, 8 warps (2x4), warp tile 64x32 via m16n8k16. Batched over
// blockIdx.z via strides. 2 CTAs/SM. K multiple of 32. OOB rows clamped.
// ---------------------------------------------------------------------------
__global__ __launch_bounds__(256, 2)
void gemm_mma(const __nv_bfloat16* __restrict__ A, const __nv_bfloat16* __restrict__ B,
              float* __restrict__ C, int M, int N, int K, float alpha,
              size_t aStride, size_t bStride, size_t cStride)
{
    __shared__ uint4 sbuf[4][1024];    // per stage: [0..511]=A (8KB), [512..1023]=B

    A += (size_t)blockIdx.z * aStride;
    B += (size_t)blockIdx.z * bStride;
    C += (size_t)blockIdx.z * cStride;

    const int tid  = threadIdx.x;
    const int lane = tid & 31;
    const int wid  = tid >> 5;
    const int wm   = wid >> 2;
    const int wn   = wid & 3;
    const int row0 = blockIdx.y * 128;
    const int col0 = blockIdx.x * 128;

    int l_sw[2];
    const __nv_bfloat16 *gA[2], *gB[2];
    #pragma unroll
    for (int i = 0; i < 2; i++) {
        int ch  = tid + i * 256;
        int row = ch >> 2, cq = ch & 3;
        l_sw[i] = row * 4 + ((cq ^ (row >> 1)) & 3);
        int ra = row0 + row; if (ra > M - 1) ra = M - 1;
        int rb = col0 + row; if (rb > N - 1) rb = N - 1;
        gA[i] = A + (size_t)ra * K + cq * 8;
        gB[i] = B + (size_t)rb * K + cq * 8;
    }

    const int NC = K >> 5;

    auto issue = [&](int stage, int c) {
        uint32_t base = smem_u32(&sbuf[stage][0]);
        #pragma unroll
        for (int i = 0; i < 2; i++) {
            CP16(base +        l_sw[i] * 16, gA[i] + c * 32);
            CP16(base + 8192 + l_sw[i] * 16, gB[i] + c * 32);
        }
        CP_COMMIT();
    };

    float acc[4][4][4];
    #pragma unroll
    for (int mi = 0; mi < 4; mi++)
        #pragma unroll
        for (int ni = 0; ni < 4; ni++)
            #pragma unroll
            for (int e = 0; e < 4; e++) acc[mi][ni][e] = 0.f;

    const int q = lane >> 3;
    const int r = lane & 7;

    auto compute = [&](int stage) {
        uint32_t abase = smem_u32(&sbuf[stage][0]);
        uint32_t bbase = abase + 8192;
        #pragma unroll
        for (int ks = 0; ks < 2; ks++) {
            uint32_t af[4][4];
            #pragma unroll
            for (int mi = 0; mi < 4; mi++) {
                int row = wm * 64 + mi * 16 + r + (q & 1) * 8;
                int cq  = ks * 2 + (q >> 1);
                uint32_t ad = abase + (uint32_t)(row * 4 + ((cq ^ (row >> 1)) & 3)) * 16u;
                LDMX4(af[mi][0], af[mi][1], af[mi][2], af[mi][3], ad);
            }
            uint32_t bf[4][2];
            #pragma unroll
            for (int nh = 0; nh < 2; nh++) {
                int ni  = nh * 2 + (q >> 1);
                int row = wn * 32 + ni * 8 + r;
                int cq  = ks * 2 + (q & 1);
                uint32_t bd = bbase + (uint32_t)(row * 4 + ((cq ^ (row >> 1)) & 3)) * 16u;
                LDMX4(bf[nh*2][0], bf[nh*2][1], bf[nh*2+1][0], bf[nh*2+1][1], bd);
            }
            #pragma unroll
            for (int mi = 0; mi < 4; mi++)
                #pragma unroll
                for (int ni = 0; ni < 4; ni++)
                    MMA16816(acc[mi][ni], af[mi], bf[ni]);
        }
    };

    issue(0, 0);
    if (NC > 1) issue(1, 1);
    if (NC > 2) issue(2, 2);
    for (int c = 0; c < NC; c++) {
        if (c + 2 < NC)      CP_WAIT(2);
        else if (c + 1 < NC) CP_WAIT(1);
        else                 CP_WAIT(0);
        __syncthreads();
        if (c + 3 < NC) issue((c + 3) & 3, c + 3);
        compute(c & 3);
    }

    const int g  = lane >> 2;
    const int tg = lane & 3;
    #pragma unroll
    for (int mi = 0; mi < 4; mi++) {
        int rr0 = row0 + wm * 64 + mi * 16 + g;
        int rr1 = rr0 + 8;
        #pragma unroll
        for (int ni = 0; ni < 4; ni++) {
            int cc = col0 + wn * 32 + ni * 8 + tg * 2;
            if (cc < N) {
                if (rr0 < M) {
                    float2 v = make_float2(alpha * acc[mi][ni][0], alpha * acc[mi][ni][1]);
                    *(float2*)(C + (size_t)rr0 * N + cc) = v;
                }
                if (rr1 < M) {
                    float2 v = make_float2(alpha * acc[mi][ni][2], alpha * acc[mi][ni][3]);
                    *(float2*)(C + (size_t)rr1 * N + cc) = v;
                }
            }
        }
    }
}

// ---------------------------------------------------------------------------
// Fused conversion: one launch covers both
//   part 1: X = [support; queries] + PE -> A-layout (hi,hi,lo) in g_Xhl
//   part 2: stacked weights -> B-layout (hi,lo,hi) in g_Whl
// ---------------------------------------------------------------------------
#define CONV_T1 (ROWS_X * D_MODEL)
#define CONV_T2 (NSTACK * D_MODEL)

__global__ void conv_inputs_kernel(const float* __restrict__ support,
                                   const float* __restrict__ queries,
                                   const float* __restrict__ k_w,
                                   const float* __restrict__ v_w)
{
    int e = blockIdx.x * blockDim.x + threadIdx.x;
    if (e < CONV_T1) {
        int n = e / (SEQ_LEN * D_MODEL);
        int rem = e % (SEQ_LEN * D_MODEL);
        int s = rem / D_MODEL, d = rem % D_MODEL;
        const float c = -9.210340371976184f / (float)D_MODEL;
        float div = expf((float)(2 * (d >> 1)) * c);
        float arg = (float)s * div;
        float pe = ((d & 1) ? cosf(arg) : sinf(arg)) * 0.1f;
        float x = ((n < N_SUPPORT) ? support[e]
                                   : queries[e - N_SUPPORT * SEQ_LEN * D_MODEL]) + pe;
        __nv_bfloat16 hi, lo; split2(x, hi, lo);
        int row = e / D_MODEL;
        __nv_bfloat16* o = g_Xhl + (size_t)row * KBIG;
        o[d] = hi; o[D_MODEL + d] = hi; o[2 * D_MODEL + d] = lo;
    } else if (e < CONV_T1 + CONV_T2) {
        int e2 = e - CONV_T1;
        int j = e2 / D_MODEL, k = e2 % D_MODEL;
        int part = j / OUT_DIM, o = j % OUT_DIM;
        const float* w = (part < 2) ? k_w : v_w;
        float x = w[(size_t)o * TWO_D + (part & 1) * D_MODEL + k];
        __nv_bfloat16 hi, lo; split2(x, hi, lo);
        __nv_bfloat16* dst = g_Whl + (size_t)j * KBIG;
        dst[k] = hi; dst[D_MODEL + k] = lo; dst[2 * D_MODEL + k] = hi;
    }
}

// vs_s^T slices -> B-layout [WAY][OUT_DIM][KPR] (hi, lo, hi), pad to 448 zero
__global__ void conv_vsT_kernel()
{
    int e = blockIdx.x * blockDim.x + threadIdx.x;
    const int total = WAY * OUT_DIM * KPR;
    if (e >= total) return;
    int w = e / (OUT_DIM * KPR);
    int rem = e % (OUT_DIM * KPR);
    int d = rem / KPR, j = rem % KPR;
    __nv_bfloat16 v = __float2bfloat16(0.f);
    if (j < 420) {
        int seg = j / SEG, jj = j - seg * SEG;
        float x = g_vs_s[(size_t)(w * SEG + jj) * OUT_DIM + d];
        __nv_bfloat16 hi, lo; split2(x, hi, lo);
        v = (seg == 1) ? lo : hi;
    }
    g_Vhl[e] = v;
}

// ---------------------------------------------------------------------------
// assemble tuple features + LayerNorm(k) -> split bf16 layouts, plain v.
// support rows -> KShl (B-layout hi,lo,hi); query rows -> KQhl (A-layout hi,hi,lo)
// ---------------------------------------------------------------------------
__global__ __launch_bounds__(256)
void assemble_kernel(const float* __restrict__ k_b, const float* __restrict__ v_b,
                     const float* __restrict__ ln_g, const float* __restrict__ ln_b)
{
    int rl = blockIdx.x;
    int n = rl / L_TUP, l = rl % L_TUP;
    int t0 = c_t0[l], t1 = c_t1[l];
    const float* P0 = g_P + (size_t)(n * SEQ_LEN + t0) * NSTACK;
    const float* P1 = g_P + (size_t)(n * SEQ_LEN + t1) * NSTACK;

    const bool isSup = (n < N_SUPPORT);
    __nv_bfloat16* kd;
    float* vsd;
    if (isSup) {
        kd  = g_KShl + (size_t)(n * L_TUP + l) * KSC;
        vsd = g_vs_s + (size_t)(n * L_TUP + l) * OUT_DIM;
    } else {
        int m = n - N_SUPPORT;
        kd  = g_KQhl + (size_t)(m * L_TUP + l) * KSC;
        vsd = g_vs_q + (size_t)(m * L_TUP + l) * OUT_DIM;
    }

    __shared__ float kbuf[OUT_DIM];
    float s = 0.f, s2 = 0.f;
    for (int o = threadIdx.x; o < OUT_DIM; o += blockDim.x) {
        float kv = P0[o] + P1[OUT_DIM + o] + k_b[o];
        kbuf[o] = kv; s += kv; s2 += kv * kv;
        vsd[o] = P0[2 * OUT_DIM + o] + P1[3 * OUT_DIM + o] + v_b[o];
    }
    int lane = threadIdx.x & 31, wid = threadIdx.x >> 5;
    #pragma unroll
    for (int off = 16; off; off >>= 1) {
        s  += __shfl_xor_sync(0xffffffffu, s,  off);
        s2 += __shfl_xor_sync(0xffffffffu, s2, off);
    }
    __shared__ float ws[8], ws2[8], sm_mean, sm_rstd;
    if (lane == 0) { ws[wid] = s; ws2[wid] = s2; }
    __syncthreads();
    if (threadIdx.x == 0) {
        float S = 0.f, S2 = 0.f;
        #pragma unroll
        for (int w = 0; w < 8; w++) { S += ws[w]; S2 += ws2[w]; }
        float mean = S / (float)OUT_DIM;
        float var  = S2 / (float)OUT_DIM - mean * mean;
        sm_mean = mean; sm_rstd = rsqrtf(var + 1e-5f);
    }
    __syncthreads();
    float mean = sm_mean, rstd = sm_rstd;
    for (int o = threadIdx.x; o < OUT_DIM; o += blockDim.x) {
        float y = (kbuf[o] - mean) * rstd * ln_g[o] + ln_b[o];
        __nv_bfloat16 hi, lo; split2(y, hi, lo);
        kd[o] = hi;
        kd[OUT_DIM + o]     = isSup ? lo : hi;
        kd[2 * OUT_DIM + o] = isSup ? hi : lo;
    }
}

// ---------------------------------------------------------------------------
// per-row blockwise softmax; writes hi/lo A-layout attn directly to g_Ahl.
// ---------------------------------------------------------------------------
__global__ __launch_bounds__(160)
void softmax_kernel()
{
    int row = blockIdx.x;
    int warp = threadIdx.x >> 5, lane = threadIdx.x & 31;
    const float* p = g_S + (size_t)row * ROWS_S + warp * SEG;
    float v[5]; float mx = -INFINITY;
    #pragma unroll
    for (int i = 0; i < 5; i++) {
        int c = lane + 32 * i;
        v[i] = (c < SEG) ? p[c] : -INFINITY;
        mx = fmaxf(mx, v[i]);
    }
    #pragma unroll
    for (int off = 16; off; off >>= 1)
        mx = fmaxf(mx, __shfl_xor_sync(0xffffffffu, mx, off));
    float sm = 0.f;
    #pragma unroll
    for (int i = 0; i < 5; i++) {
        int c = lane + 32 * i;
        v[i] = (c < SEG) ? expf(v[i] - mx) : 0.f;
        sm += v[i];
    }
    #pragma unroll
    for (int off = 16; off; off >>= 1)
        sm += __shfl_xor_sync(0xffffffffu, sm, off);
    float inv = 1.f / sm;

    __nv_bfloat16* a = g_Ahl + ((size_t)warp * ROWS_Q + row) * KPR;
    #pragma unroll
    for (int i = 0; i < 5; i++) {
        int c = lane + 32 * i;
        if (c < SEG) {
            float x = v[i] * inv;
            __nv_bfloat16 hi, lo; split2(x, hi, lo);
            a[c] = hi;
            a[SEG + c] = hi;
            a[2 * SEG + c] = lo;
        }
    }
    if (lane < KPR - 3 * SEG)          // zero pad 420..447
        a[3 * SEG + lane] = __float2bfloat16(0.f);
}

// ---------------------------------------------------------------------------
// per-query Gram matrix + distances -> sim, ori  (float4-vectorized)
// ---------------------------------------------------------------------------
__global__ __launch_bounds__(256)
void finalize_kernel(float* __restrict__ out)
{
    int q = blockIdx.x;
    const float4* v4 = (const float4*)(g_vs_q + (size_t)q * PLANE);
    const float4* pp4[WAY];
    #pragma unroll
    for (int w = 0; w < WAY; w++)
        pp4[w] = (const float4*)(g_proto + (size_t)w * ROWS_Q * OUT_DIM
                                 + (size_t)q * PLANE);

    float acc[21];
    #pragma unroll
    for (int i = 0; i < 21; i++) acc[i] = 0.f;

    const int NV4 = PLANE / 4;                 // 8064
    for (int i = threadIdx.x; i < NV4; i += blockDim.x) {
        float4 vv = v4[i];
        float4 b0 = pp4[0][i], b1 = pp4[1][i], b2 = pp4[2][i],
               b3 = pp4[3][i], b4 = pp4[4][i];
        #pragma unroll
        for (int e = 0; e < 4; e++) {
            float vvv = (&vv.x)[e];
            float a0 = (&b0.x)[e], a1 = (&b1.x)[e], a2 = (&b2.x)[e],
                  a3 = (&b3.x)[e], a4 = (&b4.x)[e];
            acc[0]  += a0 * a0;  acc[1]  += a0 * a1;  acc[2]  += a0 * a2;
            acc[3]  += a0 * a3;  acc[4]  += a0 * a4;
            acc[5]  += a1 * a1;  acc[6]  += a1 * a2;  acc[7]  += a1 * a3;
            acc[8]  += a1 * a4;
            acc[9]  += a2 * a2;  acc[10] += a2 * a3;  acc[11] += a2 * a4;
            acc[12] += a3 * a3;  acc[13] += a3 * a4;
            acc[14] += a4 * a4;
            acc[15] += vvv * a0; acc[16] += vvv * a1; acc[17] += vvv * a2;
            acc[18] += vvv * a3; acc[19] += vvv * a4;
            acc[20] += vvv * vvv;
        }
    }

    int lane = threadIdx.x & 31, wid = threadIdx.x >> 5;
    __shared__ float part[21][8];
    #pragma unroll
    for (int i = 0; i < 21; i++) {
        float a = acc[i];
        #pragma unroll
        for (int off = 16; off; off >>= 1)
            a += __shfl_xor_sync(0xffffffffu, a, off);
        if (lane == 0) part[i][wid] = a;
    }
    __syncthreads();
    __shared__ float tot[21];
    if (threadIdx.x < 21) {
        float sSum = 0.f;
        #pragma unroll
        for (int w = 0; w < 8; w++) sSum += part[threadIdx.x][w];
        tot[threadIdx.x] = sSum;
    }
    __syncthreads();
    if (threadIdx.x == 0) {
        float G[WAY][WAY];
        int t = 0;
        for (int a = 0; a < WAY; a++)
            for (int b = a; b < WAY; b++) { G[a][b] = tot[t]; G[b][a] = tot[t]; t++; }
        float D[WAY];
        for (int w = 0; w < WAY; w++) D[w] = tot[15 + w];
        float VV = tot[20];
        float nrm[WAY];
        for (int w = 0; w < WAY; w++) nrm[w] = sqrtf(G[w][w]);
        for (int a = 0; a < WAY; a++)
            for (int b = 0; b < WAY; b++)
                out[q * WAY * WAY + a * WAY + b] =
                    G[a][b] / fmaxf(nrm[a] * nrm[b], 1e-8f);
        for (int w = 0; w < WAY; w++)
            out[N_QUERIES * WAY * WAY + q * WAY + w] =
                -(VV - 2.f * D[w] + G[w][w]) / (float)L_TUP;
    }
}

// ---------------------------------------------------------------------------
// Launch
// ---------------------------------------------------------------------------
extern "C" void kernel_launch(void* const* d_in, const int* in_sizes, int n_in,
                              void* d_out, int out_size)
{
    const float* support = (const float*)d_in[0];
    const float* queries = (const float*)d_in[2];
    const float* k_w  = (const float*)d_in[3];
    const float* k_b  = (const float*)d_in[4];
    const float* v_w  = (const float*)d_in[5];
    const float* v_b  = (const float*)d_in[6];
    const float* ln_g = (const float*)d_in[7];
    const float* ln_b = (const float*)d_in[8];
    float* out = (float*)d_out;

    float *P, *S, *proto;
    __nv_bfloat16 *Xhl, *Whl, *KQhl, *KShl, *Ahl, *Vhl;
    cudaGetSymbolAddress((void**)&Xhl,   g_Xhl);
    cudaGetSymbolAddress((void**)&Whl,   g_Whl);
    cudaGetSymbolAddress((void**)&P,     g_P);
    cudaGetSymbolAddress((void**)&KQhl,  g_KQhl);
    cudaGetSymbolAddress((void**)&KShl,  g_KShl);
    cudaGetSymbolAddress((void**)&S,     g_S);
    cudaGetSymbolAddress((void**)&Ahl,   g_Ahl);
    cudaGetSymbolAddress((void**)&Vhl,   g_Vhl);
    cudaGetSymbolAddress((void**)&proto, g_proto);

    // 1. fused PE + hi/lo input conversion + weight conversion (one launch)
    {
        int total = CONV_T1 + CONV_T2;
        conv_inputs_kernel<<<(total + 255) / 256, 256>>>(support, queries, k_w, v_w);
    }
    // 2. P = X @ Wt^T  [1800, 4608], K=6144
    {
        dim3 grid(NSTACK / 128, (ROWS_X + 127) / 128, 1);
        gemm_mma<<<grid, 256>>>(Xhl, Whl, P, ROWS_X, NSTACK, KBIG, 1.0f, 0, 0, 0);
    }
    // 3. assemble -> KQhl/KShl (split bf16) + vs float
    assemble_kernel<<<N_TOTAL * L_TUP, 256>>>(k_b, v_b, ln_g, ln_b);
    // 4. scores = ks_q @ ks_s^T / sqrt(OUT_DIM)  [5600, 700], K=3456
    {
        dim3 grid((ROWS_S + 127) / 128, (ROWS_Q + 127) / 128, 1);
        gemm_mma<<<grid, 256>>>(KQhl, KShl, S, ROWS_Q, ROWS_S, KSC,
                                1.0f / sqrtf((float)OUT_DIM), 0, 0, 0);
    }
    // 5. softmax -> g_Ahl directly
    softmax_kernel<<<ROWS_Q, 160>>>();
    // 6. vs_s^T hi/lo for proto GEMM
    conv_vsT_kernel<<<(WAY * OUT_DIM * KPR + 255) / 256, 256>>>();
    // 7. proto[w] = attn_w @ vs_w  [5600, 1152], K=448 — batched over z
    {
        dim3 grid(OUT_DIM / 128, (ROWS_Q + 127) / 128, WAY);
        gemm_mma<<<grid, 256>>>(Ahl, Vhl, proto, ROWS_Q, OUT_DIM, KPR, 1.0f,
                                (size_t)ROWS_Q * KPR,
                                (size_t)OUT_DIM * KPR,
                                (size_t)ROWS_Q * OUT_DIM);
    }
    // 8. finalize
    finalize_kernel<<<N_QUERIES, 256>>>(out);
}

// round 11
// speedup vs baseline: 1.3718x; 1.0943x over previous
#include <cuda_runtime.h>
#include <cuda_bf16.h>
#include <math.h>
#include <stdint.h>

// ---------------------------------------------------------------------------
// Problem constants
// ---------------------------------------------------------------------------
#define SEQ_LEN   8
#define D_MODEL   2048
#define OUT_DIM   1152
#define WAY       5
#define SHOT      5
#define N_SUPPORT 25
#define N_QUERIES 200
#define N_TOTAL   225
#define L_TUP     28
#define TWO_D     4096
#define NSTACK    4608          // 4 * OUT_DIM (k h0, k h1, v h0, v h1)
#define ROWS_X    1800          // N_TOTAL * SEQ_LEN
#define ROWS_Q    5600          // N_QUERIES * L_TUP
#define ROWS_S    700           // N_SUPPORT * L_TUP
#define SEG       140           // SHOT * L_TUP
#define PLANE     32256         // L_TUP * OUT_DIM

// hi/lo-split K sizes (3x concatenated: A=(hi,hi,lo), B=(hi,lo,hi))
#define KBIG      6144          // 3 * 2048
#define KSC       3456          // 3 * 1152
// proto GEMM uses hi-only operands (error suppressed by the quadratic
// reductions downstream): K = 140 padded to 160 (mult of 32)
#define KP2       160

__constant__ int c_t0[L_TUP] = {0,0,0,0,0,0,0,1,1,1,1,1,1,2,2,2,2,2,3,3,3,3,4,4,4,5,5,6};
__constant__ int c_t1[L_TUP] = {1,2,3,4,5,6,7,2,3,4,5,6,7,3,4,5,6,7,4,5,6,7,5,6,7,6,7,7};

// ---------------------------------------------------------------------------
// Scratch (device globals; no allocation allowed)
// ---------------------------------------------------------------------------
__device__ __nv_bfloat16  g_Xhl[(size_t)ROWS_X * KBIG];     // A-layout (hi,hi,lo)
__device__ __nv_bfloat16  g_Whl[(size_t)NSTACK * KBIG];     // B-layout (hi,lo,hi)
__device__ float          g_P[(size_t)ROWS_X * NSTACK];
__device__ float          g_vs_s[ROWS_S * OUT_DIM];
__device__ float          g_vs_q[ROWS_Q * OUT_DIM];
__device__ __nv_bfloat16  g_KQhl[(size_t)ROWS_Q * KSC];     // A-layout (from assemble)
__device__ __nv_bfloat16  g_KShl[(size_t)ROWS_S * KSC];     // B-layout (from assemble)
__device__ float          g_S[(size_t)ROWS_Q * ROWS_S];     // scores (read-only after gemm)
__device__ __nv_bfloat16  g_Ahl[(size_t)WAY * ROWS_Q * KP2];   // attn hi (from softmax)
__device__ __nv_bfloat16  g_Vhl[(size_t)WAY * OUT_DIM * KP2];  // vs_s^T hi slices
__device__ float          g_proto[(size_t)WAY * ROWS_Q * OUT_DIM];

// ---------------------------------------------------------------------------
// Helpers
// ---------------------------------------------------------------------------
__device__ __forceinline__ uint32_t smem_u32(const void* p) {
    uint32_t a;
    asm("{ .reg .u64 t; cvta.to.shared.u64 t, %1; cvt.u32.u64 %0, t; }"
        : "=r"(a) : "l"(p));
    return a;
}

#define CP16(dst, src) \
    asm volatile("cp.async.cg.shared.global [%0], [%1], 16;" :: "r"(dst), "l"(src))
#define CP_COMMIT() asm volatile("cp.async.commit_group;" ::: "memory")
#define CP_WAIT(n)  asm volatile("cp.async.wait_group %0;" :: "n"(n) : "memory")

__device__ __forceinline__ void split2(float x, __nv_bfloat16& hi, __nv_bfloat16& lo) {
    hi = __float2bfloat16(x);
    lo = __float2bfloat16(x - __bfloat162float(hi));
}

#define LDMX4(d0,d1,d2,d3,addr) \
    asm volatile("ldmatrix.sync.aligned.m8n8.x4.shared.b16 {%0,%1,%2,%3}, [%4];" \
        : "=r"(d0), "=r"(d1), "=r"(d2), "=r"(d3) : "r"(addr))

#define MMA16816(acc, a, b) \
    asm volatile("mma.sync.aligned.m16n8k16.row.col.f32.bf16.bf16.f32 " \
        "{%0,%1,%2,%3}, {%4,%5,%6,%7}, {%8,%9}, {%0,%1,%2,%3};" \
        : "+f"((acc)[0]), "+f"((acc)[1]), "+f"((acc)[2]), "+f"((acc)[3]) \
        : "r"((a)[0]), "r"((a)[1]), "r"((a)[2]), "r"((a)[3]), \
          "r"((b)[0]), "r"((b)[1]))

// ---------------------------------------------------------------------------
// mma.sync bf16 GEMM (R5-proven): C[M,N] = alpha * A[M,K] * B[N,K]^T
// 128x128 CTA tile, BK=32, 4-stage cp.async pipeline, single barrier per
// chunk, 8 warps (2x4), warp tile 64x32 via m16n8k16. Batched over
// blockIdx.z via strides. 2 CTAs/SM. K multiple of 32. OOB rows clamped.
// ---------------------------------------------------------------------------
__global__ __launch_bounds__(256, 2)
void gemm_mma(const __nv_bfloat16* __restrict__ A, const __nv_bfloat16* __restrict__ B,
              float* __restrict__ C, int M, int N, int K, float alpha,
              size_t aStride, size_t bStride, size_t cStride)
{
    __shared__ uint4 sbuf[4][1024];    // per stage: [0..511]=A (8KB), [512..1023]=B

    A += (size_t)blockIdx.z * aStride;
    B += (size_t)blockIdx.z * bStride;
    C += (size_t)blockIdx.z * cStride;

    const int tid  = threadIdx.x;
    const int lane = tid & 31;
    const int wid  = tid >> 5;
    const int wm   = wid >> 2;
    const int wn   = wid & 3;
    const int row0 = blockIdx.y * 128;
    const int col0 = blockIdx.x * 128;

    int l_sw[2];
    const __nv_bfloat16 *gA[2], *gB[2];
    #pragma unroll
    for (int i = 0; i < 2; i++) {
        int ch  = tid + i * 256;
        int row = ch >> 2, cq = ch & 3;
        l_sw[i] = row * 4 + ((cq ^ (row >> 1)) & 3);
        int ra = row0 + row; if (ra > M - 1) ra = M - 1;
        int rb = col0 + row; if (rb > N - 1) rb = N - 1;
        gA[i] = A + (size_t)ra * K + cq * 8;
        gB[i] = B + (size_t)rb * K + cq * 8;
    }

    const int NC = K >> 5;

    auto issue = [&](int stage, int c) {
        uint32_t base = smem_u32(&sbuf[stage][0]);
        #pragma unroll
        for (int i = 0; i < 2; i++) {
            CP16(base +        l_sw[i] * 16, gA[i] + c * 32);
            CP16(base + 8192 + l_sw[i] * 16, gB[i] + c * 32);
        }
        CP_COMMIT();
    };

    float acc[4][4][4];
    #pragma unroll
    for (int mi = 0; mi < 4; mi++)
        #pragma unroll
        for (int ni = 0; ni < 4; ni++)
            #pragma unroll
            for (int e = 0; e < 4; e++) acc[mi][ni][e] = 0.f;

    const int q = lane >> 3;
    const int r = lane & 7;

    auto compute = [&](int stage) {
        uint32_t abase = smem_u32(&sbuf[stage][0]);
        uint32_t bbase = abase + 8192;
        #pragma unroll
        for (int ks = 0; ks < 2; ks++) {
            uint32_t af[4][4];
            #pragma unroll
            for (int mi = 0; mi < 4; mi++) {
                int row = wm * 64 + mi * 16 + r + (q & 1) * 8;
                int cq  = ks * 2 + (q >> 1);
                uint32_t ad = abase + (uint32_t)(row * 4 + ((cq ^ (row >> 1)) & 3)) * 16u;
                LDMX4(af[mi][0], af[mi][1], af[mi][2], af[mi][3], ad);
            }
            uint32_t bf[4][2];
            #pragma unroll
            for (int nh = 0; nh < 2; nh++) {
                int ni  = nh * 2 + (q >> 1);
                int row = wn * 32 + ni * 8 + r;
                int cq  = ks * 2 + (q & 1);
                uint32_t bd = bbase + (uint32_t)(row * 4 + ((cq ^ (row >> 1)) & 3)) * 16u;
                LDMX4(bf[nh*2][0], bf[nh*2][1], bf[nh*2+1][0], bf[nh*2+1][1], bd);
            }
            #pragma unroll
            for (int mi = 0; mi < 4; mi++)
                #pragma unroll
                for (int ni = 0; ni < 4; ni++)
                    MMA16816(acc[mi][ni], af[mi], bf[ni]);
        }
    };

    issue(0, 0);
    if (NC > 1) issue(1, 1);
    if (NC > 2) issue(2, 2);
    for (int c = 0; c < NC; c++) {
        if (c + 2 < NC)      CP_WAIT(2);
        else if (c + 1 < NC) CP_WAIT(1);
        else                 CP_WAIT(0);
        __syncthreads();
        if (c + 3 < NC) issue((c + 3) & 3, c + 3);
        compute(c & 3);
    }

    const int g  = lane >> 2;
    const int tg = lane & 3;
    #pragma unroll
    for (int mi = 0; mi < 4; mi++) {
        int rr0 = row0 + wm * 64 + mi * 16 + g;
        int rr1 = rr0 + 8;
        #pragma unroll
        for (int ni = 0; ni < 4; ni++) {
            int cc = col0 + wn * 32 + ni * 8 + tg * 2;
            if (cc < N) {
                if (rr0 < M) {
                    float2 v = make_float2(alpha * acc[mi][ni][0], alpha * acc[mi][ni][1]);
                    *(float2*)(C + (size_t)rr0 * N + cc) = v;
                }
                if (rr1 < M) {
                    float2 v = make_float2(alpha * acc[mi][ni][2], alpha * acc[mi][ni][3]);
                    *(float2*)(C + (size_t)rr1 * N + cc) = v;
                }
            }
        }
    }
}

// ---------------------------------------------------------------------------
// Fused conversion: one launch covers both
//   part 1: X = [support; queries] + PE -> A-layout (hi,hi,lo) in g_Xhl
//   part 2: stacked weights -> B-layout (hi,lo,hi) in g_Whl
// ---------------------------------------------------------------------------
#define CONV_T1 (ROWS_X * D_MODEL)
#define CONV_T2 (NSTACK * D_MODEL)

__global__ void conv_inputs_kernel(const float* __restrict__ support,
                                   const float* __restrict__ queries,
                                   const float* __restrict__ k_w,
                                   const float* __restrict__ v_w)
{
    int e = blockIdx.x * blockDim.x + threadIdx.x;
    if (e < CONV_T1) {
        int n = e / (SEQ_LEN * D_MODEL);
        int rem = e % (SEQ_LEN * D_MODEL);
        int s = rem / D_MODEL, d = rem % D_MODEL;
        const float c = -9.210340371976184f / (float)D_MODEL;
        float div = expf((float)(2 * (d >> 1)) * c);
        float arg = (float)s * div;
        float pe = ((d & 1) ? cosf(arg) : sinf(arg)) * 0.1f;
        float x = ((n < N_SUPPORT) ? support[e]
                                   : queries[e - N_SUPPORT * SEQ_LEN * D_MODEL]) + pe;
        __nv_bfloat16 hi, lo; split2(x, hi, lo);
        int row = e / D_MODEL;
        __nv_bfloat16* o = g_Xhl + (size_t)row * KBIG;
        o[d] = hi; o[D_MODEL + d] = hi; o[2 * D_MODEL + d] = lo;
    } else if (e < CONV_T1 + CONV_T2) {
        int e2 = e - CONV_T1;
        int j = e2 / D_MODEL, k = e2 % D_MODEL;
        int part = j / OUT_DIM, o = j % OUT_DIM;
        const float* w = (part < 2) ? k_w : v_w;
        float x = w[(size_t)o * TWO_D + (part & 1) * D_MODEL + k];
        __nv_bfloat16 hi, lo; split2(x, hi, lo);
        __nv_bfloat16* dst = g_Whl + (size_t)j * KBIG;
        dst[k] = hi; dst[D_MODEL + k] = lo; dst[2 * D_MODEL + k] = hi;
    }
}

// vs_s^T slices -> [WAY][OUT_DIM][KP2] hi-only, pad 140..159 zero
__global__ void conv_vsT_kernel()
{
    int e = blockIdx.x * blockDim.x + threadIdx.x;
    const int total = WAY * OUT_DIM * KP2;
    if (e >= total) return;
    int w = e / (OUT_DIM * KP2);
    int rem = e % (OUT_DIM * KP2);
    int d = rem / KP2, j = rem % KP2;
    __nv_bfloat16 v = __float2bfloat16(0.f);
    if (j < SEG)
        v = __float2bfloat16(g_vs_s[(size_t)(w * SEG + j) * OUT_DIM + d]);
    g_Vhl[e] = v;
}

// ---------------------------------------------------------------------------
// assemble tuple features + LayerNorm(k) -> split bf16 layouts, plain v.
// support rows -> KShl (B-layout hi,lo,hi); query rows -> KQhl (A-layout hi,hi,lo)
// ---------------------------------------------------------------------------
__global__ __launch_bounds__(256)
void assemble_kernel(const float* __restrict__ k_b, const float* __restrict__ v_b,
                     const float* __restrict__ ln_g, const float* __restrict__ ln_b)
{
    int rl = blockIdx.x;
    int n = rl / L_TUP, l = rl % L_TUP;
    int t0 = c_t0[l], t1 = c_t1[l];
    const float* P0 = g_P + (size_t)(n * SEQ_LEN + t0) * NSTACK;
    const float* P1 = g_P + (size_t)(n * SEQ_LEN + t1) * NSTACK;

    const bool isSup = (n < N_SUPPORT);
    __nv_bfloat16* kd;
    float* vsd;
    if (isSup) {
        kd  = g_KShl + (size_t)(n * L_TUP + l) * KSC;
        vsd = g_vs_s + (size_t)(n * L_TUP + l) * OUT_DIM;
    } else {
        int m = n - N_SUPPORT;
        kd  = g_KQhl + (size_t)(m * L_TUP + l) * KSC;
        vsd = g_vs_q + (size_t)(m * L_TUP + l) * OUT_DIM;
    }

    __shared__ float kbuf[OUT_DIM];
    float s = 0.f, s2 = 0.f;
    for (int o = threadIdx.x; o < OUT_DIM; o += blockDim.x) {
        float kv = P0[o] + P1[OUT_DIM + o] + k_b[o];
        kbuf[o] = kv; s += kv; s2 += kv * kv;
        vsd[o] = P0[2 * OUT_DIM + o] + P1[3 * OUT_DIM + o] + v_b[o];
    }
    int lane = threadIdx.x & 31, wid = threadIdx.x >> 5;
    #pragma unroll
    for (int off = 16; off; off >>= 1) {
        s  += __shfl_xor_sync(0xffffffffu, s,  off);
        s2 += __shfl_xor_sync(0xffffffffu, s2, off);
    }
    __shared__ float ws[8], ws2[8], sm_mean, sm_rstd;
    if (lane == 0) { ws[wid] = s; ws2[wid] = s2; }
    __syncthreads();
    if (threadIdx.x == 0) {
        float S = 0.f, S2 = 0.f;
        #pragma unroll
        for (int w = 0; w < 8; w++) { S += ws[w]; S2 += ws2[w]; }
        float mean = S / (float)OUT_DIM;
        float var  = S2 / (float)OUT_DIM - mean * mean;
        sm_mean = mean; sm_rstd = rsqrtf(var + 1e-5f);
    }
    __syncthreads();
    float mean = sm_mean, rstd = sm_rstd;
    for (int o = threadIdx.x; o < OUT_DIM; o += blockDim.x) {
        float y = (kbuf[o] - mean) * rstd * ln_g[o] + ln_b[o];
        __nv_bfloat16 hi, lo; split2(y, hi, lo);
        kd[o] = hi;
        kd[OUT_DIM + o]     = isSup ? lo : hi;
        kd[2 * OUT_DIM + o] = isSup ? hi : lo;
    }
}

// ---------------------------------------------------------------------------
// per-row blockwise softmax; writes hi-only attn (K=160) directly to g_Ahl.
// ---------------------------------------------------------------------------
__global__ __launch_bounds__(160)
void softmax_kernel()
{
    int row = blockIdx.x;
    int warp = threadIdx.x >> 5, lane = threadIdx.x & 31;
    const float* p = g_S + (size_t)row * ROWS_S + warp * SEG;
    float v[5]; float mx = -INFINITY;
    #pragma unroll
    for (int i = 0; i < 5; i++) {
        int c = lane + 32 * i;
        v[i] = (c < SEG) ? p[c] : -INFINITY;
        mx = fmaxf(mx, v[i]);
    }
    #pragma unroll
    for (int off = 16; off; off >>= 1)
        mx = fmaxf(mx, __shfl_xor_sync(0xffffffffu, mx, off));
    float sm = 0.f;
    #pragma unroll
    for (int i = 0; i < 5; i++) {
        int c = lane + 32 * i;
        v[i] = (c < SEG) ? expf(v[i] - mx) : 0.f;
        sm += v[i];
    }
    #pragma unroll
    for (int off = 16; off; off >>= 1)
        sm += __shfl_xor_sync(0xffffffffu, sm, off);
    float inv = 1.f / sm;

    __nv_bfloat16* a = g_Ahl + ((size_t)warp * ROWS_Q + row) * KP2;
    #pragma unroll
    for (int i = 0; i < 5; i++) {
        int c = lane + 32 * i;
        if (c < SEG)
            a[c] = __float2bfloat16(v[i] * inv);
    }
    if (lane < KP2 - SEG)              // zero pad 140..159
        a[SEG + lane] = __float2bfloat16(0.f);
}

// ---------------------------------------------------------------------------
// per-query Gram matrix + distances -> sim, ori  (float4-vectorized)
// ---------------------------------------------------------------------------
__global__ __launch_bounds__(256)
void finalize_kernel(float* __restrict__ out)
{
    int q = blockIdx.x;
    const float4* v4 = (const float4*)(g_vs_q + (size_t)q * PLANE);
    const float4* pp4[WAY];
    #pragma unroll
    for (int w = 0; w < WAY; w++)
        pp4[w] = (const float4*)(g_proto + (size_t)w * ROWS_Q * OUT_DIM
                                 + (size_t)q * PLANE);

    float acc[21];
    #pragma unroll
    for (int i = 0; i < 21; i++) acc[i] = 0.f;

    const int NV4 = PLANE / 4;                 // 8064
    for (int i = threadIdx.x; i < NV4; i += blockDim.x) {
        float4 vv = v4[i];
        float4 b0 = pp4[0][i], b1 = pp4[1][i], b2 = pp4[2][i],
               b3 = pp4[3][i], b4 = pp4[4][i];
        #pragma unroll
        for (int e = 0; e < 4; e++) {
            float vvv = (&vv.x)[e];
            float a0 = (&b0.x)[e], a1 = (&b1.x)[e], a2 = (&b2.x)[e],
                  a3 = (&b3.x)[e], a4 = (&b4.x)[e];
            acc[0]  += a0 * a0;  acc[1]  += a0 * a1;  acc[2]  += a0 * a2;
            acc[3]  += a0 * a3;  acc[4]  += a0 * a4;
            acc[5]  += a1 * a1;  acc[6]  += a1 * a2;  acc[7]  += a1 * a3;
            acc[8]  += a1 * a4;
            acc[9]  += a2 * a2;  acc[10] += a2 * a3;  acc[11] += a2 * a4;
            acc[12] += a3 * a3;  acc[13] += a3 * a4;
            acc[14] += a4 * a4;
            acc[15] += vvv * a0; acc[16] += vvv * a1; acc[17] += vvv * a2;
            acc[18] += vvv * a3; acc[19] += vvv * a4;
            acc[20] += vvv * vvv;
        }
    }

    int lane = threadIdx.x & 31, wid = threadIdx.x >> 5;
    __shared__ float part[21][8];
    #pragma unroll
    for (int i = 0; i < 21; i++) {
        float a = acc[i];
        #pragma unroll
        for (int off = 16; off; off >>= 1)
            a += __shfl_xor_sync(0xffffffffu, a, off);
        if (lane == 0) part[i][wid] = a;
    }
    __syncthreads();
    __shared__ float tot[21];
    if (threadIdx.x < 21) {
        float sSum = 0.f;
        #pragma unroll
        for (int w = 0; w < 8; w++) sSum += part[threadIdx.x][w];
        tot[threadIdx.x] = sSum;
    }
    __syncthreads();
    if (threadIdx.x == 0) {
        float G[WAY][WAY];
        int t = 0;
        for (int a = 0; a < WAY; a++)
            for (int b = a; b < WAY; b++) { G[a][b] = tot[t]; G[b][a] = tot[t]; t++; }
        float D[WAY];
        for (int w = 0; w < WAY; w++) D[w] = tot[15 + w];
        float VV = tot[20];
        float nrm[WAY];
        for (int w = 0; w < WAY; w++) nrm[w] = sqrtf(G[w][w]);
        for (int a = 0; a < WAY; a++)
            for (int b = 0; b < WAY; b++)
                out[q * WAY * WAY + a * WAY + b] =
                    G[a][b] / fmaxf(nrm[a] * nrm[b], 1e-8f);
        for (int w = 0; w < WAY; w++)
            out[N_QUERIES * WAY * WAY + q * WAY + w] =
                -(VV - 2.f * D[w] + G[w][w]) / (float)L_TUP;
    }
}

// ---------------------------------------------------------------------------
// Launch
// ---------------------------------------------------------------------------
extern "C" void kernel_launch(void* const* d_in, const int* in_sizes, int n_in,
                              void* d_out, int out_size)
{
    const float* support = (const float*)d_in[0];
    const float* queries = (const float*)d_in[2];
    const float* k_w  = (const float*)d_in[3];
    const float* k_b  = (const float*)d_in[4];
    const float* v_w  = (const float*)d_in[5];
    const float* v_b  = (const float*)d_in[6];
    const float* ln_g = (const float*)d_in[7];
    const float* ln_b = (const float*)d_in[8];
    float* out = (float*)d_out;

    float *P, *S, *proto;
    __nv_bfloat16 *Xhl, *Whl, *KQhl, *KShl, *Ahl, *Vhl;
    cudaGetSymbolAddress((void**)&Xhl,   g_Xhl);
    cudaGetSymbolAddress((void**)&Whl,   g_Whl);
    cudaGetSymbolAddress((void**)&P,     g_P);
    cudaGetSymbolAddress((void**)&KQhl,  g_KQhl);
    cudaGetSymbolAddress((void**)&KShl,  g_KShl);
    cudaGetSymbolAddress((void**)&S,     g_S);
    cudaGetSymbolAddress((void**)&Ahl,   g_Ahl);
    cudaGetSymbolAddress((void**)&Vhl,   g_Vhl);
    cudaGetSymbolAddress((void**)&proto, g_proto);

    // 1. fused PE + hi/lo input conversion + weight conversion (one launch)
    {
        int total = CONV_T1 + CONV_T2;
        conv_inputs_kernel<<<(total + 255) / 256, 256>>>(support, queries, k_w, v_w);
    }
    // 2. P = X @ Wt^T  [1800, 4608], K=6144
    {
        dim3 grid(NSTACK / 128, (ROWS_X + 127) / 128, 1);
        gemm_mma<<<grid, 256>>>(Xhl, Whl, P, ROWS_X, NSTACK, KBIG, 1.0f, 0, 0, 0);
    }
    // 3. assemble -> KQhl/KShl (split bf16) + vs float
    assemble_kernel<<<N_TOTAL * L_TUP, 256>>>(k_b, v_b, ln_g, ln_b);
    // 4. scores = ks_q @ ks_s^T / sqrt(OUT_DIM)  [5600, 700], K=3456
    {
        dim3 grid((ROWS_S + 127) / 128, (ROWS_Q + 127) / 128, 1);
        gemm_mma<<<grid, 256>>>(KQhl, KShl, S, ROWS_Q, ROWS_S, KSC,
                                1.0f / sqrtf((float)OUT_DIM), 0, 0, 0);
    }
    // 5. softmax -> g_Ahl (hi-only) directly
    softmax_kernel<<<ROWS_Q, 160>>>();
    // 6. vs_s^T hi for proto GEMM
    conv_vsT_kernel<<<(WAY * OUT_DIM * KP2 + 255) / 256, 256>>>();
    // 7. proto[w] = attn_w @ vs_w  [5600, 1152], K=160 — batched over z
    {
        dim3 grid(OUT_DIM / 128, (ROWS_Q + 127) / 128, WAY);
        gemm_mma<<<grid, 256>>>(Ahl, Vhl, proto, ROWS_Q, OUT_DIM, KP2, 1.0f,
                                (size_t)ROWS_Q * KP2,
                                (size_t)OUT_DIM * KP2,
                                (size_t)ROWS_Q * OUT_DIM);
    }
    // 8. finalize
    finalize_kernel<<<N_QUERIES, 256>>>(out);
}

// round 12
// speedup vs baseline: 1.4305x; 1.0428x over previous
#include <cuda_runtime.h>
#include <cuda_bf16.h>
#include <math.h>
#include <stdint.h>

// ---------------------------------------------------------------------------
// Problem constants
// ---------------------------------------------------------------------------
#define SEQ_LEN   8
#define D_MODEL   2048
#define OUT_DIM   1152
#define WAY       5
#define SHOT      5
#define N_SUPPORT 25
#define N_QUERIES 200
#define N_TOTAL   225
#define L_TUP     28
#define TWO_D     4096
#define NSTACK    4608          // 4 * OUT_DIM (k h0, k h1, v h0, v h1)
#define ROWS_X    1800          // N_TOTAL * SEQ_LEN
#define ROWS_Q    5600          // N_QUERIES * L_TUP
#define ROWS_S    700           // N_SUPPORT * L_TUP
#define SEG       140           // SHOT * L_TUP
#define PLANE     32256         // L_TUP * OUT_DIM

// hi/lo-split K sizes (3x concatenated: A=(hi,hi,lo), B=(hi,lo,hi))
#define KBIG      6144          // 3 * 2048
#define KSC       3456          // 3 * 1152
// proto GEMM uses hi-only operands: K = 140 padded to 160 (mult of 32)
#define KP2       160

__constant__ int c_t0[L_TUP] = {0,0,0,0,0,0,0,1,1,1,1,1,1,2,2,2,2,2,3,3,3,3,4,4,4,5,5,6};
__constant__ int c_t1[L_TUP] = {1,2,3,4,5,6,7,2,3,4,5,6,7,3,4,5,6,7,4,5,6,7,5,6,7,6,7,7};

// ---------------------------------------------------------------------------
// Scratch (device globals; no allocation allowed)
// ---------------------------------------------------------------------------
__device__ __nv_bfloat16  g_Xhl[(size_t)ROWS_X * KBIG];     // A-layout (hi,hi,lo)
__device__ __nv_bfloat16  g_Whl[(size_t)NSTACK * KBIG];     // B-layout (hi,lo,hi)
__device__ float          g_P[(size_t)ROWS_X * NSTACK];
__device__ __nv_bfloat16  g_vs_s[ROWS_S * OUT_DIM];         // bf16 (feeds proto B only)
__device__ __nv_bfloat16  g_vs_q[ROWS_Q * OUT_DIM];         // bf16 (feeds finalize only)
__device__ __nv_bfloat16  g_KQhl[(size_t)ROWS_Q * KSC];     // A-layout (from assemble)
__device__ __nv_bfloat16  g_KShl[(size_t)ROWS_S * KSC];     // B-layout (from assemble)
__device__ float          g_S[(size_t)ROWS_Q * ROWS_S];     // scores (read-only after gemm)
__device__ __nv_bfloat16  g_Ahl[(size_t)WAY * ROWS_Q * KP2];   // attn hi (from softmax)
__device__ __nv_bfloat16  g_Vhl[(size_t)WAY * OUT_DIM * KP2];  // vs_s^T hi slices
__device__ __nv_bfloat16  g_proto[(size_t)WAY * ROWS_Q * OUT_DIM];  // bf16

// ---------------------------------------------------------------------------
// Helpers
// ---------------------------------------------------------------------------
__device__ __forceinline__ uint32_t smem_u32(const void* p) {
    uint32_t a;
    asm("{ .reg .u64 t; cvta.to.shared.u64 t, %1; cvt.u32.u64 %0, t; }"
        : "=r"(a) : "l"(p));
    return a;
}

#define CP16(dst, src) \
    asm volatile("cp.async.cg.shared.global [%0], [%1], 16;" :: "r"(dst), "l"(src))
#define CP_COMMIT() asm volatile("cp.async.commit_group;" ::: "memory")
#define CP_WAIT(n)  asm volatile("cp.async.wait_group %0;" :: "n"(n) : "memory")

__device__ __forceinline__ void split2(float x, __nv_bfloat16& hi, __nv_bfloat16& lo) {
    hi = __float2bfloat16(x);
    lo = __float2bfloat16(x - __bfloat162float(hi));
}

#define LDMX4(d0,d1,d2,d3,addr) \
    asm volatile("ldmatrix.sync.aligned.m8n8.x4.shared.b16 {%0,%1,%2,%3}, [%4];" \
        : "=r"(d0), "=r"(d1), "=r"(d2), "=r"(d3) : "r"(addr))

#define MMA16816(acc, a, b) \
    asm volatile("mma.sync.aligned.m16n8k16.row.col.f32.bf16.bf16.f32 " \
        "{%0,%1,%2,%3}, {%4,%5,%6,%7}, {%8,%9}, {%0,%1,%2,%3};" \
        : "+f"((acc)[0]), "+f"((acc)[1]), "+f"((acc)[2]), "+f"((acc)[3]) \
        : "r"((a)[0]), "r"((a)[1]), "r"((a)[2]), "r"((a)[3]), \
          "r"((b)[0]), "r"((b)[1]))

// ---------------------------------------------------------------------------
// mma.sync bf16 GEMM (R5-proven inner loop): C[M,N] = alpha * A[M,K] * B[N,K]^T
// 128x128 CTA tile, BK=32, 4-stage cp.async pipeline, single barrier per
// chunk, 8 warps (2x4), warp tile 64x32 via m16n8k16. Batched over
// blockIdx.z via strides. 2 CTAs/SM. K multiple of 32. OOB rows clamped.
// Templated output: float (float2 stores) or __nv_bfloat16 (bf162 stores).
// ---------------------------------------------------------------------------
template<typename TOut>
__global__ __launch_bounds__(256, 2)
void gemm_mma(const __nv_bfloat16* __restrict__ A, const __nv_bfloat16* __restrict__ B,
              TOut* __restrict__ C, int M, int N, int K, float alpha,
              size_t aStride, size_t bStride, size_t cStride)
{
    __shared__ uint4 sbuf[4][1024];    // per stage: [0..511]=A (8KB), [512..1023]=B

    A += (size_t)blockIdx.z * aStride;
    B += (size_t)blockIdx.z * bStride;
    C += (size_t)blockIdx.z * cStride;

    const int tid  = threadIdx.x;
    const int lane = tid & 31;
    const int wid  = tid >> 5;
    const int wm   = wid >> 2;
    const int wn   = wid & 3;
    const int row0 = blockIdx.y * 128;
    const int col0 = blockIdx.x * 128;

    int l_sw[2];
    const __nv_bfloat16 *gA[2], *gB[2];
    #pragma unroll
    for (int i = 0; i < 2; i++) {
        int ch  = tid + i * 256;
        int row = ch >> 2, cq = ch & 3;
        l_sw[i] = row * 4 + ((cq ^ (row >> 1)) & 3);
        int ra = row0 + row; if (ra > M - 1) ra = M - 1;
        int rb = col0 + row; if (rb > N - 1) rb = N - 1;
        gA[i] = A + (size_t)ra * K + cq * 8;
        gB[i] = B + (size_t)rb * K + cq * 8;
    }

    const int NC = K >> 5;

    auto issue = [&](int stage, int c) {
        uint32_t base = smem_u32(&sbuf[stage][0]);
        #pragma unroll
        for (int i = 0; i < 2; i++) {
            CP16(base +        l_sw[i] * 16, gA[i] + c * 32);
            CP16(base + 8192 + l_sw[i] * 16, gB[i] + c * 32);
        }
        CP_COMMIT();
    };

    float acc[4][4][4];
    #pragma unroll
    for (int mi = 0; mi < 4; mi++)
        #pragma unroll
        for (int ni = 0; ni < 4; ni++)
            #pragma unroll
            for (int e = 0; e < 4; e++) acc[mi][ni][e] = 0.f;

    const int q = lane >> 3;
    const int r = lane & 7;

    auto compute = [&](int stage) {
        uint32_t abase = smem_u32(&sbuf[stage][0]);
        uint32_t bbase = abase + 8192;
        #pragma unroll
        for (int ks = 0; ks < 2; ks++) {
            uint32_t af[4][4];
            #pragma unroll
            for (int mi = 0; mi < 4; mi++) {
                int row = wm * 64 + mi * 16 + r + (q & 1) * 8;
                int cq  = ks * 2 + (q >> 1);
                uint32_t ad = abase + (uint32_t)(row * 4 + ((cq ^ (row >> 1)) & 3)) * 16u;
                LDMX4(af[mi][0], af[mi][1], af[mi][2], af[mi][3], ad);
            }
            uint32_t bf[4][2];
            #pragma unroll
            for (int nh = 0; nh < 2; nh++) {
                int ni  = nh * 2 + (q >> 1);
                int row = wn * 32 + ni * 8 + r;
                int cq  = ks * 2 + (q & 1);
                uint32_t bd = bbase + (uint32_t)(row * 4 + ((cq ^ (row >> 1)) & 3)) * 16u;
                LDMX4(bf[nh*2][0], bf[nh*2][1], bf[nh*2+1][0], bf[nh*2+1][1], bd);
            }
            #pragma unroll
            for (int mi = 0; mi < 4; mi++)
                #pragma unroll
                for (int ni = 0; ni < 4; ni++)
                    MMA16816(acc[mi][ni], af[mi], bf[ni]);
        }
    };

    issue(0, 0);
    if (NC > 1) issue(1, 1);
    if (NC > 2) issue(2, 2);
    for (int c = 0; c < NC; c++) {
        if (c + 2 < NC)      CP_WAIT(2);
        else if (c + 1 < NC) CP_WAIT(1);
        else                 CP_WAIT(0);
        __syncthreads();
        if (c + 3 < NC) issue((c + 3) & 3, c + 3);
        compute(c & 3);
    }

    const int g  = lane >> 2;
    const int tg = lane & 3;
    #pragma unroll
    for (int mi = 0; mi < 4; mi++) {
        int rr0 = row0 + wm * 64 + mi * 16 + g;
        int rr1 = rr0 + 8;
        #pragma unroll
        for (int ni = 0; ni < 4; ni++) {
            int cc = col0 + wn * 32 + ni * 8 + tg * 2;
            if (cc < N) {
                if (rr0 < M) {
                    if (sizeof(TOut) == 4) {
                        float2 v = make_float2(alpha * acc[mi][ni][0],
                                               alpha * acc[mi][ni][1]);
                        *(float2*)((float*)C + (size_t)rr0 * N + cc) = v;
                    } else {
                        __nv_bfloat162 h;
                        h.x = __float2bfloat16(alpha * acc[mi][ni][0]);
                        h.y = __float2bfloat16(alpha * acc[mi][ni][1]);
                        *(__nv_bfloat162*)((__nv_bfloat16*)C + (size_t)rr0 * N + cc) = h;
                    }
                }
                if (rr1 < M) {
                    if (sizeof(TOut) == 4) {
                        float2 v = make_float2(alpha * acc[mi][ni][2],
                                               alpha * acc[mi][ni][3]);
                        *(float2*)((float*)C + (size_t)rr1 * N + cc) = v;
                    } else {
                        __nv_bfloat162 h;
                        h.x = __float2bfloat16(alpha * acc[mi][ni][2]);
                        h.y = __float2bfloat16(alpha * acc[mi][ni][3]);
                        *(__nv_bfloat162*)((__nv_bfloat16*)C + (size_t)rr1 * N + cc) = h;
                    }
                }
            }
        }
    }
}

// ---------------------------------------------------------------------------
// Fused conversion: one launch covers both
//   part 1: X = [support; queries] + PE -> A-layout (hi,hi,lo) in g_Xhl
//   part 2: stacked weights -> B-layout (hi,lo,hi) in g_Whl
// ---------------------------------------------------------------------------
#define CONV_T1 (ROWS_X * D_MODEL)
#define CONV_T2 (NSTACK * D_MODEL)

__global__ void conv_inputs_kernel(const float* __restrict__ support,
                                   const float* __restrict__ queries,
                                   const float* __restrict__ k_w,
                                   const float* __restrict__ v_w)
{
    int e = blockIdx.x * blockDim.x + threadIdx.x;
    if (e < CONV_T1) {
        int n = e / (SEQ_LEN * D_MODEL);
        int rem = e % (SEQ_LEN * D_MODEL);
        int s = rem / D_MODEL, d = rem % D_MODEL;
        const float c = -9.210340371976184f / (float)D_MODEL;
        float div = expf((float)(2 * (d >> 1)) * c);
        float arg = (float)s * div;
        float pe = ((d & 1) ? cosf(arg) : sinf(arg)) * 0.1f;
        float x = ((n < N_SUPPORT) ? support[e]
                                   : queries[e - N_SUPPORT * SEQ_LEN * D_MODEL]) + pe;
        __nv_bfloat16 hi, lo; split2(x, hi, lo);
        int row = e / D_MODEL;
        __nv_bfloat16* o = g_Xhl + (size_t)row * KBIG;
        o[d] = hi; o[D_MODEL + d] = hi; o[2 * D_MODEL + d] = lo;
    } else if (e < CONV_T1 + CONV_T2) {
        int e2 = e - CONV_T1;
        int j = e2 / D_MODEL, k = e2 % D_MODEL;
        int part = j / OUT_DIM, o = j % OUT_DIM;
        const float* w = (part < 2) ? k_w : v_w;
        float x = w[(size_t)o * TWO_D + (part & 1) * D_MODEL + k];
        __nv_bfloat16 hi, lo; split2(x, hi, lo);
        __nv_bfloat16* dst = g_Whl + (size_t)j * KBIG;
        dst[k] = hi; dst[D_MODEL + k] = lo; dst[2 * D_MODEL + k] = hi;
    }
}

// vs_s^T slices -> [WAY][OUT_DIM][KP2], pad 140..159 zero (vs_s already bf16)
__global__ void conv_vsT_kernel()
{
    int e = blockIdx.x * blockDim.x + threadIdx.x;
    const int total = WAY * OUT_DIM * KP2;
    if (e >= total) return;
    int w = e / (OUT_DIM * KP2);
    int rem = e % (OUT_DIM * KP2);
    int d = rem / KP2, j = rem % KP2;
    __nv_bfloat16 v = __float2bfloat16(0.f);
    if (j < SEG)
        v = g_vs_s[(size_t)(w * SEG + j) * OUT_DIM + d];
    g_Vhl[e] = v;
}

// ---------------------------------------------------------------------------
// assemble tuple features + LayerNorm(k) -> split bf16 layouts, v -> bf16.
// support rows -> KShl (B-layout hi,lo,hi); query rows -> KQhl (A-layout hi,hi,lo)
// ---------------------------------------------------------------------------
__global__ __launch_bounds__(256)
void assemble_kernel(const float* __restrict__ k_b, const float* __restrict__ v_b,
                     const float* __restrict__ ln_g, const float* __restrict__ ln_b)
{
    int rl = blockIdx.x;
    int n = rl / L_TUP, l = rl % L_TUP;
    int t0 = c_t0[l], t1 = c_t1[l];
    const float* P0 = g_P + (size_t)(n * SEQ_LEN + t0) * NSTACK;
    const float* P1 = g_P + (size_t)(n * SEQ_LEN + t1) * NSTACK;

    const bool isSup = (n < N_SUPPORT);
    __nv_bfloat16* kd;
    __nv_bfloat16* vsd;
    if (isSup) {
        kd  = g_KShl + (size_t)(n * L_TUP + l) * KSC;
        vsd = g_vs_s + (size_t)(n * L_TUP + l) * OUT_DIM;
    } else {
        int m = n - N_SUPPORT;
        kd  = g_KQhl + (size_t)(m * L_TUP + l) * KSC;
        vsd = g_vs_q + (size_t)(m * L_TUP + l) * OUT_DIM;
    }

    __shared__ float kbuf[OUT_DIM];
    float s = 0.f, s2 = 0.f;
    for (int o = threadIdx.x; o < OUT_DIM; o += blockDim.x) {
        float kv = P0[o] + P1[OUT_DIM + o] + k_b[o];
        kbuf[o] = kv; s += kv; s2 += kv * kv;
        vsd[o] = __float2bfloat16(P0[2 * OUT_DIM + o] + P1[3 * OUT_DIM + o] + v_b[o]);
    }
    int lane = threadIdx.x & 31, wid = threadIdx.x >> 5;
    #pragma unroll
    for (int off = 16; off; off >>= 1) {
        s  += __shfl_xor_sync(0xffffffffu, s,  off);
        s2 += __shfl_xor_sync(0xffffffffu, s2, off);
    }
    __shared__ float ws[8], ws2[8], sm_mean, sm_rstd;
    if (lane == 0) { ws[wid] = s; ws2[wid] = s2; }
    __syncthreads();
    if (threadIdx.x == 0) {
        float S = 0.f, S2 = 0.f;
        #pragma unroll
        for (int w = 0; w < 8; w++) { S += ws[w]; S2 += ws2[w]; }
        float mean = S / (float)OUT_DIM;
        float var  = S2 / (float)OUT_DIM - mean * mean;
        sm_mean = mean; sm_rstd = rsqrtf(var + 1e-5f);
    }
    __syncthreads();
    float mean = sm_mean, rstd = sm_rstd;
    for (int o = threadIdx.x; o < OUT_DIM; o += blockDim.x) {
        float y = (kbuf[o] - mean) * rstd * ln_g[o] + ln_b[o];
        __nv_bfloat16 hi, lo; split2(y, hi, lo);
        kd[o] = hi;
        kd[OUT_DIM + o]     = isSup ? lo : hi;
        kd[2 * OUT_DIM + o] = isSup ? hi : lo;
    }
}

// ---------------------------------------------------------------------------
// per-row blockwise softmax; writes hi-only attn (K=160) directly to g_Ahl.
// ---------------------------------------------------------------------------
__global__ __launch_bounds__(160)
void softmax_kernel()
{
    int row = blockIdx.x;
    int warp = threadIdx.x >> 5, lane = threadIdx.x & 31;
    const float* p = g_S + (size_t)row * ROWS_S + warp * SEG;
    float v[5]; float mx = -INFINITY;
    #pragma unroll
    for (int i = 0; i < 5; i++) {
        int c = lane + 32 * i;
        v[i] = (c < SEG) ? p[c] : -INFINITY;
        mx = fmaxf(mx, v[i]);
    }
    #pragma unroll
    for (int off = 16; off; off >>= 1)
        mx = fmaxf(mx, __shfl_xor_sync(0xffffffffu, mx, off));
    float sm = 0.f;
    #pragma unroll
    for (int i = 0; i < 5; i++) {
        int c = lane + 32 * i;
        v[i] = (c < SEG) ? expf(v[i] - mx) : 0.f;
        sm += v[i];
    }
    #pragma unroll
    for (int off = 16; off; off >>= 1)
        sm += __shfl_xor_sync(0xffffffffu, sm, off);
    float inv = 1.f / sm;

    __nv_bfloat16* a = g_Ahl + ((size_t)warp * ROWS_Q + row) * KP2;
    #pragma unroll
    for (int i = 0; i < 5; i++) {
        int c = lane + 32 * i;
        if (c < SEG)
            a[c] = __float2bfloat16(v[i] * inv);
    }
    if (lane < KP2 - SEG)              // zero pad 140..159
        a[SEG + lane] = __float2bfloat16(0.f);
}

// ---------------------------------------------------------------------------
// per-query Gram matrix + distances -> sim, ori  (bf16 inputs, uint4 loads)
// ---------------------------------------------------------------------------
__global__ __launch_bounds__(256)
void finalize_kernel(float* __restrict__ out)
{
    int q = blockIdx.x;
    const uint4* v8 = (const uint4*)(g_vs_q + (size_t)q * PLANE);
    const uint4* pp8[WAY];
    #pragma unroll
    for (int w = 0; w < WAY; w++)
        pp8[w] = (const uint4*)(g_proto + (size_t)w * ROWS_Q * OUT_DIM
                                + (size_t)q * PLANE);

    float acc[21];
    #pragma unroll
    for (int i = 0; i < 21; i++) acc[i] = 0.f;

    const int NV8 = PLANE / 8;                 // 4032
    for (int i = threadIdx.x; i < NV8; i += blockDim.x) {
        uint4 uv = v8[i];
        uint4 u0 = pp8[0][i], u1 = pp8[1][i], u2 = pp8[2][i],
              u3 = pp8[3][i], u4 = pp8[4][i];
        float fv[8], f0[8], f1[8], f2[8], f3[8], f4[8];
        #pragma unroll
        for (int h = 0; h < 4; h++) {
            float2 t;
            t = __bfloat1622float2(*(__nv_bfloat162*)((uint32_t*)&uv + h));
            fv[2*h] = t.x; fv[2*h+1] = t.y;
            t = __bfloat1622float2(*(__nv_bfloat162*)((uint32_t*)&u0 + h));
            f0[2*h] = t.x; f0[2*h+1] = t.y;
            t = __bfloat1622float2(*(__nv_bfloat162*)((uint32_t*)&u1 + h));
            f1[2*h] = t.x; f1[2*h+1] = t.y;
            t = __bfloat1622float2(*(__nv_bfloat162*)((uint32_t*)&u2 + h));
            f2[2*h] = t.x; f2[2*h+1] = t.y;
            t = __bfloat1622float2(*(__nv_bfloat162*)((uint32_t*)&u3 + h));
            f3[2*h] = t.x; f3[2*h+1] = t.y;
            t = __bfloat1622float2(*(__nv_bfloat162*)((uint32_t*)&u4 + h));
            f4[2*h] = t.x; f4[2*h+1] = t.y;
        }
        #pragma unroll
        for (int e = 0; e < 8; e++) {
            float vvv = fv[e];
            float a0 = f0[e], a1 = f1[e], a2 = f2[e], a3 = f3[e], a4 = f4[e];
            acc[0]  += a0 * a0;  acc[1]  += a0 * a1;  acc[2]  += a0 * a2;
            acc[3]  += a0 * a3;  acc[4]  += a0 * a4;
            acc[5]  += a1 * a1;  acc[6]  += a1 * a2;  acc[7]  += a1 * a3;
            acc[8]  += a1 * a4;
            acc[9]  += a2 * a2;  acc[10] += a2 * a3;  acc[11] += a2 * a4;
            acc[12] += a3 * a3;  acc[13] += a3 * a4;
            acc[14] += a4 * a4;
            acc[15] += vvv * a0; acc[16] += vvv * a1; acc[17] += vvv * a2;
            acc[18] += vvv * a3; acc[19] += vvv * a4;
            acc[20] += vvv * vvv;
        }
    }

    int lane = threadIdx.x & 31, wid = threadIdx.x >> 5;
    __shared__ float part[21][8];
    #pragma unroll
    for (int i = 0; i < 21; i++) {
        float a = acc[i];
        #pragma unroll
        for (int off = 16; off; off >>= 1)
            a += __shfl_xor_sync(0xffffffffu, a, off);
        if (lane == 0) part[i][wid] = a;
    }
    __syncthreads();
    __shared__ float tot[21];
    if (threadIdx.x < 21) {
        float sSum = 0.f;
        #pragma unroll
        for (int w = 0; w < 8; w++) sSum += part[threadIdx.x][w];
        tot[threadIdx.x] = sSum;
    }
    __syncthreads();
    if (threadIdx.x == 0) {
        float G[WAY][WAY];
        int t = 0;
        for (int a = 0; a < WAY; a++)
            for (int b = a; b < WAY; b++) { G[a][b] = tot[t]; G[b][a] = tot[t]; t++; }
        float D[WAY];
        for (int w = 0; w < WAY; w++) D[w] = tot[15 + w];
        float VV = tot[20];
        float nrm[WAY];
        for (int w = 0; w < WAY; w++) nrm[w] = sqrtf(G[w][w]);
        for (int a = 0; a < WAY; a++)
            for (int b = 0; b < WAY; b++)
                out[q * WAY * WAY + a * WAY + b] =
                    G[a][b] / fmaxf(nrm[a] * nrm[b], 1e-8f);
        for (int w = 0; w < WAY; w++)
            out[N_QUERIES * WAY * WAY + q * WAY + w] =
                -(VV - 2.f * D[w] + G[w][w]) / (float)L_TUP;
    }
}

// ---------------------------------------------------------------------------
// Launch
// ---------------------------------------------------------------------------
extern "C" void kernel_launch(void* const* d_in, const int* in_sizes, int n_in,
                              void* d_out, int out_size)
{
    const float* support = (const float*)d_in[0];
    const float* queries = (const float*)d_in[2];
    const float* k_w  = (const float*)d_in[3];
    const float* k_b  = (const float*)d_in[4];
    const float* v_w  = (const float*)d_in[5];
    const float* v_b  = (const float*)d_in[6];
    const float* ln_g = (const float*)d_in[7];
    const float* ln_b = (const float*)d_in[8];
    float* out = (float*)d_out;

    float *P, *S;
    __nv_bfloat16 *Xhl, *Whl, *KQhl, *KShl, *Ahl, *Vhl, *proto;
    cudaGetSymbolAddress((void**)&Xhl,   g_Xhl);
    cudaGetSymbolAddress((void**)&Whl,   g_Whl);
    cudaGetSymbolAddress((void**)&P,     g_P);
    cudaGetSymbolAddress((void**)&KQhl,  g_KQhl);
    cudaGetSymbolAddress((void**)&KShl,  g_KShl);
    cudaGetSymbolAddress((void**)&S,     g_S);
    cudaGetSymbolAddress((void**)&Ahl,   g_Ahl);
    cudaGetSymbolAddress((void**)&Vhl,   g_Vhl);
    cudaGetSymbolAddress((void**)&proto, g_proto);

    // 1. fused PE + hi/lo input conversion + weight conversion (one launch)
    {
        int total = CONV_T1 + CONV_T2;
        conv_inputs_kernel<<<(total + 255) / 256, 256>>>(support, queries, k_w, v_w);
    }
    // 2. P = X @ Wt^T  [1800, 4608], K=6144  (fp32 out)
    {
        dim3 grid(NSTACK / 128, (ROWS_X + 127) / 128, 1);
        gemm_mma<float><<<grid, 256>>>(Xhl, Whl, P, ROWS_X, NSTACK, KBIG, 1.0f,
                                       0, 0, 0);
    }
    // 3. assemble -> KQhl/KShl (split bf16) + vs bf16
    assemble_kernel<<<N_TOTAL * L_TUP, 256>>>(k_b, v_b, ln_g, ln_b);
    // 4. scores = ks_q @ ks_s^T / sqrt(OUT_DIM)  [5600, 700], K=3456  (fp32 out)
    {
        dim3 grid((ROWS_S + 127) / 128, (ROWS_Q + 127) / 128, 1);
        gemm_mma<float><<<grid, 256>>>(KQhl, KShl, S, ROWS_Q, ROWS_S, KSC,
                                       1.0f / sqrtf((float)OUT_DIM), 0, 0, 0);
    }
    // 5. softmax -> g_Ahl (hi-only) directly
    softmax_kernel<<<ROWS_Q, 160>>>();
    // 6. vs_s^T for proto GEMM
    conv_vsT_kernel<<<(WAY * OUT_DIM * KP2 + 255) / 256, 256>>>();
    // 7. proto[w] = attn_w @ vs_w  [5600, 1152], K=160 — batched, bf16 out
    {
        dim3 grid(OUT_DIM / 128, (ROWS_Q + 127) / 128, WAY);
        gemm_mma<__nv_bfloat16><<<grid, 256>>>(Ahl, Vhl, proto,
                                               ROWS_Q, OUT_DIM, KP2, 1.0f,
                                               (size_t)ROWS_Q * KP2,
                                               (size_t)OUT_DIM * KP2,
                                               (size_t)ROWS_Q * OUT_DIM);
    }
    // 8. finalize
    finalize_kernel<<<N_QUERIES, 256>>>(out);
}

// round 14
// speedup vs baseline: 1.7271x; 1.2073x over previous
#include <cuda_runtime.h>
#include <cuda_bf16.h>
#include <math.h>
#include <stdint.h>

// ---------------------------------------------------------------------------
// Problem constants
// ---------------------------------------------------------------------------
#define SEQ_LEN   8
#define D_MODEL   2048
#define OUT_DIM   1152
#define WAY       5
#define SHOT      5
#define N_SUPPORT 25
#define N_QUERIES 200
#define N_TOTAL   225
#define L_TUP     28
#define TWO_D     4096
#define NSTACK    4608          // 4 * OUT_DIM (k h0, k h1, v h0, v h1)
#define NK_HALF   2304          // 2 * OUT_DIM (k columns / v columns)
#define ROWS_X    1800          // N_TOTAL * SEQ_LEN
#define ROWS_Q    5600          // N_QUERIES * L_TUP
#define ROWS_S    700           // N_SUPPORT * L_TUP
#define SEG       140           // SHOT * L_TUP
#define PLANE     32256         // L_TUP * OUT_DIM

// hi/lo-split K sizes (3x concatenated: A=(hi,hi,lo), B=(hi,lo,hi))
#define KBIG      6144          // 3 * 2048
#define KSC       3456          // 3 * 1152
// proto GEMM + v-projection use hi-only operands (error-suppressed sinks)
#define KP2       160           // 140 padded to 160
#define KVH       2048          // v-projection hi-only K

__constant__ int c_t0[L_TUP] = {0,0,0,0,0,0,0,1,1,1,1,1,1,2,2,2,2,2,3,3,3,3,4,4,4,5,5,6};
__constant__ int c_t1[L_TUP] = {1,2,3,4,5,6,7,2,3,4,5,6,7,3,4,5,6,7,4,5,6,7,5,6,7,6,7,7};

// ---------------------------------------------------------------------------
// Scratch (device globals; no allocation allowed)
// ---------------------------------------------------------------------------
__device__ __nv_bfloat16  g_Xhl[(size_t)ROWS_X * KBIG];     // A-layout (hi,hi,lo); hi prefix = first 2048 cols
__device__ __nv_bfloat16  g_Whl[(size_t)NK_HALF * KBIG];    // k-weight rows, B-layout (hi,lo,hi)
__device__ __nv_bfloat16  g_Wv[(size_t)NK_HALF * KVH];      // v-weight rows, hi only
__device__ float          g_P[(size_t)ROWS_X * NSTACK];
__device__ __nv_bfloat16  g_vs_s[ROWS_S * OUT_DIM];         // bf16
__device__ __nv_bfloat16  g_vs_q[ROWS_Q * OUT_DIM];         // bf16
__device__ __nv_bfloat16  g_KQhl[(size_t)ROWS_Q * KSC];     // A-layout (from assemble)
__device__ __nv_bfloat16  g_KShl[(size_t)ROWS_S * KSC];     // B-layout (from assemble)
__device__ float          g_S[(size_t)ROWS_Q * ROWS_S];     // scores
__device__ __nv_bfloat16  g_Ahl[(size_t)WAY * ROWS_Q * KP2];   // attn hi (from softmax)
__device__ __nv_bfloat16  g_Vhl[(size_t)WAY * OUT_DIM * KP2];  // vs_s^T hi slices
__device__ __nv_bfloat16  g_proto[(size_t)WAY * ROWS_Q * OUT_DIM];  // bf16

// ---------------------------------------------------------------------------
// Helpers
// ---------------------------------------------------------------------------
__device__ __forceinline__ uint32_t smem_u32(const void* p) {
    uint32_t a;
    asm("{ .reg .u64 t; cvta.to.shared.u64 t, %1; cvt.u32.u64 %0, t; }"
        : "=r"(a) : "l"(p));
    return a;
}

#define CP16(dst, src) \
    asm volatile("cp.async.cg.shared.global [%0], [%1], 16;" :: "r"(dst), "l"(src))
#define CP_COMMIT() asm volatile("cp.async.commit_group;" ::: "memory")
#define CP_WAIT(n)  asm volatile("cp.async.wait_group %0;" :: "n"(n) : "memory")

__device__ __forceinline__ void split2(float x, __nv_bfloat16& hi, __nv_bfloat16& lo) {
    hi = __float2bfloat16(x);
    lo = __float2bfloat16(x - __bfloat162float(hi));
}

#define LDMX4(d0,d1,d2,d3,addr) \
    asm volatile("ldmatrix.sync.aligned.m8n8.x4.shared.b16 {%0,%1,%2,%3}, [%4];" \
        : "=r"(d0), "=r"(d1), "=r"(d2), "=r"(d3) : "r"(addr))

#define MMA16816(acc, a, b) \
    asm volatile("mma.sync.aligned.m16n8k16.row.col.f32.bf16.bf16.f32 " \
        "{%0,%1,%2,%3}, {%4,%5,%6,%7}, {%8,%9}, {%0,%1,%2,%3};" \
        : "+f"((acc)[0]), "+f"((acc)[1]), "+f"((acc)[2]), "+f"((acc)[3]) \
        : "r"((a)[0]), "r"((a)[1]), "r"((a)[2]), "r"((a)[3]), \
          "r"((b)[0]), "r"((b)[1]))

// ---------------------------------------------------------------------------
// mma.sync bf16 GEMM (R5-proven inner loop): C[M,N] = alpha * A[M,K] * B[N,K]^T
// with explicit row strides lda/ldb (elements) and output stride ldc.
// 128x128 CTA tile, BK=32, 4-stage cp.async pipeline, single barrier per
// chunk, 8 warps (2x4), warp tile 64x32. Batched over blockIdx.z via strides.
// 2 CTAs/SM. K multiple of 32. OOB rows clamped (outputs never stored).
// Templated output: float (float2 stores) or __nv_bfloat16 (bf162 stores).
// ---------------------------------------------------------------------------
template<typename TOut>
__global__ __launch_bounds__(256, 2)
void gemm_mma(const __nv_bfloat16* __restrict__ A, const __nv_bfloat16* __restrict__ B,
              TOut* __restrict__ C, int M, int N, int K, float alpha,
              int lda, int ldb, int ldc,
              size_t aStride, size_t bStride, size_t cStride)
{
    __shared__ uint4 sbuf[4][1024];    // per stage: [0..511]=A (8KB), [512..1023]=B

    A += (size_t)blockIdx.z * aStride;
    B += (size_t)blockIdx.z * bStride;
    C += (size_t)blockIdx.z * cStride;

    const int tid  = threadIdx.x;
    const int lane = tid & 31;
    const int wid  = tid >> 5;
    const int wm   = wid >> 2;
    const int wn   = wid & 3;
    const int row0 = blockIdx.y * 128;
    const int col0 = blockIdx.x * 128;

    int l_sw[2];
    const __nv_bfloat16 *gA[2], *gB[2];
    #pragma unroll
    for (int i = 0; i < 2; i++) {
        int ch  = tid + i * 256;
        int row = ch >> 2, cq = ch & 3;
        l_sw[i] = row * 4 + ((cq ^ (row >> 1)) & 3);
        int ra = row0 + row; if (ra > M - 1) ra = M - 1;
        int rb = col0 + row; if (rb > N - 1) rb = N - 1;
        gA[i] = A + (size_t)ra * lda + cq * 8;
        gB[i] = B + (size_t)rb * ldb + cq * 8;
    }

    const int NC = K >> 5;

    auto issue = [&](int stage, int c) {
        uint32_t base = smem_u32(&sbuf[stage][0]);
        #pragma unroll
        for (int i = 0; i < 2; i++) {
            CP16(base +        l_sw[i] * 16, gA[i] + c * 32);
            CP16(base + 8192 + l_sw[i] * 16, gB[i] + c * 32);
        }
        CP_COMMIT();
    };

    float acc[4][4][4];
    #pragma unroll
    for (int mi = 0; mi < 4; mi++)
        #pragma unroll
        for (int ni = 0; ni < 4; ni++)
            #pragma unroll
            for (int e = 0; e < 4; e++) acc[mi][ni][e] = 0.f;

    const int q = lane >> 3;
    const int r = lane & 7;

    auto compute = [&](int stage) {
        uint32_t abase = smem_u32(&sbuf[stage][0]);
        uint32_t bbase = abase + 8192;
        #pragma unroll
        for (int ks = 0; ks < 2; ks++) {
            uint32_t af[4][4];
            #pragma unroll
            for (int mi = 0; mi < 4; mi++) {
                int row = wm * 64 + mi * 16 + r + (q & 1) * 8;
                int cq  = ks * 2 + (q >> 1);
                uint32_t ad = abase + (uint32_t)(row * 4 + ((cq ^ (row >> 1)) & 3)) * 16u;
                LDMX4(af[mi][0], af[mi][1], af[mi][2], af[mi][3], ad);
            }
            uint32_t bf[4][2];
            #pragma unroll
            for (int nh = 0; nh < 2; nh++) {
                int ni  = nh * 2 + (q >> 1);
                int row = wn * 32 + ni * 8 + r;
                int cq  = ks * 2 + (q & 1);
                uint32_t bd = bbase + (uint32_t)(row * 4 + ((cq ^ (row >> 1)) & 3)) * 16u;
                LDMX4(bf[nh*2][0], bf[nh*2][1], bf[nh*2+1][0], bf[nh*2+1][1], bd);
            }
            #pragma unroll
            for (int mi = 0; mi < 4; mi++)
                #pragma unroll
                for (int ni = 0; ni < 4; ni++)
                    MMA16816(acc[mi][ni], af[mi], bf[ni]);
        }
    };

    issue(0, 0);
    if (NC > 1) issue(1, 1);
    if (NC > 2) issue(2, 2);
    for (int c = 0; c < NC; c++) {
        if (c + 2 < NC)      CP_WAIT(2);
        else if (c + 1 < NC) CP_WAIT(1);
        else                 CP_WAIT(0);
        __syncthreads();
        if (c + 3 < NC) issue((c + 3) & 3, c + 3);
        compute(c & 3);
    }

    const int g  = lane >> 2;
    const int tg = lane & 3;
    #pragma unroll
    for (int mi = 0; mi < 4; mi++) {
        int rr0 = row0 + wm * 64 + mi * 16 + g;
        int rr1 = rr0 + 8;
        #pragma unroll
        for (int ni = 0; ni < 4; ni++) {
            int cc = col0 + wn * 32 + ni * 8 + tg * 2;
            if (cc < N) {
                if (rr0 < M) {
                    if (sizeof(TOut) == 4) {
                        float2 v = make_float2(alpha * acc[mi][ni][0],
                                               alpha * acc[mi][ni][1]);
                        *(float2*)((float*)C + (size_t)rr0 * ldc + cc) = v;
                    } else {
                        __nv_bfloat162 h;
                        h.x = __float2bfloat16(alpha * acc[mi][ni][0]);
                        h.y = __float2bfloat16(alpha * acc[mi][ni][1]);
                        *(__nv_bfloat162*)((__nv_bfloat16*)C + (size_t)rr0 * ldc + cc) = h;
                    }
                }
                if (rr1 < M) {
                    if (sizeof(TOut) == 4) {
                        float2 v = make_float2(alpha * acc[mi][ni][2],
                                               alpha * acc[mi][ni][3]);
                        *(float2*)((float*)C + (size_t)rr1 * ldc + cc) = v;
                    } else {
                        __nv_bfloat162 h;
                        h.x = __float2bfloat16(alpha * acc[mi][ni][2]);
                        h.y = __float2bfloat16(alpha * acc[mi][ni][3]);
                        *(__nv_bfloat162*)((__nv_bfloat16*)C + (size_t)rr1 * ldc + cc) = h;
                    }
                }
            }
        }
    }
}

// ---------------------------------------------------------------------------
// Fused conversion: one launch covers
//   part 1: X + PE -> A-layout (hi,hi,lo) in g_Xhl  (hi prefix doubles as
//           the hi-only A for the v-projection)
//   part 2: k-weights -> B-layout (hi,lo,hi) in g_Whl; v-weights -> hi-only g_Wv
// ---------------------------------------------------------------------------
#define CONV_T1 (ROWS_X * D_MODEL)
#define CONV_T2 (NSTACK * D_MODEL)

__global__ void conv_inputs_kernel(const float* __restrict__ support,
                                   const float* __restrict__ queries,
                                   const float* __restrict__ k_w,
                                   const float* __restrict__ v_w)
{
    int e = blockIdx.x * blockDim.x + threadIdx.x;
    if (e < CONV_T1) {
        int n = e / (SEQ_LEN * D_MODEL);
        int rem = e % (SEQ_LEN * D_MODEL);
        int s = rem / D_MODEL, d = rem % D_MODEL;
        const float c = -9.210340371976184f / (float)D_MODEL;
        float div = expf((float)(2 * (d >> 1)) * c);
        float arg = (float)s * div;
        float pe = ((d & 1) ? cosf(arg) : sinf(arg)) * 0.1f;
        float x = ((n < N_SUPPORT) ? support[e]
                                   : queries[e - N_SUPPORT * SEQ_LEN * D_MODEL]) + pe;
        __nv_bfloat16 hi, lo; split2(x, hi, lo);
        int row = e / D_MODEL;
        __nv_bfloat16* o = g_Xhl + (size_t)row * KBIG;
        o[d] = hi; o[D_MODEL + d] = hi; o[2 * D_MODEL + d] = lo;
    } else if (e < CONV_T1 + CONV_T2) {
        int e2 = e - CONV_T1;
        int j = e2 / D_MODEL, k = e2 % D_MODEL;
        int part = j / OUT_DIM, o = j % OUT_DIM;
        if (part < 2) {                    // k-weights: 3-term B-layout
            float x = k_w[(size_t)o * TWO_D + part * D_MODEL + k];
            __nv_bfloat16 hi, lo; split2(x, hi, lo);
            __nv_bfloat16* dst = g_Whl + (size_t)j * KBIG;
            dst[k] = hi; dst[D_MODEL + k] = lo; dst[2 * D_MODEL + k] = hi;
        } else {                           // v-weights: hi only
            int j2 = j - NK_HALF;          // 0..2303
            float x = v_w[(size_t)o * TWO_D + (part & 1) * D_MODEL + k];
            g_Wv[(size_t)j2 * KVH + k] = __float2bfloat16(x);
        }
    }
}

// vs_s^T slices -> [WAY][OUT_DIM][KP2], pad 140..159 zero (vs_s already bf16)
__global__ void conv_vsT_kernel()
{
    int e = blockIdx.x * blockDim.x + threadIdx.x;
    const int total = WAY * OUT_DIM * KP2;
    if (e >= total) return;
    int w = e / (OUT_DIM * KP2);
    int rem = e % (OUT_DIM * KP2);
    int d = rem / KP2, j = rem % KP2;
    __nv_bfloat16 v = __float2bfloat16(0.f);
    if (j < SEG)
        v = g_vs_s[(size_t)(w * SEG + j) * OUT_DIM + d];
    g_Vhl[e] = v;
}

// ---------------------------------------------------------------------------
// assemble tuple features + LayerNorm(k) -> split bf16 layouts, v -> bf16.
// ---------------------------------------------------------------------------
__global__ __launch_bounds__(256)
void assemble_kernel(const float* __restrict__ k_b, const float* __restrict__ v_b,
                     const float* __restrict__ ln_g, const float* __restrict__ ln_b)
{
    int rl = blockIdx.x;
    int n = rl / L_TUP, l = rl % L_TUP;
    int t0 = c_t0[l], t1 = c_t1[l];
    const float* P0 = g_P + (size_t)(n * SEQ_LEN + t0) * NSTACK;
    const float* P1 = g_P + (size_t)(n * SEQ_LEN + t1) * NSTACK;

    const bool isSup = (n < N_SUPPORT);
    __nv_bfloat16* kd;
    __nv_bfloat16* vsd;
    if (isSup) {
        kd  = g_KShl + (size_t)(n * L_TUP + l) * KSC;
        vsd = g_vs_s + (size_t)(n * L_TUP + l) * OUT_DIM;
    } else {
        int m = n - N_SUPPORT;
        kd  = g_KQhl + (size_t)(m * L_TUP + l) * KSC;
        vsd = g_vs_q + (size_t)(m * L_TUP + l) * OUT_DIM;
    }

    __shared__ float kbuf[OUT_DIM];
    float s = 0.f, s2 = 0.f;
    for (int o = threadIdx.x; o < OUT_DIM; o += blockDim.x) {
        float kv = P0[o] + P1[OUT_DIM + o] + k_b[o];
        kbuf[o] = kv; s += kv; s2 += kv * kv;
        vsd[o] = __float2bfloat16(P0[2 * OUT_DIM + o] + P1[3 * OUT_DIM + o] + v_b[o]);
    }
    int lane = threadIdx.x & 31, wid = threadIdx.x >> 5;
    #pragma unroll
    for (int off = 16; off; off >>= 1) {
        s  += __shfl_xor_sync(0xffffffffu, s,  off);
        s2 += __shfl_xor_sync(0xffffffffu, s2, off);
    }
    __shared__ float ws[8], ws2[8], sm_mean, sm_rstd;
    if (lane == 0) { ws[wid] = s; ws2[wid] = s2; }
    __syncthreads();
    if (threadIdx.x == 0) {
        float S = 0.f, S2 = 0.f;
        #pragma unroll
        for (int w = 0; w < 8; w++) { S += ws[w]; S2 += ws2[w]; }
        float mean = S / (float)OUT_DIM;
        float var  = S2 / (float)OUT_DIM - mean * mean;
        sm_mean = mean; sm_rstd = rsqrtf(var + 1e-5f);
    }
    __syncthreads();
    float mean = sm_mean, rstd = sm_rstd;
    for (int o = threadIdx.x; o < OUT_DIM; o += blockDim.x) {
        float y = (kbuf[o] - mean) * rstd * ln_g[o] + ln_b[o];
        __nv_bfloat16 hi, lo; split2(y, hi, lo);
        kd[o] = hi;
        kd[OUT_DIM + o]     = isSup ? lo : hi;
        kd[2 * OUT_DIM + o] = isSup ? hi : lo;
    }
}

// ---------------------------------------------------------------------------
// per-row blockwise softmax; writes hi-only attn (K=160) directly to g_Ahl.
// ---------------------------------------------------------------------------
__global__ __launch_bounds__(160)
void softmax_kernel()
{
    int row = blockIdx.x;
    int warp = threadIdx.x >> 5, lane = threadIdx.x & 31;
    const float* p = g_S + (size_t)row * ROWS_S + warp * SEG;
    float v[5]; float mx = -INFINITY;
    #pragma unroll
    for (int i = 0; i < 5; i++) {
        int c = lane + 32 * i;
        v[i] = (c < SEG) ? p[c] : -INFINITY;
        mx = fmaxf(mx, v[i]);
    }
    #pragma unroll
    for (int off = 16; off; off >>= 1)
        mx = fmaxf(mx, __shfl_xor_sync(0xffffffffu, mx, off));
    float sm = 0.f;
    #pragma unroll
    for (int i = 0; i < 5; i++) {
        int c = lane + 32 * i;
        v[i] = (c < SEG) ? expf(v[i] - mx) : 0.f;
        sm += v[i];
    }
    #pragma unroll
    for (int off = 16; off; off >>= 1)
        sm += __shfl_xor_sync(0xffffffffu, sm, off);
    float inv = 1.f / sm;

    __nv_bfloat16* a = g_Ahl + ((size_t)warp * ROWS_Q + row) * KP2;
    #pragma unroll
    for (int i = 0; i < 5; i++) {
        int c = lane + 32 * i;
        if (c < SEG)
            a[c] = __float2bfloat16(v[i] * inv);
    }
    if (lane < KP2 - SEG)              // zero pad 140..159
        a[SEG + lane] = __float2bfloat16(0.f);
}

// ---------------------------------------------------------------------------
// per-query Gram matrix + distances -> sim, ori  (bf16 inputs, uint4 loads)
// ---------------------------------------------------------------------------
__global__ __launch_bounds__(256)
void finalize_kernel(float* __restrict__ out)
{
    int q = blockIdx.x;
    const uint4* v8 = (const uint4*)(g_vs_q + (size_t)q * PLANE);
    const uint4* pp8[WAY];
    #pragma unroll
    for (int w = 0; w < WAY; w++)
        pp8[w] = (const uint4*)(g_proto + (size_t)w * ROWS_Q * OUT_DIM
                                + (size_t)q * PLANE);

    float acc[21];
    #pragma unroll
    for (int i = 0; i < 21; i++) acc[i] = 0.f;

    const int NV8 = PLANE / 8;                 // 4032
    for (int i = threadIdx.x; i < NV8; i += blockDim.x) {
        uint4 uv = v8[i];
        uint4 u0 = pp8[0][i], u1 = pp8[1][i], u2 = pp8[2][i],
              u3 = pp8[3][i], u4 = pp8[4][i];
        float fv[8], f0[8], f1[8], f2[8], f3[8], f4[8];
        #pragma unroll
        for (int h = 0; h < 4; h++) {
            float2 t;
            t = __bfloat1622float2(*(__nv_bfloat162*)((uint32_t*)&uv + h));
            fv[2*h] = t.x; fv[2*h+1] = t.y;
            t = __bfloat1622float2(*(__nv_bfloat162*)((uint32_t*)&u0 + h));
            f0[2*h] = t.x; f0[2*h+1] = t.y;
            t = __bfloat1622float2(*(__nv_bfloat162*)((uint32_t*)&u1 + h));
            f1[2*h] = t.x; f1[2*h+1] = t.y;
            t = __bfloat1622float2(*(__nv_bfloat162*)((uint32_t*)&u2 + h));
            f2[2*h] = t.x; f2[2*h+1] = t.y;
            t = __bfloat1622float2(*(__nv_bfloat162*)((uint32_t*)&u3 + h));
            f3[2*h] = t.x; f3[2*h+1] = t.y;
            t = __bfloat1622float2(*(__nv_bfloat162*)((uint32_t*)&u4 + h));
            f4[2*h] = t.x; f4[2*h+1] = t.y;
        }
        #pragma unroll
        for (int e = 0; e < 8; e++) {
            float vvv = fv[e];
            float a0 = f0[e], a1 = f1[e], a2 = f2[e], a3 = f3[e], a4 = f4[e];
            acc[0]  += a0 * a0;  acc[1]  += a0 * a1;  acc[2]  += a0 * a2;
            acc[3]  += a0 * a3;  acc[4]  += a0 * a4;
            acc[5]  += a1 * a1;  acc[6]  += a1 * a2;  acc[7]  += a1 * a3;
            acc[8]  += a1 * a4;
            acc[9]  += a2 * a2;  acc[10] += a2 * a3;  acc[11] += a2 * a4;
            acc[12] += a3 * a3;  acc[13] += a3 * a4;
            acc[14] += a4 * a4;
            acc[15] += vvv * a0; acc[16] += vvv * a1; acc[17] += vvv * a2;
            acc[18] += vvv * a3; acc[19] += vvv * a4;
            acc[20] += vvv * vvv;
        }
    }

    int lane = threadIdx.x & 31, wid = threadIdx.x >> 5;
    __shared__ float part[21][8];
    #pragma unroll
    for (int i = 0; i < 21; i++) {
        float a = acc[i];
        #pragma unroll
        for (int off = 16; off; off >>= 1)
            a += __shfl_xor_sync(0xffffffffu, a, off);
        if (lane == 0) part[i][wid] = a;
    }
    __syncthreads();
    __shared__ float tot[21];
    if (threadIdx.x < 21) {
        float sSum = 0.f;
        #pragma unroll
        for (int w = 0; w < 8; w++) sSum += part[threadIdx.x][w];
        tot[threadIdx.x] = sSum;
    }
    __syncthreads();
    if (threadIdx.x == 0) {
        float G[WAY][WAY];
        int t = 0;
        for (int a = 0; a < WAY; a++)
            for (int b = a; b < WAY; b++) { G[a][b] = tot[t]; G[b][a] = tot[t]; t++; }
        float D[WAY];
        for (int w = 0; w < WAY; w++) D[w] = tot[15 + w];
        float VV = tot[20];
        float nrm[WAY];
        for (int w = 0; w < WAY; w++) nrm[w] = sqrtf(G[w][w]);
        for (int a = 0; a < WAY; a++)
            for (int b = 0; b < WAY; b++)
                out[q * WAY * WAY + a * WAY + b] =
                    G[a][b] / fmaxf(nrm[a] * nrm[b], 1e-8f);
        for (int w = 0; w < WAY; w++)
            out[N_QUERIES * WAY * WAY + q * WAY + w] =
                -(VV - 2.f * D[w] + G[w][w]) / (float)L_TUP;
    }
}

// ---------------------------------------------------------------------------
// Launch
// ---------------------------------------------------------------------------
extern "C" void kernel_launch(void* const* d_in, const int* in_sizes, int n_in,
                              void* d_out, int out_size)
{
    const float* support = (const float*)d_in[0];
    const float* queries = (const float*)d_in[2];
    const float* k_w  = (const float*)d_in[3];
    const float* k_b  = (const float*)d_in[4];
    const float* v_w  = (const float*)d_in[5];
    const float* v_b  = (const float*)d_in[6];
    const float* ln_g = (const float*)d_in[7];
    const float* ln_b = (const float*)d_in[8];
    float* out = (float*)d_out;

    float *P, *S;
    __nv_bfloat16 *Xhl, *Whl, *Wv, *KQhl, *KShl, *Ahl, *Vhl, *proto;
    cudaGetSymbolAddress((void**)&Xhl,   g_Xhl);
    cudaGetSymbolAddress((void**)&Whl,   g_Whl);
    cudaGetSymbolAddress((void**)&Wv,    g_Wv);
    cudaGetSymbolAddress((void**)&P,     g_P);
    cudaGetSymbolAddress((void**)&KQhl,  g_KQhl);
    cudaGetSymbolAddress((void**)&KShl,  g_KShl);
    cudaGetSymbolAddress((void**)&S,     g_S);
    cudaGetSymbolAddress((void**)&Ahl,   g_Ahl);
    cudaGetSymbolAddress((void**)&Vhl,   g_Vhl);
    cudaGetSymbolAddress((void**)&proto, g_proto);

    // 1. fused PE + hi/lo input conversion + weight conversion (one launch)
    {
        int total = CONV_T1 + CONV_T2;
        conv_inputs_kernel<<<(total + 255) / 256, 256>>>(support, queries, k_w, v_w);
    }
    // 2a. P[:, 0:2304] = X @ Wk^T  (3-term split, K=6144)
    {
        dim3 grid(NK_HALF / 128, (ROWS_X + 127) / 128, 1);
        gemm_mma<float><<<grid, 256>>>(Xhl, Whl, P, ROWS_X, NK_HALF, KBIG, 1.0f,
                                       KBIG, KBIG, NSTACK, 0, 0, 0);
    }
    // 2b. P[:, 2304:4608] = Xhi @ Wv^T  (hi-only, K=2048)
    {
        dim3 grid(NK_HALF / 128, (ROWS_X + 127) / 128, 1);
        gemm_mma<float><<<grid, 256>>>(Xhl, Wv, P + NK_HALF,
                                       ROWS_X, NK_HALF, KVH, 1.0f,
                                       KBIG, KVH, NSTACK, 0, 0, 0);
    }
    // 3. assemble -> KQhl/KShl (split bf16) + vs bf16
    assemble_kernel<<<N_TOTAL * L_TUP, 256>>>(k_b, v_b, ln_g, ln_b);
    // 4. scores = ks_q @ ks_s^T / sqrt(OUT_DIM)  [5600, 700], K=3456
    {
        dim3 grid((ROWS_S + 127) / 128, (ROWS_Q + 127) / 128, 1);
        gemm_mma<float><<<grid, 256>>>(KQhl, KShl, S, ROWS_Q, ROWS_S, KSC,
                                       1.0f / sqrtf((float)OUT_DIM),
                                       KSC, KSC, ROWS_S, 0, 0, 0);
    }
    // 5. softmax -> g_Ahl (hi-only) directly
    softmax_kernel<<<ROWS_Q, 160>>>();
    // 6. vs_s^T for proto GEMM
    conv_vsT_kernel<<<(WAY * OUT_DIM * KP2 + 255) / 256, 256>>>();
    // 7. proto[w] = attn_w @ vs_w  [5600, 1152], K=160 — batched, bf16 out
    {
        dim3 grid(OUT_DIM / 128, (ROWS_Q + 127) / 128, WAY);
        gemm_mma<__nv_bfloat16><<<grid, 256>>>(Ahl, Vhl, proto,
                                               ROWS_Q, OUT_DIM, KP2, 1.0f,
                                               KP2, KP2, OUT_DIM,
                                               (size_t)ROWS_Q * KP2,
                                               (size_t)OUT_DIM * KP2,
                                               (size_t)ROWS_Q * OUT_DIM);
    }
    // 8. finalize
    finalize_kernel<<<N_QUERIES, 256>>>(out);
}

// round 15
// speedup vs baseline: 1.8723x; 1.0841x over previous
#include <cuda_runtime.h>
#include <cuda_bf16.h>
#include <math.h>
#include <stdint.h>

// ---------------------------------------------------------------------------
// Problem constants
// ---------------------------------------------------------------------------
#define SEQ_LEN   8
#define D_MODEL   2048
#define OUT_DIM   1152
#define WAY       5
#define SHOT      5
#define N_SUPPORT 25
#define N_QUERIES 200
#define N_TOTAL   225
#define L_TUP     28
#define TWO_D     4096
#define NSTACK    4608          // 4 * OUT_DIM (k h0, k h1, v h0, v h1)
#define NK_HALF   2304          // 2 * OUT_DIM (k columns / v columns)
#define ROWS_X    1800          // N_TOTAL * SEQ_LEN
#define ROWS_Q    5600          // N_QUERIES * L_TUP
#define ROWS_S    700           // N_SUPPORT * L_TUP
#define SEG       140           // SHOT * L_TUP
#define PLANE     32256         // L_TUP * OUT_DIM

// K sizes
#define KBIG      6144          // k-projection: 3-term (hi,hi,lo)x(hi,lo,hi)
#define KVH       2048          // v-projection: hi-only
#define KSC       2304          // scores: 2-term  A=[hi|lo], B=[hi|hi]
#define KP2       160           // proto: hi-only, 140 padded to 160

__constant__ int c_t0[L_TUP] = {0,0,0,0,0,0,0,1,1,1,1,1,1,2,2,2,2,2,3,3,3,3,4,4,4,5,5,6};
__constant__ int c_t1[L_TUP] = {1,2,3,4,5,6,7,2,3,4,5,6,7,3,4,5,6,7,4,5,6,7,5,6,7,6,7,7};

// ---------------------------------------------------------------------------
// Scratch (device globals; no allocation allowed)
// ---------------------------------------------------------------------------
__device__ __nv_bfloat16  g_Xhl[(size_t)ROWS_X * KBIG];     // (hi,hi,lo); hi prefix = v-proj A
__device__ __nv_bfloat16  g_Whl[(size_t)NK_HALF * KBIG];    // k-weights (hi,lo,hi)
__device__ __nv_bfloat16  g_Wv[(size_t)NK_HALF * KVH];      // v-weights hi only
__device__ float          g_P[(size_t)ROWS_X * NSTACK];
__device__ __nv_bfloat16  g_vs_s[ROWS_S * OUT_DIM];         // bf16
__device__ __nv_bfloat16  g_vs_q[ROWS_Q * OUT_DIM];         // bf16
__device__ __nv_bfloat16  g_KQhl[(size_t)ROWS_Q * KSC];     // queries: [hi | lo]
__device__ __nv_bfloat16  g_KShl[(size_t)ROWS_S * KSC];     // support: [hi | hi]
__device__ float          g_S[(size_t)ROWS_Q * ROWS_S];     // scores
__device__ __nv_bfloat16  g_Ahl[(size_t)WAY * ROWS_Q * KP2];   // attn hi
__device__ __nv_bfloat16  g_Vhl[(size_t)WAY * OUT_DIM * KP2];  // vs_s^T hi slices
__device__ __nv_bfloat16  g_proto[(size_t)WAY * ROWS_Q * OUT_DIM];  // bf16

// ---------------------------------------------------------------------------
// Helpers
// ---------------------------------------------------------------------------
__device__ __forceinline__ uint32_t smem_u32(const void* p) {
    uint32_t a;
    asm("{ .reg .u64 t; cvta.to.shared.u64 t, %1; cvt.u32.u64 %0, t; }"
        : "=r"(a) : "l"(p));
    return a;
}

#define CP16(dst, src) \
    asm volatile("cp.async.cg.shared.global [%0], [%1], 16;" :: "r"(dst), "l"(src))
#define CP_COMMIT() asm volatile("cp.async.commit_group;" ::: "memory")
#define CP_WAIT(n)  asm volatile("cp.async.wait_group %0;" :: "n"(n) : "memory")

__device__ __forceinline__ void split2(float x, __nv_bfloat16& hi, __nv_bfloat16& lo) {
    hi = __float2bfloat16(x);
    lo = __float2bfloat16(x - __bfloat162float(hi));
}

#define LDMX4(d0,d1,d2,d3,addr) \
    asm volatile("ldmatrix.sync.aligned.m8n8.x4.shared.b16 {%0,%1,%2,%3}, [%4];" \
        : "=r"(d0), "=r"(d1), "=r"(d2), "=r"(d3) : "r"(addr))

#define MMA16816(acc, a, b) \
    asm volatile("mma.sync.aligned.m16n8k16.row.col.f32.bf16.bf16.f32 " \
        "{%0,%1,%2,%3}, {%4,%5,%6,%7}, {%8,%9}, {%0,%1,%2,%3};" \
        : "+f"((acc)[0]), "+f"((acc)[1]), "+f"((acc)[2]), "+f"((acc)[3]) \
        : "r"((a)[0]), "r"((a)[1]), "r"((a)[2]), "r"((a)[3]), \
          "r"((b)[0]), "r"((b)[1]))

// ---------------------------------------------------------------------------
// Shared GEMM body (R5-proven): 128x128 CTA tile, BK=32, 4-stage cp.async,
// single barrier per chunk, 8 warps (2x4), warp tile 64x32. K mult of 32.
// OOB rows clamped (their outputs never stored).
// ---------------------------------------------------------------------------
#define GEMM_BODY(A_, B_, C_, M_, N_, K_, alpha_, lda_, ldb_, ldc_, STORE_BF16) \
{                                                                               \
    __shared__ uint4 sbuf[4][1024];                                             \
    const int tid  = threadIdx.x;                                               \
    const int lane = tid & 31;                                                  \
    const int wid  = tid >> 5;                                                  \
    const int wm   = wid >> 2;                                                  \
    const int wn   = wid & 3;                                                   \
    const int row0 = blockIdx.y * 128;                                          \
    const int col0 = blockIdx.x * 128;                                          \
    int l_sw[2];                                                                \
    const __nv_bfloat16 *gA[2], *gB[2];                                         \
    _Pragma("unroll")                                                           \
    for (int i = 0; i < 2; i++) {                                               \
        int ch  = tid + i * 256;                                                \
        int row = ch >> 2, cq = ch & 3;                                         \
        l_sw[i] = row * 4 + ((cq ^ (row >> 1)) & 3);                            \
        int ra = row0 + row; if (ra > (M_) - 1) ra = (M_) - 1;                  \
        int rb = col0 + row; if (rb > (N_) - 1) rb = (N_) - 1;                  \
        gA[i] = (A_) + (size_t)ra * (lda_) + cq * 8;                            \
        gB[i] = (B_) + (size_t)rb * (ldb_) + cq * 8;                            \
    }                                                                           \
    const int NC = (K_) >> 5;                                                   \
    auto issue = [&](int stage, int c) {                                        \
        uint32_t base = smem_u32(&sbuf[stage][0]);                              \
        _Pragma("unroll")                                                       \
        for (int i = 0; i < 2; i++) {                                           \
            CP16(base +        l_sw[i] * 16, gA[i] + c * 32);                   \
            CP16(base + 8192 + l_sw[i] * 16, gB[i] + c * 32);                   \
        }                                                                       \
        CP_COMMIT();                                                            \
    };                                                                          \
    float acc[4][4][4];                                                         \
    _Pragma("unroll")                                                           \
    for (int mi = 0; mi < 4; mi++)                                              \
        _Pragma("unroll")                                                       \
        for (int ni = 0; ni < 4; ni++)                                          \
            _Pragma("unroll")                                                   \
            for (int e = 0; e < 4; e++) acc[mi][ni][e] = 0.f;                   \
    const int q = lane >> 3;                                                    \
    const int r = lane & 7;                                                     \
    auto compute = [&](int stage) {                                             \
        uint32_t abase = smem_u32(&sbuf[stage][0]);                             \
        uint32_t bbase = abase + 8192;                                          \
        _Pragma("unroll")                                                       \
        for (int ks = 0; ks < 2; ks++) {                                        \
            uint32_t af[4][4];                                                  \
            _Pragma("unroll")                                                   \
            for (int mi = 0; mi < 4; mi++) {                                    \
                int row = wm * 64 + mi * 16 + r + (q & 1) * 8;                  \
                int cq  = ks * 2 + (q >> 1);                                    \
                uint32_t ad = abase + (uint32_t)(row * 4 + ((cq ^ (row >> 1)) & 3)) * 16u; \
                LDMX4(af[mi][0], af[mi][1], af[mi][2], af[mi][3], ad);          \
            }                                                                   \
            uint32_t bf[4][2];                                                  \
            _Pragma("unroll")                                                   \
            for (int nh = 0; nh < 2; nh++) {                                    \
                int ni  = nh * 2 + (q >> 1);                                    \
                int row = wn * 32 + ni * 8 + r;                                 \
                int cq  = ks * 2 + (q & 1);                                     \
                uint32_t bd = bbase + (uint32_t)(row * 4 + ((cq ^ (row >> 1)) & 3)) * 16u; \
                LDMX4(bf[nh*2][0], bf[nh*2][1], bf[nh*2+1][0], bf[nh*2+1][1], bd); \
            }                                                                   \
            _Pragma("unroll")                                                   \
            for (int mi = 0; mi < 4; mi++)                                      \
                _Pragma("unroll")                                               \
                for (int ni = 0; ni < 4; ni++)                                  \
                    MMA16816(acc[mi][ni], af[mi], bf[ni]);                      \
        }                                                                       \
    };                                                                          \
    issue(0, 0);                                                                \
    if (NC > 1) issue(1, 1);                                                    \
    if (NC > 2) issue(2, 2);                                                    \
    for (int c = 0; c < NC; c++) {                                              \
        if (c + 2 < NC)      CP_WAIT(2);                                        \
        else if (c + 1 < NC) CP_WAIT(1);                                        \
        else                 CP_WAIT(0);                                        \
        __syncthreads();                                                        \
        if (c + 3 < NC) issue((c + 3) & 3, c + 3);                              \
        compute(c & 3);                                                         \
    }                                                                           \
    const int g  = lane >> 2;                                                   \
    const int tg = lane & 3;                                                    \
    _Pragma("unroll")                                                           \
    for (int mi = 0; mi < 4; mi++) {                                            \
        int rr0 = row0 + wm * 64 + mi * 16 + g;                                 \
        int rr1 = rr0 + 8;                                                      \
        _Pragma("unroll")                                                       \
        for (int ni = 0; ni < 4; ni++) {                                        \
            int cc = col0 + wn * 32 + ni * 8 + tg * 2;                          \
            if (cc < (N_)) {                                                    \
                if (rr0 < (M_)) {                                               \
                    if (!(STORE_BF16)) {                                        \
                        float2 v = make_float2((alpha_) * acc[mi][ni][0],       \
                                               (alpha_) * acc[mi][ni][1]);      \
                        *(float2*)((float*)(C_) + (size_t)rr0 * (ldc_) + cc) = v; \
                    } else {                                                    \
                        __nv_bfloat162 h;                                       \
                        h.x = __float2bfloat16((alpha_) * acc[mi][ni][0]);      \
                        h.y = __float2bfloat16((alpha_) * acc[mi][ni][1]);      \
                        *(__nv_bfloat162*)((__nv_bfloat16*)(C_) + (size_t)rr0 * (ldc_) + cc) = h; \
                    }                                                           \
                }                                                               \
                if (rr1 < (M_)) {                                               \
                    if (!(STORE_BF16)) {                                        \
                        float2 v = make_float2((alpha_) * acc[mi][ni][2],       \
                                               (alpha_) * acc[mi][ni][3]);      \
                        *(float2*)((float*)(C_) + (size_t)rr1 * (ldc_) + cc) = v; \
                    } else {                                                    \
                        __nv_bfloat162 h;                                       \
                        h.x = __float2bfloat16((alpha_) * acc[mi][ni][2]);      \
                        h.y = __float2bfloat16((alpha_) * acc[mi][ni][3]);      \
                        *(__nv_bfloat162*)((__nv_bfloat16*)(C_) + (size_t)rr1 * (ldc_) + cc) = h; \
                    }                                                           \
                }                                                               \
            }                                                                   \
        }                                                                       \
    }                                                                           \
}

// ---------------------------------------------------------------------------
// Fused projection GEMM: z=0 -> k-part (B=Whl, K=6144), z=1 -> v-part
// (B=Wv, K=2048, C offset +NK_HALF). Same A (Xhl, lda=KBIG), same grid x/y.
// ---------------------------------------------------------------------------
__global__ __launch_bounds__(256, 2)
void gemm_proj(const __nv_bfloat16* __restrict__ A,
               const __nv_bfloat16* __restrict__ Bk,
               const __nv_bfloat16* __restrict__ Bv,
               float* __restrict__ C)
{
    const __nv_bfloat16* B;
    int K, ldb;
    float* Cp;
    if (blockIdx.z == 0) { B = Bk; K = KBIG; ldb = KBIG; Cp = C; }
    else                 { B = Bv; K = KVH;  ldb = KVH;  Cp = C + NK_HALF; }
    GEMM_BODY(A, B, Cp, ROWS_X, NK_HALF, K, 1.0f, KBIG, ldb, NSTACK, 0)
}

// ---------------------------------------------------------------------------
// Generic GEMM (fp32 out): scores
// ---------------------------------------------------------------------------
__global__ __launch_bounds__(256, 2)
void gemm_f32(const __nv_bfloat16* __restrict__ A, const __nv_bfloat16* __restrict__ B,
              float* __restrict__ C, int M, int N, int K, float alpha,
              int lda, int ldb, int ldc)
{
    GEMM_BODY(A, B, C, M, N, K, alpha, lda, ldb, ldc, 0)
}

// ---------------------------------------------------------------------------
// Generic GEMM (bf16 out, z-batched): proto
// ---------------------------------------------------------------------------
__global__ __launch_bounds__(256, 2)
void gemm_bf16(const __nv_bfloat16* __restrict__ A, const __nv_bfloat16* __restrict__ B,
               __nv_bfloat16* __restrict__ C, int M, int N, int K, float alpha,
               int lda, int ldb, int ldc,
               size_t aStride, size_t bStride, size_t cStride)
{
    A += (size_t)blockIdx.z * aStride;
    B += (size_t)blockIdx.z * bStride;
    C += (size_t)blockIdx.z * cStride;
    GEMM_BODY(A, B, C, M, N, K, alpha, lda, ldb, ldc, 1)
}

// ---------------------------------------------------------------------------
// Fused conversion: X+PE -> (hi,hi,lo); k-weights -> (hi,lo,hi); v -> hi-only
// ---------------------------------------------------------------------------
#define CONV_T1 (ROWS_X * D_MODEL)
#define CONV_T2 (NSTACK * D_MODEL)

__global__ void conv_inputs_kernel(const float* __restrict__ support,
                                   const float* __restrict__ queries,
                                   const float* __restrict__ k_w,
                                   const float* __restrict__ v_w)
{
    int e = blockIdx.x * blockDim.x + threadIdx.x;
    if (e < CONV_T1) {
        int n = e / (SEQ_LEN * D_MODEL);
        int rem = e % (SEQ_LEN * D_MODEL);
        int s = rem / D_MODEL, d = rem % D_MODEL;
        const float c = -9.210340371976184f / (float)D_MODEL;
        float div = expf((float)(2 * (d >> 1)) * c);
        float arg = (float)s * div;
        float pe = ((d & 1) ? cosf(arg) : sinf(arg)) * 0.1f;
        float x = ((n < N_SUPPORT) ? support[e]
                                   : queries[e - N_SUPPORT * SEQ_LEN * D_MODEL]) + pe;
        __nv_bfloat16 hi, lo; split2(x, hi, lo);
        int row = e / D_MODEL;
        __nv_bfloat16* o = g_Xhl + (size_t)row * KBIG;
        o[d] = hi; o[D_MODEL + d] = hi; o[2 * D_MODEL + d] = lo;
    } else if (e < CONV_T1 + CONV_T2) {
        int e2 = e - CONV_T1;
        int j = e2 / D_MODEL, k = e2 % D_MODEL;
        int part = j / OUT_DIM, o = j % OUT_DIM;
        if (part < 2) {                    // k-weights: 3-term B-layout
            float x = k_w[(size_t)o * TWO_D + part * D_MODEL + k];
            __nv_bfloat16 hi, lo; split2(x, hi, lo);
            __nv_bfloat16* dst = g_Whl + (size_t)j * KBIG;
            dst[k] = hi; dst[D_MODEL + k] = lo; dst[2 * D_MODEL + k] = hi;
        } else {                           // v-weights: hi only
            int j2 = j - NK_HALF;
            float x = v_w[(size_t)o * TWO_D + (part & 1) * D_MODEL + k];
            g_Wv[(size_t)j2 * KVH + k] = __float2bfloat16(x);
        }
    }
}

// vs_s^T slices -> [WAY][OUT_DIM][KP2], pad 140..159 zero
__global__ void conv_vsT_kernel()
{
    int e = blockIdx.x * blockDim.x + threadIdx.x;
    const int total = WAY * OUT_DIM * KP2;
    if (e >= total) return;
    int w = e / (OUT_DIM * KP2);
    int rem = e % (OUT_DIM * KP2);
    int d = rem / KP2, j = rem % KP2;
    __nv_bfloat16 v = __float2bfloat16(0.f);
    if (j < SEG)
        v = g_vs_s[(size_t)(w * SEG + j) * OUT_DIM + d];
    g_Vhl[e] = v;
}

// ---------------------------------------------------------------------------
// assemble tuple features + LayerNorm(k) -> 2-term bf16 layouts, v -> bf16.
// queries: kd = [hi | lo];  support: kd = [hi | hi]
// ---------------------------------------------------------------------------
__global__ __launch_bounds__(256)
void assemble_kernel(const float* __restrict__ k_b, const float* __restrict__ v_b,
                     const float* __restrict__ ln_g, const float* __restrict__ ln_b)
{
    int rl = blockIdx.x;
    int n = rl / L_TUP, l = rl % L_TUP;
    int t0 = c_t0[l], t1 = c_t1[l];
    const float* P0 = g_P + (size_t)(n * SEQ_LEN + t0) * NSTACK;
    const float* P1 = g_P + (size_t)(n * SEQ_LEN + t1) * NSTACK;

    const bool isSup = (n < N_SUPPORT);
    __nv_bfloat16* kd;
    __nv_bfloat16* vsd;
    if (isSup) {
        kd  = g_KShl + (size_t)(n * L_TUP + l) * KSC;
        vsd = g_vs_s + (size_t)(n * L_TUP + l) * OUT_DIM;
    } else {
        int m = n - N_SUPPORT;
        kd  = g_KQhl + (size_t)(m * L_TUP + l) * KSC;
        vsd = g_vs_q + (size_t)(m * L_TUP + l) * OUT_DIM;
    }

    __shared__ float kbuf[OUT_DIM];
    float s = 0.f, s2 = 0.f;
    for (int o = threadIdx.x; o < OUT_DIM; o += blockDim.x) {
        float kv = P0[o] + P1[OUT_DIM + o] + k_b[o];
        kbuf[o] = kv; s += kv; s2 += kv * kv;
        vsd[o] = __float2bfloat16(P0[2 * OUT_DIM + o] + P1[3 * OUT_DIM + o] + v_b[o]);
    }
    int lane = threadIdx.x & 31, wid = threadIdx.x >> 5;
    #pragma unroll
    for (int off = 16; off; off >>= 1) {
        s  += __shfl_xor_sync(0xffffffffu, s,  off);
        s2 += __shfl_xor_sync(0xffffffffu, s2, off);
    }
    __shared__ float ws[8], ws2[8], sm_mean, sm_rstd;
    if (lane == 0) { ws[wid] = s; ws2[wid] = s2; }
    __syncthreads();
    if (threadIdx.x == 0) {
        float S = 0.f, S2 = 0.f;
        #pragma unroll
        for (int w = 0; w < 8; w++) { S += ws[w]; S2 += ws2[w]; }
        float mean = S / (float)OUT_DIM;
        float var  = S2 / (float)OUT_DIM - mean * mean;
        sm_mean = mean; sm_rstd = rsqrtf(var + 1e-5f);
    }
    __syncthreads();
    float mean = sm_mean, rstd = sm_rstd;
    for (int o = threadIdx.x; o < OUT_DIM; o += blockDim.x) {
        float y = (kbuf[o] - mean) * rstd * ln_g[o] + ln_b[o];
        __nv_bfloat16 hi, lo; split2(y, hi, lo);
        kd[o] = hi;
        kd[OUT_DIM + o] = isSup ? hi : lo;
    }
}

// ---------------------------------------------------------------------------
// per-row blockwise softmax; writes hi-only attn (K=160) directly to g_Ahl.
// ---------------------------------------------------------------------------
__global__ __launch_bounds__(160)
void softmax_kernel()
{
    int row = blockIdx.x;
    int warp = threadIdx.x >> 5, lane = threadIdx.x & 31;
    const float* p = g_S + (size_t)row * ROWS_S + warp * SEG;
    float v[5]; float mx = -INFINITY;
    #pragma unroll
    for (int i = 0; i < 5; i++) {
        int c = lane + 32 * i;
        v[i] = (c < SEG) ? p[c] : -INFINITY;
        mx = fmaxf(mx, v[i]);
    }
    #pragma unroll
    for (int off = 16; off; off >>= 1)
        mx = fmaxf(mx, __shfl_xor_sync(0xffffffffu, mx, off));
    float sm = 0.f;
    #pragma unroll
    for (int i = 0; i < 5; i++) {
        int c = lane + 32 * i;
        v[i] = (c < SEG) ? expf(v[i] - mx) : 0.f;
        sm += v[i];
    }
    #pragma unroll
    for (int off = 16; off; off >>= 1)
        sm += __shfl_xor_sync(0xffffffffu, sm, off);
    float inv = 1.f / sm;

    __nv_bfloat16* a = g_Ahl + ((size_t)warp * ROWS_Q + row) * KP2;
    #pragma unroll
    for (int i = 0; i < 5; i++) {
        int c = lane + 32 * i;
        if (c < SEG)
            a[c] = __float2bfloat16(v[i] * inv);
    }
    if (lane < KP2 - SEG)
        a[SEG + lane] = __float2bfloat16(0.f);
}

// ---------------------------------------------------------------------------
// per-query Gram matrix + distances -> sim, ori  (bf16 inputs, uint4 loads)
// ---------------------------------------------------------------------------
__global__ __launch_bounds__(256)
void finalize_kernel(float* __restrict__ out)
{
    int q = blockIdx.x;
    const uint4* v8 = (const uint4*)(g_vs_q + (size_t)q * PLANE);
    const uint4* pp8[WAY];
    #pragma unroll
    for (int w = 0; w < WAY; w++)
        pp8[w] = (const uint4*)(g_proto + (size_t)w * ROWS_Q * OUT_DIM
                                + (size_t)q * PLANE);

    float acc[21];
    #pragma unroll
    for (int i = 0; i < 21; i++) acc[i] = 0.f;

    const int NV8 = PLANE / 8;                 // 4032
    for (int i = threadIdx.x; i < NV8; i += blockDim.x) {
        uint4 uv = v8[i];
        uint4 u0 = pp8[0][i], u1 = pp8[1][i], u2 = pp8[2][i],
              u3 = pp8[3][i], u4 = pp8[4][i];
        float fv[8], f0[8], f1[8], f2[8], f3[8], f4[8];
        #pragma unroll
        for (int h = 0; h < 4; h++) {
            float2 t;
            t = __bfloat1622float2(*(__nv_bfloat162*)((uint32_t*)&uv + h));
            fv[2*h] = t.x; fv[2*h+1] = t.y;
            t = __bfloat1622float2(*(__nv_bfloat162*)((uint32_t*)&u0 + h));
            f0[2*h] = t.x; f0[2*h+1] = t.y;
            t = __bfloat1622float2(*(__nv_bfloat162*)((uint32_t*)&u1 + h));
            f1[2*h] = t.x; f1[2*h+1] = t.y;
            t = __bfloat1622float2(*(__nv_bfloat162*)((uint32_t*)&u2 + h));
            f2[2*h] = t.x; f2[2*h+1] = t.y;
            t = __bfloat1622float2(*(__nv_bfloat162*)((uint32_t*)&u3 + h));
            f3[2*h] = t.x; f3[2*h+1] = t.y;
            t = __bfloat1622float2(*(__nv_bfloat162*)((uint32_t*)&u4 + h));
            f4[2*h] = t.x; f4[2*h+1] = t.y;
        }
        #pragma unroll
        for (int e = 0; e < 8; e++) {
            float vvv = fv[e];
            float a0 = f0[e], a1 = f1[e], a2 = f2[e], a3 = f3[e], a4 = f4[e];
            acc[0]  += a0 * a0;  acc[1]  += a0 * a1;  acc[2]  += a0 * a2;
            acc[3]  += a0 * a3;  acc[4]  += a0 * a4;
            acc[5]  += a1 * a1;  acc[6]  += a1 * a2;  acc[7]  += a1 * a3;
            acc[8]  += a1 * a4;
            acc[9]  += a2 * a2;  acc[10] += a2 * a3;  acc[11] += a2 * a4;
            acc[12] += a3 * a3;  acc[13] += a3 * a4;
            acc[14] += a4 * a4;
            acc[15] += vvv * a0; acc[16] += vvv * a1; acc[17] += vvv * a2;
            acc[18] += vvv * a3; acc[19] += vvv * a4;
            acc[20] += vvv * vvv;
        }
    }

    int lane = threadIdx.x & 31, wid = threadIdx.x >> 5;
    __shared__ float part[21][8];
    #pragma unroll
    for (int i = 0; i < 21; i++) {
        float a = acc[i];
        #pragma unroll
        for (int off = 16; off; off >>= 1)
            a += __shfl_xor_sync(0xffffffffu, a, off);
        if (lane == 0) part[i][wid] = a;
    }
    __syncthreads();
    __shared__ float tot[21];
    if (threadIdx.x < 21) {
        float sSum = 0.f;
        #pragma unroll
        for (int w = 0; w < 8; w++) sSum += part[threadIdx.x][w];
        tot[threadIdx.x] = sSum;
    }
    __syncthreads();
    if (threadIdx.x == 0) {
        float G[WAY][WAY];
        int t = 0;
        for (int a = 0; a < WAY; a++)
            for (int b = a; b < WAY; b++) { G[a][b] = tot[t]; G[b][a] = tot[t]; t++; }
        float D[WAY];
        for (int w = 0; w < WAY; w++) D[w] = tot[15 + w];
        float VV = tot[20];
        float nrm[WAY];
        for (int w = 0; w < WAY; w++) nrm[w] = sqrtf(G[w][w]);
        for (int a = 0; a < WAY; a++)
            for (int b = 0; b < WAY; b++)
                out[q * WAY * WAY + a * WAY + b] =
                    G[a][b] / fmaxf(nrm[a] * nrm[b], 1e-8f);
        for (int w = 0; w < WAY; w++)
            out[N_QUERIES * WAY * WAY + q * WAY + w] =
                -(VV - 2.f * D[w] + G[w][w]) / (float)L_TUP;
    }
}

// ---------------------------------------------------------------------------
// Launch
// ---------------------------------------------------------------------------
extern "C" void kernel_launch(void* const* d_in, const int* in_sizes, int n_in,
                              void* d_out, int out_size)
{
    const float* support = (const float*)d_in[0];
    const float* queries = (const float*)d_in[2];
    const float* k_w  = (const float*)d_in[3];
    const float* k_b  = (const float*)d_in[4];
    const float* v_w  = (const float*)d_in[5];
    const float* v_b  = (const float*)d_in[6];
    const float* ln_g = (const float*)d_in[7];
    const float* ln_b = (const float*)d_in[8];
    float* out = (float*)d_out;

    float *P, *S;
    __nv_bfloat16 *Xhl, *Whl, *Wv, *KQhl, *KShl, *Ahl, *Vhl, *proto;
    cudaGetSymbolAddress((void**)&Xhl,   g_Xhl);
    cudaGetSymbolAddress((void**)&Whl,   g_Whl);
    cudaGetSymbolAddress((void**)&Wv,    g_Wv);
    cudaGetSymbolAddress((void**)&P,     g_P);
    cudaGetSymbolAddress((void**)&KQhl,  g_KQhl);
    cudaGetSymbolAddress((void**)&KShl,  g_KShl);
    cudaGetSymbolAddress((void**)&S,     g_S);
    cudaGetSymbolAddress((void**)&Ahl,   g_Ahl);
    cudaGetSymbolAddress((void**)&Vhl,   g_Vhl);
    cudaGetSymbolAddress((void**)&proto, g_proto);

    // 1. fused PE + hi/lo input conversion + weight conversion (one launch)
    {
        int total = CONV_T1 + CONV_T2;
        conv_inputs_kernel<<<(total + 255) / 256, 256>>>(support, queries, k_w, v_w);
    }
    // 2. fused projection: z=0 k-part (K=6144, 3-term), z=1 v-part (K=2048, hi)
    {
        dim3 grid(NK_HALF / 128, (ROWS_X + 127) / 128, 2);
        gemm_proj<<<grid, 256>>>(Xhl, Whl, Wv, P);
    }
    // 3. assemble -> KQhl/KShl (2-term bf16) + vs bf16
    assemble_kernel<<<N_TOTAL * L_TUP, 256>>>(k_b, v_b, ln_g, ln_b);
    // 4. scores = ks_q @ ks_s^T / sqrt(OUT_DIM)  [5600, 700], K=2304 (2-term)
    {
        dim3 grid((ROWS_S + 127) / 128, (ROWS_Q + 127) / 128, 1);
        gemm_f32<<<grid, 256>>>(KQhl, KShl, S, ROWS_Q, ROWS_S, KSC,
                                1.0f / sqrtf((float)OUT_DIM),
                                KSC, KSC, ROWS_S);
    }
    // 5. softmax -> g_Ahl (hi-only) directly
    softmax_kernel<<<ROWS_Q, 160>>>();
    // 6. vs_s^T for proto GEMM
    conv_vsT_kernel<<<(WAY * OUT_DIM * KP2 + 255) / 256, 256>>>();
    // 7. proto[w] = attn_w @ vs_w  [5600, 1152], K=160 — batched, bf16 out
    {
        dim3 grid(OUT_DIM / 128, (ROWS_Q + 127) / 128, WAY);
        gemm_bf16<<<grid, 256>>>(Ahl, Vhl, proto,
                                 ROWS_Q, OUT_DIM, KP2, 1.0f,
                                 KP2, KP2, OUT_DIM,
                                 (size_t)ROWS_Q * KP2,
                                 (size_t)OUT_DIM * KP2,
                                 (size_t)ROWS_Q * OUT_DIM);
    }
    // 8. finalize
    finalize_kernel<<<N_QUERIES, 256>>>(out);
}

// round 16
// speedup vs baseline: 2.1177x; 1.1311x over previous
#include <cuda_runtime.h>
#include <cuda_bf16.h>
#include <math.h>
#include <stdint.h>

// ---------------------------------------------------------------------------
// Problem constants
// ---------------------------------------------------------------------------
#define SEQ_LEN   8
#define D_MODEL   2048
#define OUT_DIM   1152
#define WAY       5
#define SHOT      5
#define N_SUPPORT 25
#define N_QUERIES 200
#define N_TOTAL   225
#define L_TUP     28
#define TWO_D     4096
#define NSTACK    4608          // 4 * OUT_DIM (k h0, k h1, v h0, v h1)
#define NK_HALF   2304          // 2 * OUT_DIM (k columns / v columns)
#define ROWS_X    1800          // N_TOTAL * SEQ_LEN
#define ROWS_Q    5600          // N_QUERIES * L_TUP
#define ROWS_S    700           // N_SUPPORT * L_TUP
#define SEG       140           // SHOT * L_TUP
#define PLANE     32256         // L_TUP * OUT_DIM

// K sizes
#define KKP       4096          // k-projection: 2-term  A=[hi|lo], B=[hi|hi]
#define KVH       2048          // v-projection: hi-only (uses hi prefix of X)
#define KSC       2304          // scores: 2-term  A=[hi|lo], B=[hi|hi]
#define KP2       160           // proto: hi-only, 140 padded to 160

__constant__ int c_t0[L_TUP] = {0,0,0,0,0,0,0,1,1,1,1,1,1,2,2,2,2,2,3,3,3,3,4,4,4,5,5,6};
__constant__ int c_t1[L_TUP] = {1,2,3,4,5,6,7,2,3,4,5,6,7,3,4,5,6,7,4,5,6,7,5,6,7,6,7,7};

// ---------------------------------------------------------------------------
// Scratch (device globals; no allocation allowed)
// ---------------------------------------------------------------------------
__device__ __nv_bfloat16  g_Xhl[(size_t)ROWS_X * KKP];      // [hi | lo]; hi prefix = v-proj A
__device__ __nv_bfloat16  g_Whl[(size_t)NK_HALF * KKP];     // k-weights [hi | hi]
__device__ __nv_bfloat16  g_Wv[(size_t)NK_HALF * KVH];      // v-weights hi only
__device__ float          g_P[(size_t)ROWS_X * NSTACK];
__device__ __nv_bfloat16  g_vs_s[ROWS_S * OUT_DIM];         // bf16
__device__ __nv_bfloat16  g_vs_q[ROWS_Q * OUT_DIM];         // bf16
__device__ __nv_bfloat16  g_KQhl[(size_t)ROWS_Q * KSC];     // queries: [hi | lo]
__device__ __nv_bfloat16  g_KShl[(size_t)ROWS_S * KSC];     // support: [hi | hi]
__device__ float          g_S[(size_t)ROWS_Q * ROWS_S];     // scores
__device__ __nv_bfloat16  g_Ahl[(size_t)WAY * ROWS_Q * KP2];   // attn hi
__device__ __nv_bfloat16  g_Vhl[(size_t)WAY * OUT_DIM * KP2];  // vs_s^T hi slices
__device__ __nv_bfloat16  g_proto[(size_t)WAY * ROWS_Q * OUT_DIM];  // bf16

// ---------------------------------------------------------------------------
// Helpers
// ---------------------------------------------------------------------------
__device__ __forceinline__ uint32_t smem_u32(const void* p) {
    uint32_t a;
    asm("{ .reg .u64 t; cvta.to.shared.u64 t, %1; cvt.u32.u64 %0, t; }"
        : "=r"(a) : "l"(p));
    return a;
}

#define CP16(dst, src) \
    asm volatile("cp.async.cg.shared.global [%0], [%1], 16;" :: "r"(dst), "l"(src))
#define CP_COMMIT() asm volatile("cp.async.commit_group;" ::: "memory")
#define CP_WAIT(n)  asm volatile("cp.async.wait_group %0;" :: "n"(n) : "memory")

__device__ __forceinline__ void split2(float x, __nv_bfloat16& hi, __nv_bfloat16& lo) {
    hi = __float2bfloat16(x);
    lo = __float2bfloat16(x - __bfloat162float(hi));
}

#define LDMX4(d0,d1,d2,d3,addr) \
    asm volatile("ldmatrix.sync.aligned.m8n8.x4.shared.b16 {%0,%1,%2,%3}, [%4];" \
        : "=r"(d0), "=r"(d1), "=r"(d2), "=r"(d3) : "r"(addr))

#define MMA16816(acc, a, b) \
    asm volatile("mma.sync.aligned.m16n8k16.row.col.f32.bf16.bf16.f32 " \
        "{%0,%1,%2,%3}, {%4,%5,%6,%7}, {%8,%9}, {%0,%1,%2,%3};" \
        : "+f"((acc)[0]), "+f"((acc)[1]), "+f"((acc)[2]), "+f"((acc)[3]) \
        : "r"((a)[0]), "r"((a)[1]), "r"((a)[2]), "r"((a)[3]), \
          "r"((b)[0]), "r"((b)[1]))

// ---------------------------------------------------------------------------
// Shared GEMM body (R5-proven): 128x128 CTA tile, BK=32, 4-stage cp.async,
// single barrier per chunk, 8 warps (2x4), warp tile 64x32. K mult of 32.
// OOB rows clamped (their outputs never stored).
// ---------------------------------------------------------------------------
#define GEMM_BODY(A_, B_, C_, M_, N_, K_, alpha_, lda_, ldb_, ldc_, STORE_BF16) \
{                                                                               \
    __shared__ uint4 sbuf[4][1024];                                             \
    const int tid  = threadIdx.x;                                               \
    const int lane = tid & 31;                                                  \
    const int wid  = tid >> 5;                                                  \
    const int wm   = wid >> 2;                                                  \
    const int wn   = wid & 3;                                                   \
    const int row0 = blockIdx.y * 128;                                          \
    const int col0 = blockIdx.x * 128;                                          \
    int l_sw[2];                                                                \
    const __nv_bfloat16 *gA[2], *gB[2];                                         \
    _Pragma("unroll")                                                           \
    for (int i = 0; i < 2; i++) {                                               \
        int ch  = tid + i * 256;                                                \
        int row = ch >> 2, cq = ch & 3;                                         \
        l_sw[i] = row * 4 + ((cq ^ (row >> 1)) & 3);                            \
        int ra = row0 + row; if (ra > (M_) - 1) ra = (M_) - 1;                  \
        int rb = col0 + row; if (rb > (N_) - 1) rb = (N_) - 1;                  \
        gA[i] = (A_) + (size_t)ra * (lda_) + cq * 8;                            \
        gB[i] = (B_) + (size_t)rb * (ldb_) + cq * 8;                            \
    }                                                                           \
    const int NC = (K_) >> 5;                                                   \
    auto issue = [&](int stage, int c) {                                        \
        uint32_t base = smem_u32(&sbuf[stage][0]);                              \
        _Pragma("unroll")                                                       \
        for (int i = 0; i < 2; i++) {                                           \
            CP16(base +        l_sw[i] * 16, gA[i] + c * 32);                   \
            CP16(base + 8192 + l_sw[i] * 16, gB[i] + c * 32);                   \
        }                                                                       \
        CP_COMMIT();                                                            \
    };                                                                          \
    float acc[4][4][4];                                                         \
    _Pragma("unroll")                                                           \
    for (int mi = 0; mi < 4; mi++)                                              \
        _Pragma("unroll")                                                       \
        for (int ni = 0; ni < 4; ni++)                                          \
            _Pragma("unroll")                                                   \
            for (int e = 0; e < 4; e++) acc[mi][ni][e] = 0.f;                   \
    const int q = lane >> 3;                                                    \
    const int r = lane & 7;                                                     \
    auto compute = [&](int stage) {                                             \
        uint32_t abase = smem_u32(&sbuf[stage][0]);                             \
        uint32_t bbase = abase + 8192;                                          \
        _Pragma("unroll")                                                       \
        for (int ks = 0; ks < 2; ks++) {                                        \
            uint32_t af[4][4];                                                  \
            _Pragma("unroll")                                                   \
            for (int mi = 0; mi < 4; mi++) {                                    \
                int row = wm * 64 + mi * 16 + r + (q & 1) * 8;                  \
                int cq  = ks * 2 + (q >> 1);                                    \
                uint32_t ad = abase + (uint32_t)(row * 4 + ((cq ^ (row >> 1)) & 3)) * 16u; \
                LDMX4(af[mi][0], af[mi][1], af[mi][2], af[mi][3], ad);          \
            }                                                                   \
            uint32_t bf[4][2];                                                  \
            _Pragma("unroll")                                                   \
            for (int nh = 0; nh < 2; nh++) {                                    \
                int ni  = nh * 2 + (q >> 1);                                    \
                int row = wn * 32 + ni * 8 + r;                                 \
                int cq  = ks * 2 + (q & 1);                                     \
                uint32_t bd = bbase + (uint32_t)(row * 4 + ((cq ^ (row >> 1)) & 3)) * 16u; \
                LDMX4(bf[nh*2][0], bf[nh*2][1], bf[nh*2+1][0], bf[nh*2+1][1], bd); \
            }                                                                   \
            _Pragma("unroll")                                                   \
            for (int mi = 0; mi < 4; mi++)                                      \
                _Pragma("unroll")                                               \
                for (int ni = 0; ni < 4; ni++)                                  \
                    MMA16816(acc[mi][ni], af[mi], bf[ni]);                      \
        }                                                                       \
    };                                                                          \
    issue(0, 0);                                                                \
    if (NC > 1) issue(1, 1);                                                    \
    if (NC > 2) issue(2, 2);                                                    \
    for (int c = 0; c < NC; c++) {                                              \
        if (c + 2 < NC)      CP_WAIT(2);                                        \
        else if (c + 1 < NC) CP_WAIT(1);                                        \
        else                 CP_WAIT(0);                                        \
        __syncthreads();                                                        \
        if (c + 3 < NC) issue((c + 3) & 3, c + 3);                              \
        compute(c & 3);                                                         \
    }                                                                           \
    const int g  = lane >> 2;                                                   \
    const int tg = lane & 3;                                                    \
    _Pragma("unroll")                                                           \
    for (int mi = 0; mi < 4; mi++) {                                            \
        int rr0 = row0 + wm * 64 + mi * 16 + g;                                 \
        int rr1 = rr0 + 8;                                                      \
        _Pragma("unroll")                                                       \
        for (int ni = 0; ni < 4; ni++) {                                        \
            int cc = col0 + wn * 32 + ni * 8 + tg * 2;                          \
            if (cc < (N_)) {                                                    \
                if (rr0 < (M_)) {                                               \
                    if (!(STORE_BF16)) {                                        \
                        float2 v = make_float2((alpha_) * acc[mi][ni][0],       \
                                               (alpha_) * acc[mi][ni][1]);      \
                        *(float2*)((float*)(C_) + (size_t)rr0 * (ldc_) + cc) = v; \
                    } else {                                                    \
                        __nv_bfloat162 h;                                       \
                        h.x = __float2bfloat16((alpha_) * acc[mi][ni][0]);      \
                        h.y = __float2bfloat16((alpha_) * acc[mi][ni][1]);      \
                        *(__nv_bfloat162*)((__nv_bfloat16*)(C_) + (size_t)rr0 * (ldc_) + cc) = h; \
                    }                                                           \
                }                                                               \
                if (rr1 < (M_)) {                                               \
                    if (!(STORE_BF16)) {                                        \
                        float2 v = make_float2((alpha_) * acc[mi][ni][2],       \
                                               (alpha_) * acc[mi][ni][3]);      \
                        *(float2*)((float*)(C_) + (size_t)rr1 * (ldc_) + cc) = v; \
                    } else {                                                    \
                        __nv_bfloat162 h;                                       \
                        h.x = __float2bfloat16((alpha_) * acc[mi][ni][2]);      \
                        h.y = __float2bfloat16((alpha_) * acc[mi][ni][3]);      \
                        *(__nv_bfloat162*)((__nv_bfloat16*)(C_) + (size_t)rr1 * (ldc_) + cc) = h; \
                    }                                                           \
                }                                                               \
            }                                                                   \
        }                                                                       \
    }                                                                           \
}

// ---------------------------------------------------------------------------
// Fused projection GEMM: z=0 -> k-part (B=Whl, K=4096, 2-term),
// z=1 -> v-part (B=Wv, K=2048 hi-only, C offset +NK_HALF).
// Same A (Xhl, lda=KKP; v uses the hi prefix), same grid x/y.
// ---------------------------------------------------------------------------
__global__ __launch_bounds__(256, 2)
void gemm_proj(const __nv_bfloat16* __restrict__ A,
               const __nv_bfloat16* __restrict__ Bk,
               const __nv_bfloat16* __restrict__ Bv,
               float* __restrict__ C)
{
    const __nv_bfloat16* B;
    int K, ldb;
    float* Cp;
    if (blockIdx.z == 0) { B = Bk; K = KKP; ldb = KKP; Cp = C; }
    else                 { B = Bv; K = KVH; ldb = KVH; Cp = C + NK_HALF; }
    GEMM_BODY(A, B, Cp, ROWS_X, NK_HALF, K, 1.0f, KKP, ldb, NSTACK, 0)
}

// ---------------------------------------------------------------------------
// Generic GEMM (fp32 out): scores
// ---------------------------------------------------------------------------
__global__ __launch_bounds__(256, 2)
void gemm_f32(const __nv_bfloat16* __restrict__ A, const __nv_bfloat16* __restrict__ B,
              float* __restrict__ C, int M, int N, int K, float alpha,
              int lda, int ldb, int ldc)
{
    GEMM_BODY(A, B, C, M, N, K, alpha, lda, ldb, ldc, 0)
}

// ---------------------------------------------------------------------------
// Generic GEMM (bf16 out, z-batched): proto
// ---------------------------------------------------------------------------
__global__ __launch_bounds__(256, 2)
void gemm_bf16(const __nv_bfloat16* __restrict__ A, const __nv_bfloat16* __restrict__ B,
               __nv_bfloat16* __restrict__ C, int M, int N, int K, float alpha,
               int lda, int ldb, int ldc,
               size_t aStride, size_t bStride, size_t cStride)
{
    A += (size_t)blockIdx.z * aStride;
    B += (size_t)blockIdx.z * bStride;
    C += (size_t)blockIdx.z * cStride;
    GEMM_BODY(A, B, C, M, N, K, alpha, lda, ldb, ldc, 1)
}

// ---------------------------------------------------------------------------
// Fused conversion: X+PE -> [hi|lo]; k-weights -> [hi|hi]; v-weights -> hi
// ---------------------------------------------------------------------------
#define CONV_T1 (ROWS_X * D_MODEL)
#define CONV_T2 (NSTACK * D_MODEL)

__global__ void conv_inputs_kernel(const float* __restrict__ support,
                                   const float* __restrict__ queries,
                                   const float* __restrict__ k_w,
                                   const float* __restrict__ v_w)
{
    int e = blockIdx.x * blockDim.x + threadIdx.x;
    if (e < CONV_T1) {
        int n = e / (SEQ_LEN * D_MODEL);
        int rem = e % (SEQ_LEN * D_MODEL);
        int s = rem / D_MODEL, d = rem % D_MODEL;
        const float c = -9.210340371976184f / (float)D_MODEL;
        float div = expf((float)(2 * (d >> 1)) * c);
        float arg = (float)s * div;
        float pe = ((d & 1) ? cosf(arg) : sinf(arg)) * 0.1f;
        float x = ((n < N_SUPPORT) ? support[e]
                                   : queries[e - N_SUPPORT * SEQ_LEN * D_MODEL]) + pe;
        __nv_bfloat16 hi, lo; split2(x, hi, lo);
        int row = e / D_MODEL;
        __nv_bfloat16* o = g_Xhl + (size_t)row * KKP;
        o[d] = hi; o[D_MODEL + d] = lo;
    } else if (e < CONV_T1 + CONV_T2) {
        int e2 = e - CONV_T1;
        int j = e2 / D_MODEL, k = e2 % D_MODEL;
        int part = j / OUT_DIM, o = j % OUT_DIM;
        if (part < 2) {                    // k-weights: [hi | hi]
            float x = k_w[(size_t)o * TWO_D + part * D_MODEL + k];
            __nv_bfloat16 hi = __float2bfloat16(x);
            __nv_bfloat16* dst = g_Whl + (size_t)j * KKP;
            dst[k] = hi; dst[D_MODEL + k] = hi;
        } else {                           // v-weights: hi only
            int j2 = j - NK_HALF;
            float x = v_w[(size_t)o * TWO_D + (part & 1) * D_MODEL + k];
            g_Wv[(size_t)j2 * KVH + k] = __float2bfloat16(x);
        }
    }
}

// vs_s^T slices -> [WAY][OUT_DIM][KP2], pad 140..159 zero
__global__ void conv_vsT_kernel()
{
    int e = blockIdx.x * blockDim.x + threadIdx.x;
    const int total = WAY * OUT_DIM * KP2;
    if (e >= total) return;
    int w = e / (OUT_DIM * KP2);
    int rem = e % (OUT_DIM * KP2);
    int d = rem / KP2, j = rem % KP2;
    __nv_bfloat16 v = __float2bfloat16(0.f);
    if (j < SEG)
        v = g_vs_s[(size_t)(w * SEG + j) * OUT_DIM + d];
    g_Vhl[e] = v;
}

// ---------------------------------------------------------------------------
// assemble tuple features + LayerNorm(k) -> 2-term bf16 layouts, v -> bf16.
// queries: kd = [hi | lo];  support: kd = [hi | hi]
// ---------------------------------------------------------------------------
__global__ __launch_bounds__(256)
void assemble_kernel(const float* __restrict__ k_b, const float* __restrict__ v_b,
                     const float* __restrict__ ln_g, const float* __restrict__ ln_b)
{
    int rl = blockIdx.x;
    int n = rl / L_TUP, l = rl % L_TUP;
    int t0 = c_t0[l], t1 = c_t1[l];
    const float* P0 = g_P + (size_t)(n * SEQ_LEN + t0) * NSTACK;
    const float* P1 = g_P + (size_t)(n * SEQ_LEN + t1) * NSTACK;

    const bool isSup = (n < N_SUPPORT);
    __nv_bfloat16* kd;
    __nv_bfloat16* vsd;
    if (isSup) {
        kd  = g_KShl + (size_t)(n * L_TUP + l) * KSC;
        vsd = g_vs_s + (size_t)(n * L_TUP + l) * OUT_DIM;
    } else {
        int m = n - N_SUPPORT;
        kd  = g_KQhl + (size_t)(m * L_TUP + l) * KSC;
        vsd = g_vs_q + (size_t)(m * L_TUP + l) * OUT_DIM;
    }

    __shared__ float kbuf[OUT_DIM];
    float s = 0.f, s2 = 0.f;
    for (int o = threadIdx.x; o < OUT_DIM; o += blockDim.x) {
        float kv = P0[o] + P1[OUT_DIM + o] + k_b[o];
        kbuf[o] = kv; s += kv; s2 += kv * kv;
        vsd[o] = __float2bfloat16(P0[2 * OUT_DIM + o] + P1[3 * OUT_DIM + o] + v_b[o]);
    }
    int lane = threadIdx.x & 31, wid = threadIdx.x >> 5;
    #pragma unroll
    for (int off = 16; off; off >>= 1) {
        s  += __shfl_xor_sync(0xffffffffu, s,  off);
        s2 += __shfl_xor_sync(0xffffffffu, s2, off);
    }
    __shared__ float ws[8], ws2[8], sm_mean, sm_rstd;
    if (lane == 0) { ws[wid] = s; ws2[wid] = s2; }
    __syncthreads();
    if (threadIdx.x == 0) {
        float S = 0.f, S2 = 0.f;
        #pragma unroll
        for (int w = 0; w < 8; w++) { S += ws[w]; S2 += ws2[w]; }
        float mean = S / (float)OUT_DIM;
        float var  = S2 / (float)OUT_DIM - mean * mean;
        sm_mean = mean; sm_rstd = rsqrtf(var + 1e-5f);
    }
    __syncthreads();
    float mean = sm_mean, rstd = sm_rstd;
    for (int o = threadIdx.x; o < OUT_DIM; o += blockDim.x) {
        float y = (kbuf[o] - mean) * rstd * ln_g[o] + ln_b[o];
        __nv_bfloat16 hi, lo; split2(y, hi, lo);
        kd[o] = hi;
        kd[OUT_DIM + o] = isSup ? hi : lo;
    }
}

// ---------------------------------------------------------------------------
// per-row blockwise softmax; writes hi-only attn (K=160) directly to g_Ahl.
// ---------------------------------------------------------------------------
__global__ __launch_bounds__(160)
void softmax_kernel()
{
    int row = blockIdx.x;
    int warp = threadIdx.x >> 5, lane = threadIdx.x & 31;
    const float* p = g_S + (size_t)row * ROWS_S + warp * SEG;
    float v[5]; float mx = -INFINITY;
    #pragma unroll
    for (int i = 0; i < 5; i++) {
        int c = lane + 32 * i;
        v[i] = (c < SEG) ? p[c] : -INFINITY;
        mx = fmaxf(mx, v[i]);
    }
    #pragma unroll
    for (int off = 16; off; off >>= 1)
        mx = fmaxf(mx, __shfl_xor_sync(0xffffffffu, mx, off));
    float sm = 0.f;
    #pragma unroll
    for (int i = 0; i < 5; i++) {
        int c = lane + 32 * i;
        v[i] = (c < SEG) ? expf(v[i] - mx) : 0.f;
        sm += v[i];
    }
    #pragma unroll
    for (int off = 16; off; off >>= 1)
        sm += __shfl_xor_sync(0xffffffffu, sm, off);
    float inv = 1.f / sm;

    __nv_bfloat16* a = g_Ahl + ((size_t)warp * ROWS_Q + row) * KP2;
    #pragma unroll
    for (int i = 0; i < 5; i++) {
        int c = lane + 32 * i;
        if (c < SEG)
            a[c] = __float2bfloat16(v[i] * inv);
    }
    if (lane < KP2 - SEG)
        a[SEG + lane] = __float2bfloat16(0.f);
}

// ---------------------------------------------------------------------------
// per-query Gram matrix + distances -> sim, ori  (bf16 inputs, uint4 loads)
// ---------------------------------------------------------------------------
__global__ __launch_bounds__(256)
void finalize_kernel(float* __restrict__ out)
{
    int q = blockIdx.x;
    const uint4* v8 = (const uint4*)(g_vs_q + (size_t)q * PLANE);
    const uint4* pp8[WAY];
    #pragma unroll
    for (int w = 0; w < WAY; w++)
        pp8[w] = (const uint4*)(g_proto + (size_t)w * ROWS_Q * OUT_DIM
                                + (size_t)q * PLANE);

    float acc[21];
    #pragma unroll
    for (int i = 0; i < 21; i++) acc[i] = 0.f;

    const int NV8 = PLANE / 8;                 // 4032
    for (int i = threadIdx.x; i < NV8; i += blockDim.x) {
        uint4 uv = v8[i];
        uint4 u0 = pp8[0][i], u1 = pp8[1][i], u2 = pp8[2][i],
              u3 = pp8[3][i], u4 = pp8[4][i];
        float fv[8], f0[8], f1[8], f2[8], f3[8], f4[8];
        #pragma unroll
        for (int h = 0; h < 4; h++) {
            float2 t;
            t = __bfloat1622float2(*(__nv_bfloat162*)((uint32_t*)&uv + h));
            fv[2*h] = t.x; fv[2*h+1] = t.y;
            t = __bfloat1622float2(*(__nv_bfloat162*)((uint32_t*)&u0 + h));
            f0[2*h] = t.x; f0[2*h+1] = t.y;
            t = __bfloat1622float2(*(__nv_bfloat162*)((uint32_t*)&u1 + h));
            f1[2*h] = t.x; f1[2*h+1] = t.y;
            t = __bfloat1622float2(*(__nv_bfloat162*)((uint32_t*)&u2 + h));
            f2[2*h] = t.x; f2[2*h+1] = t.y;
            t = __bfloat1622float2(*(__nv_bfloat162*)((uint32_t*)&u3 + h));
            f3[2*h] = t.x; f3[2*h+1] = t.y;
            t = __bfloat1622float2(*(__nv_bfloat162*)((uint32_t*)&u4 + h));
            f4[2*h] = t.x; f4[2*h+1] = t.y;
        }
        #pragma unroll
        for (int e = 0; e < 8; e++) {
            float vvv = fv[e];
            float a0 = f0[e], a1 = f1[e], a2 = f2[e], a3 = f3[e], a4 = f4[e];
            acc[0]  += a0 * a0;  acc[1]  += a0 * a1;  acc[2]  += a0 * a2;
            acc[3]  += a0 * a3;  acc[4]  += a0 * a4;
            acc[5]  += a1 * a1;  acc[6]  += a1 * a2;  acc[7]  += a1 * a3;
            acc[8]  += a1 * a4;
            acc[9]  += a2 * a2;  acc[10] += a2 * a3;  acc[11] += a2 * a4;
            acc[12] += a3 * a3;  acc[13] += a3 * a4;
            acc[14] += a4 * a4;
            acc[15] += vvv * a0; acc[16] += vvv * a1; acc[17] += vvv * a2;
            acc[18] += vvv * a3; acc[19] += vvv * a4;
            acc[20] += vvv * vvv;
        }
    }

    int lane = threadIdx.x & 31, wid = threadIdx.x >> 5;
    __shared__ float part[21][8];
    #pragma unroll
    for (int i = 0; i < 21; i++) {
        float a = acc[i];
        #pragma unroll
        for (int off = 16; off; off >>= 1)
            a += __shfl_xor_sync(0xffffffffu, a, off);
        if (lane == 0) part[i][wid] = a;
    }
    __syncthreads();
    __shared__ float tot[21];
    if (threadIdx.x < 21) {
        float sSum = 0.f;
        #pragma unroll
        for (int w = 0; w < 8; w++) sSum += part[threadIdx.x][w];
        tot[threadIdx.x] = sSum;
    }
    __syncthreads();
    if (threadIdx.x == 0) {
        float G[WAY][WAY];
        int t = 0;
        for (int a = 0; a < WAY; a++)
            for (int b = a; b < WAY; b++) { G[a][b] = tot[t]; G[b][a] = tot[t]; t++; }
        float D[WAY];
        for (int w = 0; w < WAY; w++) D[w] = tot[15 + w];
        float VV = tot[20];
        float nrm[WAY];
        for (int w = 0; w < WAY; w++) nrm[w] = sqrtf(G[w][w]);
        for (int a = 0; a < WAY; a++)
            for (int b = 0; b < WAY; b++)
                out[q * WAY * WAY + a * WAY + b] =
                    G[a][b] / fmaxf(nrm[a] * nrm[b], 1e-8f);
        for (int w = 0; w < WAY; w++)
            out[N_QUERIES * WAY * WAY + q * WAY + w] =
                -(VV - 2.f * D[w] + G[w][w]) / (float)L_TUP;
    }
}

// ---------------------------------------------------------------------------
// Launch
// ---------------------------------------------------------------------------
extern "C" void kernel_launch(void* const* d_in, const int* in_sizes, int n_in,
                              void* d_out, int out_size)
{
    const float* support = (const float*)d_in[0];
    const float* queries = (const float*)d_in[2];
    const float* k_w  = (const float*)d_in[3];
    const float* k_b  = (const float*)d_in[4];
    const float* v_w  = (const float*)d_in[5];
    const float* v_b  = (const float*)d_in[6];
    const float* ln_g = (const float*)d_in[7];
    const float* ln_b = (const float*)d_in[8];
    float* out = (float*)d_out;

    float *P, *S;
    __nv_bfloat16 *Xhl, *Whl, *Wv, *KQhl, *KShl, *Ahl, *Vhl, *proto;
    cudaGetSymbolAddress((void**)&Xhl,   g_Xhl);
    cudaGetSymbolAddress((void**)&Whl,   g_Whl);
    cudaGetSymbolAddress((void**)&Wv,    g_Wv);
    cudaGetSymbolAddress((void**)&P,     g_P);
    cudaGetSymbolAddress((void**)&KQhl,  g_KQhl);
    cudaGetSymbolAddress((void**)&KShl,  g_KShl);
    cudaGetSymbolAddress((void**)&S,     g_S);
    cudaGetSymbolAddress((void**)&Ahl,   g_Ahl);
    cudaGetSymbolAddress((void**)&Vhl,   g_Vhl);
    cudaGetSymbolAddress((void**)&proto, g_proto);

    // 1. fused PE + hi/lo input conversion + weight conversion (one launch)
    {
        int total = CONV_T1 + CONV_T2;
        conv_inputs_kernel<<<(total + 255) / 256, 256>>>(support, queries, k_w, v_w);
    }
    // 2. fused projection: z=0 k-part (K=4096, 2-term), z=1 v-part (K=2048, hi)
    {
        dim3 grid(NK_HALF / 128, (ROWS_X + 127) / 128, 2);
        gemm_proj<<<grid, 256>>>(Xhl, Whl, Wv, P);
    }
    // 3. assemble -> KQhl/KShl (2-term bf16) + vs bf16
    assemble_kernel<<<N_TOTAL * L_TUP, 256>>>(k_b, v_b, ln_g, ln_b);
    // 4. scores = ks_q @ ks_s^T / sqrt(OUT_DIM)  [5600, 700], K=2304 (2-term)
    {
        dim3 grid((ROWS_S + 127) / 128, (ROWS_Q + 127) / 128, 1);
        gemm_f32<<<grid, 256>>>(KQhl, KShl, S, ROWS_Q, ROWS_S, KSC,
                                1.0f / sqrtf((float)OUT_DIM),
                                KSC, KSC, ROWS_S);
    }
    // 5. softmax -> g_Ahl (hi-only) directly
    softmax_kernel<<<ROWS_Q, 160>>>();
    // 6. vs_s^T for proto GEMM
    conv_vsT_kernel<<<(WAY * OUT_DIM * KP2 + 255) / 256, 256>>>();
    // 7. proto[w] = attn_w @ vs_w  [5600, 1152], K=160 — batched, bf16 out
    {
        dim3 grid(OUT_DIM / 128, (ROWS_Q + 127) / 128, WAY);
        gemm_bf16<<<grid, 256>>>(Ahl, Vhl, proto,
                                 ROWS_Q, OUT_DIM, KP2, 1.0f,
                                 KP2, KP2, OUT_DIM,
                                 (size_t)ROWS_Q * KP2,
                                 (size_t)OUT_DIM * KP2,
                                 (size_t)ROWS_Q * OUT_DIM);
    }
    // 8. finalize
    finalize_kernel<<<N_QUERIES, 256>>>(out);
}

// round 17
// speedup vs baseline: 2.3313x; 1.1009x over previous
#include <cuda_runtime.h>
#include <cuda_bf16.h>
#include <math.h>
#include <stdint.h>

// ---------------------------------------------------------------------------
// Problem constants
// ---------------------------------------------------------------------------
#define SEQ_LEN   8
#define D_MODEL   2048
#define OUT_DIM   1152
#define WAY       5
#define SHOT      5
#define N_SUPPORT 25
#define N_QUERIES 200
#define N_TOTAL   225
#define L_TUP     28
#define TWO_D     4096
#define NSTACK    4608          // 4 * OUT_DIM (k h0, k h1, v h0, v h1)
#define NK_HALF   2304          // 2 * OUT_DIM (k columns / v columns)
#define ROWS_X    1800          // N_TOTAL * SEQ_LEN
#define ROWS_Q    5600          // N_QUERIES * L_TUP
#define ROWS_S    700           // N_SUPPORT * L_TUP
#define SEG       140           // SHOT * L_TUP
#define PLANE     32256         // L_TUP * OUT_DIM

// K sizes
#define KKP       4096          // k-projection: 2-term  A=[hi|lo], B=[hi|hi]
#define KVH       2048          // v-projection: hi-only (uses hi prefix of X)
#define KSC       1152          // scores: hi-only
#define KP2       160           // proto: hi-only, 140 padded to 160

__constant__ int c_t0[L_TUP] = {0,0,0,0,0,0,0,1,1,1,1,1,1,2,2,2,2,2,3,3,3,3,4,4,4,5,5,6};
__constant__ int c_t1[L_TUP] = {1,2,3,4,5,6,7,2,3,4,5,6,7,3,4,5,6,7,4,5,6,7,5,6,7,6,7,7};

// ---------------------------------------------------------------------------
// Scratch (device globals; no allocation allowed).
// NOTE: g_Vhl pad columns j in [SEG, KP2) are NEVER written; __device__
// globals are zero-initialized, so the padding stays zero across replays.
// ---------------------------------------------------------------------------
__device__ __nv_bfloat16  g_Xhl[(size_t)ROWS_X * KKP];      // [hi | lo]; hi prefix = v-proj A
__device__ __nv_bfloat16  g_Whl[(size_t)NK_HALF * KKP];     // k-weights [hi | hi]
__device__ __nv_bfloat16  g_Wv[(size_t)NK_HALF * KVH];      // v-weights hi only
__device__ float          g_P[(size_t)ROWS_X * NSTACK];
__device__ __nv_bfloat16  g_vs_q[ROWS_Q * OUT_DIM];         // bf16
__device__ __nv_bfloat16  g_KQhl[(size_t)ROWS_Q * KSC];     // queries: hi
__device__ __nv_bfloat16  g_KShl[(size_t)ROWS_S * KSC];     // support: hi
__device__ float          g_S[(size_t)ROWS_Q * ROWS_S];     // scores
__device__ __nv_bfloat16  g_Ahl[(size_t)WAY * ROWS_Q * KP2];   // attn hi
__device__ __nv_bfloat16  g_Vhl[(size_t)WAY * OUT_DIM * KP2];  // vs_s^T hi (from assemble)
__device__ __nv_bfloat16  g_proto[(size_t)WAY * ROWS_Q * OUT_DIM];  // bf16

// ---------------------------------------------------------------------------
// Helpers
// ---------------------------------------------------------------------------
__device__ __forceinline__ uint32_t smem_u32(const void* p) {
    uint32_t a;
    asm("{ .reg .u64 t; cvta.to.shared.u64 t, %1; cvt.u32.u64 %0, t; }"
        : "=r"(a) : "l"(p));
    return a;
}

#define CP16(dst, src) \
    asm volatile("cp.async.cg.shared.global [%0], [%1], 16;" :: "r"(dst), "l"(src))
#define CP_COMMIT() asm volatile("cp.async.commit_group;" ::: "memory")
#define CP_WAIT(n)  asm volatile("cp.async.wait_group %0;" :: "n"(n) : "memory")

__device__ __forceinline__ void split2(float x, __nv_bfloat16& hi, __nv_bfloat16& lo) {
    hi = __float2bfloat16(x);
    lo = __float2bfloat16(x - __bfloat162float(hi));
}

#define LDMX4(d0,d1,d2,d3,addr) \
    asm volatile("ldmatrix.sync.aligned.m8n8.x4.shared.b16 {%0,%1,%2,%3}, [%4];" \
        : "=r"(d0), "=r"(d1), "=r"(d2), "=r"(d3) : "r"(addr))

#define MMA16816(acc, a, b) \
    asm volatile("mma.sync.aligned.m16n8k16.row.col.f32.bf16.bf16.f32 " \
        "{%0,%1,%2,%3}, {%4,%5,%6,%7}, {%8,%9}, {%0,%1,%2,%3};" \
        : "+f"((acc)[0]), "+f"((acc)[1]), "+f"((acc)[2]), "+f"((acc)[3]) \
        : "r"((a)[0]), "r"((a)[1]), "r"((a)[2]), "r"((a)[3]), \
          "r"((b)[0]), "r"((b)[1]))

// ---------------------------------------------------------------------------
// Shared GEMM body (R5-proven): 128x128 CTA tile, BK=32, 4-stage cp.async,
// single barrier per chunk, 8 warps (2x4), warp tile 64x32. K mult of 32.
// OOB rows clamped (their outputs never stored).
// ---------------------------------------------------------------------------
#define GEMM_BODY(A_, B_, C_, M_, N_, K_, alpha_, lda_, ldb_, ldc_, STORE_BF16) \
{                                                                               \
    __shared__ uint4 sbuf[4][1024];                                             \
    const int tid  = threadIdx.x;                                               \
    const int lane = tid & 31;                                                  \
    const int wid  = tid >> 5;                                                  \
    const int wm   = wid >> 2;                                                  \
    const int wn   = wid & 3;                                                   \
    const int row0 = blockIdx.y * 128;                                          \
    const int col0 = blockIdx.x * 128;                                          \
    int l_sw[2];                                                                \
    const __nv_bfloat16 *gA[2], *gB[2];                                         \
    _Pragma("unroll")                                                           \
    for (int i = 0; i < 2; i++) {                                               \
        int ch  = tid + i * 256;                                                \
        int row = ch >> 2, cq = ch & 3;                                         \
        l_sw[i] = row * 4 + ((cq ^ (row >> 1)) & 3);                            \
        int ra = row0 + row; if (ra > (M_) - 1) ra = (M_) - 1;                  \
        int rb = col0 + row; if (rb > (N_) - 1) rb = (N_) - 1;                  \
        gA[i] = (A_) + (size_t)ra * (lda_) + cq * 8;                            \
        gB[i] = (B_) + (size_t)rb * (ldb_) + cq * 8;                            \
    }                                                                           \
    const int NC = (K_) >> 5;                                                   \
    auto issue = [&](int stage, int c) {                                        \
        uint32_t base = smem_u32(&sbuf[stage][0]);                              \
        _Pragma("unroll")                                                       \
        for (int i = 0; i < 2; i++) {                                           \
            CP16(base +        l_sw[i] * 16, gA[i] + c * 32);                   \
            CP16(base + 8192 + l_sw[i] * 16, gB[i] + c * 32);                   \
        }                                                                       \
        CP_COMMIT();                                                            \
    };                                                                          \
    float acc[4][4][4];                                                         \
    _Pragma("unroll")                                                           \
    for (int mi = 0; mi < 4; mi++)                                              \
        _Pragma("unroll")                                                       \
        for (int ni = 0; ni < 4; ni++)                                          \
            _Pragma("unroll")                                                   \
            for (int e = 0; e < 4; e++) acc[mi][ni][e] = 0.f;                   \
    const int q = lane >> 3;                                                    \
    const int r = lane & 7;                                                     \
    auto compute = [&](int stage) {                                             \
        uint32_t abase = smem_u32(&sbuf[stage][0]);                             \
        uint32_t bbase = abase + 8192;                                          \
        _Pragma("unroll")                                                       \
        for (int ks = 0; ks < 2; ks++) {                                        \
            uint32_t af[4][4];                                                  \
            _Pragma("unroll")                                                   \
            for (int mi = 0; mi < 4; mi++) {                                    \
                int row = wm * 64 + mi * 16 + r + (q & 1) * 8;                  \
                int cq  = ks * 2 + (q >> 1);                                    \
                uint32_t ad = abase + (uint32_t)(row * 4 + ((cq ^ (row >> 1)) & 3)) * 16u; \
                LDMX4(af[mi][0], af[mi][1], af[mi][2], af[mi][3], ad);          \
            }                                                                   \
            uint32_t bf[4][2];                                                  \
            _Pragma("unroll")                                                   \
            for (int nh = 0; nh < 2; nh++) {                                    \
                int ni  = nh * 2 + (q >> 1);                                    \
                int row = wn * 32 + ni * 8 + r;                                 \
                int cq  = ks * 2 + (q & 1);                                     \
                uint32_t bd = bbase + (uint32_t)(row * 4 + ((cq ^ (row >> 1)) & 3)) * 16u; \
                LDMX4(bf[nh*2][0], bf[nh*2][1], bf[nh*2+1][0], bf[nh*2+1][1], bd); \
            }                                                                   \
            _Pragma("unroll")                                                   \
            for (int mi = 0; mi < 4; mi++)                                      \
                _Pragma("unroll")                                               \
                for (int ni = 0; ni < 4; ni++)                                  \
                    MMA16816(acc[mi][ni], af[mi], bf[ni]);                      \
        }                                                                       \
    };                                                                          \
    issue(0, 0);                                                                \
    if (NC > 1) issue(1, 1);                                                    \
    if (NC > 2) issue(2, 2);                                                    \
    for (int c = 0; c < NC; c++) {                                              \
        if (c + 2 < NC)      CP_WAIT(2);                                        \
        else if (c + 1 < NC) CP_WAIT(1);                                        \
        else                 CP_WAIT(0);                                        \
        __syncthreads();                                                        \
        if (c + 3 < NC) issue((c + 3) & 3, c + 3);                              \
        compute(c & 3);                                                         \
    }                                                                           \
    const int g  = lane >> 2;                                                   \
    const int tg = lane & 3;                                                    \
    _Pragma("unroll")                                                           \
    for (int mi = 0; mi < 4; mi++) {                                            \
        int rr0 = row0 + wm * 64 + mi * 16 + g;                                 \
        int rr1 = rr0 + 8;                                                      \
        _Pragma("unroll")                                                       \
        for (int ni = 0; ni < 4; ni++) {                                        \
            int cc = col0 + wn * 32 + ni * 8 + tg * 2;                          \
            if (cc < (N_)) {                                                    \
                if (rr0 < (M_)) {                                               \
                    if (!(STORE_BF16)) {                                        \
                        float2 v = make_float2((alpha_) * acc[mi][ni][0],       \
                                               (alpha_) * acc[mi][ni][1]);      \
                        *(float2*)((float*)(C_) + (size_t)rr0 * (ldc_) + cc) = v; \
                    } else {                                                    \
                        __nv_bfloat162 h;                                       \
                        h.x = __float2bfloat16((alpha_) * acc[mi][ni][0]);      \
                        h.y = __float2bfloat16((alpha_) * acc[mi][ni][1]);      \
                        *(__nv_bfloat162*)((__nv_bfloat16*)(C_) + (size_t)rr0 * (ldc_) + cc) = h; \
                    }                                                           \
                }                                                               \
                if (rr1 < (M_)) {                                               \
                    if (!(STORE_BF16)) {                                        \
                        float2 v = make_float2((alpha_) * acc[mi][ni][2],       \
                                               (alpha_) * acc[mi][ni][3]);      \
                        *(float2*)((float*)(C_) + (size_t)rr1 * (ldc_) + cc) = v; \
                    } else {                                                    \
                        __nv_bfloat162 h;                                       \
                        h.x = __float2bfloat16((alpha_) * acc[mi][ni][2]);      \
                        h.y = __float2bfloat16((alpha_) * acc[mi][ni][3]);      \
                        *(__nv_bfloat162*)((__nv_bfloat16*)(C_) + (size_t)rr1 * (ldc_) + cc) = h; \
                    }                                                           \
                }                                                               \
            }                                                                   \
        }                                                                       \
    }                                                                           \
}

// ---------------------------------------------------------------------------
// Fused projection GEMM: z=0 -> k-part (B=Whl, K=4096, 2-term),
// z=1 -> v-part (B=Wv, K=2048 hi-only, C offset +NK_HALF).
// ---------------------------------------------------------------------------
__global__ __launch_bounds__(256, 2)
void gemm_proj(const __nv_bfloat16* __restrict__ A,
               const __nv_bfloat16* __restrict__ Bk,
               const __nv_bfloat16* __restrict__ Bv,
               float* __restrict__ C)
{
    const __nv_bfloat16* B;
    int K, ldb;
    float* Cp;
    if (blockIdx.z == 0) { B = Bk; K = KKP; ldb = KKP; Cp = C; }
    else                 { B = Bv; K = KVH; ldb = KVH; Cp = C + NK_HALF; }
    GEMM_BODY(A, B, Cp, ROWS_X, NK_HALF, K, 1.0f, KKP, ldb, NSTACK, 0)
}

// ---------------------------------------------------------------------------
// Generic GEMM (fp32 out): scores
// ---------------------------------------------------------------------------
__global__ __launch_bounds__(256, 2)
void gemm_f32(const __nv_bfloat16* __restrict__ A, const __nv_bfloat16* __restrict__ B,
              float* __restrict__ C, int M, int N, int K, float alpha,
              int lda, int ldb, int ldc)
{
    GEMM_BODY(A, B, C, M, N, K, alpha, lda, ldb, ldc, 0)
}

// ---------------------------------------------------------------------------
// Generic GEMM (bf16 out, z-batched): proto
// ---------------------------------------------------------------------------
__global__ __launch_bounds__(256, 2)
void gemm_bf16(const __nv_bfloat16* __restrict__ A, const __nv_bfloat16* __restrict__ B,
               __nv_bfloat16* __restrict__ C, int M, int N, int K, float alpha,
               int lda, int ldb, int ldc,
               size_t aStride, size_t bStride, size_t cStride)
{
    A += (size_t)blockIdx.z * aStride;
    B += (size_t)blockIdx.z * bStride;
    C += (size_t)blockIdx.z * cStride;
    GEMM_BODY(A, B, C, M, N, K, alpha, lda, ldb, ldc, 1)
}

// ---------------------------------------------------------------------------
// Fused conversion: X+PE -> [hi|lo]; k-weights -> [hi|hi]; v-weights -> hi
// ---------------------------------------------------------------------------
#define CONV_T1 (ROWS_X * D_MODEL)
#define CONV_T2 (NSTACK * D_MODEL)

__global__ void conv_inputs_kernel(const float* __restrict__ support,
                                   const float* __restrict__ queries,
                                   const float* __restrict__ k_w,
                                   const float* __restrict__ v_w)
{
    int e = blockIdx.x * blockDim.x + threadIdx.x;
    if (e < CONV_T1) {
        int n = e / (SEQ_LEN * D_MODEL);
        int rem = e % (SEQ_LEN * D_MODEL);
        int s = rem / D_MODEL, d = rem % D_MODEL;
        const float c = -9.210340371976184f / (float)D_MODEL;
        float div = expf((float)(2 * (d >> 1)) * c);
        float arg = (float)s * div;
        float pe = ((d & 1) ? cosf(arg) : sinf(arg)) * 0.1f;
        float x = ((n < N_SUPPORT) ? support[e]
                                   : queries[e - N_SUPPORT * SEQ_LEN * D_MODEL]) + pe;
        __nv_bfloat16 hi, lo; split2(x, hi, lo);
        int row = e / D_MODEL;
        __nv_bfloat16* o = g_Xhl + (size_t)row * KKP;
        o[d] = hi; o[D_MODEL + d] = lo;
    } else if (e < CONV_T1 + CONV_T2) {
        int e2 = e - CONV_T1;
        int j = e2 / D_MODEL, k = e2 % D_MODEL;
        int part = j / OUT_DIM, o = j % OUT_DIM;
        if (part < 2) {                    // k-weights: [hi | hi]
            float x = k_w[(size_t)o * TWO_D + part * D_MODEL + k];
            __nv_bfloat16 hi = __float2bfloat16(x);
            __nv_bfloat16* dst = g_Whl + (size_t)j * KKP;
            dst[k] = hi; dst[D_MODEL + k] = hi;
        } else {                           // v-weights: hi only
            int j2 = j - NK_HALF;
            float x = v_w[(size_t)o * TWO_D + (part & 1) * D_MODEL + k];
            g_Wv[(size_t)j2 * KVH + k] = __float2bfloat16(x);
        }
    }
}

// ---------------------------------------------------------------------------
// assemble tuple features + LayerNorm(k) -> hi bf16, v -> bf16.
// queries: k -> g_KQhl, v -> g_vs_q (row).
// support: k -> g_KShl, v -> g_Vhl transposed slice directly
//          (w = n/SHOT, j = (n%SHOT)*L_TUP + l; pad cols stay zero-init).
// ---------------------------------------------------------------------------
__global__ __launch_bounds__(256)
void assemble_kernel(const float* __restrict__ k_b, const float* __restrict__ v_b,
                     const float* __restrict__ ln_g, const float* __restrict__ ln_b)
{
    int rl = blockIdx.x;
    int n = rl / L_TUP, l = rl % L_TUP;
    int t0 = c_t0[l], t1 = c_t1[l];
    const float* P0 = g_P + (size_t)(n * SEQ_LEN + t0) * NSTACK;
    const float* P1 = g_P + (size_t)(n * SEQ_LEN + t1) * NSTACK;

    const bool isSup = (n < N_SUPPORT);
    __nv_bfloat16* kd;
    __nv_bfloat16* vq = nullptr;
    __nv_bfloat16* vtr = nullptr;          // transposed base for support
    if (isSup) {
        kd  = g_KShl + (size_t)(n * L_TUP + l) * KSC;
        int w = n / SHOT;
        int j = (n % SHOT) * L_TUP + l;    // 0..139
        vtr = g_Vhl + (size_t)w * OUT_DIM * KP2 + j;
    } else {
        int m = n - N_SUPPORT;
        kd  = g_KQhl + (size_t)(m * L_TUP + l) * KSC;
        vq  = g_vs_q + (size_t)(m * L_TUP + l) * OUT_DIM;
    }

    __shared__ float kbuf[OUT_DIM];
    float s = 0.f, s2 = 0.f;
    for (int o = threadIdx.x; o < OUT_DIM; o += blockDim.x) {
        float kv = P0[o] + P1[OUT_DIM + o] + k_b[o];
        kbuf[o] = kv; s += kv; s2 += kv * kv;
        float vv = P0[2 * OUT_DIM + o] + P1[3 * OUT_DIM + o] + v_b[o];
        if (isSup) vtr[(size_t)o * KP2] = __float2bfloat16(vv);
        else       vq[o] = __float2bfloat16(vv);
    }
    int lane = threadIdx.x & 31, wid = threadIdx.x >> 5;
    #pragma unroll
    for (int off = 16; off; off >>= 1) {
        s  += __shfl_xor_sync(0xffffffffu, s,  off);
        s2 += __shfl_xor_sync(0xffffffffu, s2, off);
    }
    __shared__ float ws[8], ws2[8], sm_mean, sm_rstd;
    if (lane == 0) { ws[wid] = s; ws2[wid] = s2; }
    __syncthreads();
    if (threadIdx.x == 0) {
        float S = 0.f, S2 = 0.f;
        #pragma unroll
        for (int w = 0; w < 8; w++) { S += ws[w]; S2 += ws2[w]; }
        float mean = S / (float)OUT_DIM;
        float var  = S2 / (float)OUT_DIM - mean * mean;
        sm_mean = mean; sm_rstd = rsqrtf(var + 1e-5f);
    }
    __syncthreads();
    float mean = sm_mean, rstd = sm_rstd;
    for (int o = threadIdx.x; o < OUT_DIM; o += blockDim.x) {
        float y = (kbuf[o] - mean) * rstd * ln_g[o] + ln_b[o];
        kd[o] = __float2bfloat16(y);
    }
}

// ---------------------------------------------------------------------------
// per-row blockwise softmax; writes hi-only attn (K=160) directly to g_Ahl.
// ---------------------------------------------------------------------------
__global__ __launch_bounds__(160)
void softmax_kernel()
{
    int row = blockIdx.x;
    int warp = threadIdx.x >> 5, lane = threadIdx.x & 31;
    const float* p = g_S + (size_t)row * ROWS_S + warp * SEG;
    float v[5]; float mx = -INFINITY;
    #pragma unroll
    for (int i = 0; i < 5; i++) {
        int c = lane + 32 * i;
        v[i] = (c < SEG) ? p[c] : -INFINITY;
        mx = fmaxf(mx, v[i]);
    }
    #pragma unroll
    for (int off = 16; off; off >>= 1)
        mx = fmaxf(mx, __shfl_xor_sync(0xffffffffu, mx, off));
    float sm = 0.f;
    #pragma unroll
    for (int i = 0; i < 5; i++) {
        int c = lane + 32 * i;
        v[i] = (c < SEG) ? expf(v[i] - mx) : 0.f;
        sm += v[i];
    }
    #pragma unroll
    for (int off = 16; off; off >>= 1)
        sm += __shfl_xor_sync(0xffffffffu, sm, off);
    float inv = 1.f / sm;

    __nv_bfloat16* a = g_Ahl + ((size_t)warp * ROWS_Q + row) * KP2;
    #pragma unroll
    for (int i = 0; i < 5; i++) {
        int c = lane + 32 * i;
        if (c < SEG)
            a[c] = __float2bfloat16(v[i] * inv);
    }
    if (lane < KP2 - SEG)
        a[SEG + lane] = __float2bfloat16(0.f);
}

// ---------------------------------------------------------------------------
// per-query Gram matrix + distances -> sim, ori  (bf16 inputs, uint4 loads)
// ---------------------------------------------------------------------------
__global__ __launch_bounds__(256)
void finalize_kernel(float* __restrict__ out)
{
    int q = blockIdx.x;
    const uint4* v8 = (const uint4*)(g_vs_q + (size_t)q * PLANE);
    const uint4* pp8[WAY];
    #pragma unroll
    for (int w = 0; w < WAY; w++)
        pp8[w] = (const uint4*)(g_proto + (size_t)w * ROWS_Q * OUT_DIM
                                + (size_t)q * PLANE);

    float acc[21];
    #pragma unroll
    for (int i = 0; i < 21; i++) acc[i] = 0.f;

    const int NV8 = PLANE / 8;                 // 4032
    for (int i = threadIdx.x; i < NV8; i += blockDim.x) {
        uint4 uv = v8[i];
        uint4 u0 = pp8[0][i], u1 = pp8[1][i], u2 = pp8[2][i],
              u3 = pp8[3][i], u4 = pp8[4][i];
        float fv[8], f0[8], f1[8], f2[8], f3[8], f4[8];
        #pragma unroll
        for (int h = 0; h < 4; h++) {
            float2 t;
            t = __bfloat1622float2(*(__nv_bfloat162*)((uint32_t*)&uv + h));
            fv[2*h] = t.x; fv[2*h+1] = t.y;
            t = __bfloat1622float2(*(__nv_bfloat162*)((uint32_t*)&u0 + h));
            f0[2*h] = t.x; f0[2*h+1] = t.y;
            t = __bfloat1622float2(*(__nv_bfloat162*)((uint32_t*)&u1 + h));
            f1[2*h] = t.x; f1[2*h+1] = t.y;
            t = __bfloat1622float2(*(__nv_bfloat162*)((uint32_t*)&u2 + h));
            f2[2*h] = t.x; f2[2*h+1] = t.y;
            t = __bfloat1622float2(*(__nv_bfloat162*)((uint32_t*)&u3 + h));
            f3[2*h] = t.x; f3[2*h+1] = t.y;
            t = __bfloat1622float2(*(__nv_bfloat162*)((uint32_t*)&u4 + h));
            f4[2*h] = t.x; f4[2*h+1] = t.y;
        }
        #pragma unroll
        for (int e = 0; e < 8; e++) {
            float vvv = fv[e];
            float a0 = f0[e], a1 = f1[e], a2 = f2[e], a3 = f3[e], a4 = f4[e];
            acc[0]  += a0 * a0;  acc[1]  += a0 * a1;  acc[2]  += a0 * a2;
            acc[3]  += a0 * a3;  acc[4]  += a0 * a4;
            acc[5]  += a1 * a1;  acc[6]  += a1 * a2;  acc[7]  += a1 * a3;
            acc[8]  += a1 * a4;
            acc[9]  += a2 * a2;  acc[10] += a2 * a3;  acc[11] += a2 * a4;
            acc[12] += a3 * a3;  acc[13] += a3 * a4;
            acc[14] += a4 * a4;
            acc[15] += vvv * a0; acc[16] += vvv * a1; acc[17] += vvv * a2;
            acc[18] += vvv * a3; acc[19] += vvv * a4;
            acc[20] += vvv * vvv;
        }
    }

    int lane = threadIdx.x & 31, wid = threadIdx.x >> 5;
    __shared__ float part[21][8];
    #pragma unroll
    for (int i = 0; i < 21; i++) {
        float a = acc[i];
        #pragma unroll
        for (int off = 16; off; off >>= 1)
            a += __shfl_xor_sync(0xffffffffu, a, off);
        if (lane == 0) part[i][wid] = a;
    }
    __syncthreads();
    __shared__ float tot[21];
    if (threadIdx.x < 21) {
        float sSum = 0.f;
        #pragma unroll
        for (int w = 0; w < 8; w++) sSum += part[threadIdx.x][w];
        tot[threadIdx.x] = sSum;
    }
    __syncthreads();
    if (threadIdx.x == 0) {
        float G[WAY][WAY];
        int t = 0;
        for (int a = 0; a < WAY; a++)
            for (int b = a; b < WAY; b++) { G[a][b] = tot[t]; G[b][a] = tot[t]; t++; }
        float D[WAY];
        for (int w = 0; w < WAY; w++) D[w] = tot[15 + w];
        float VV = tot[20];
        float nrm[WAY];
        for (int w = 0; w < WAY; w++) nrm[w] = sqrtf(G[w][w]);
        for (int a = 0; a < WAY; a++)
            for (int b = 0; b < WAY; b++)
                out[q * WAY * WAY + a * WAY + b] =
                    G[a][b] / fmaxf(nrm[a] * nrm[b], 1e-8f);
        for (int w = 0; w < WAY; w++)
            out[N_QUERIES * WAY * WAY + q * WAY + w] =
                -(VV - 2.f * D[w] + G[w][w]) / (float)L_TUP;
    }
}

// ---------------------------------------------------------------------------
// Launch
// ---------------------------------------------------------------------------
extern "C" void kernel_launch(void* const* d_in, const int* in_sizes, int n_in,
                              void* d_out, int out_size)
{
    const float* support = (const float*)d_in[0];
    const float* queries = (const float*)d_in[2];
    const float* k_w  = (const float*)d_in[3];
    const float* k_b  = (const float*)d_in[4];
    const float* v_w  = (const float*)d_in[5];
    const float* v_b  = (const float*)d_in[6];
    const float* ln_g = (const float*)d_in[7];
    const float* ln_b = (const float*)d_in[8];
    float* out = (float*)d_out;

    float *P, *S;
    __nv_bfloat16 *Xhl, *Whl, *Wv, *KQhl, *KShl, *Ahl, *Vhl, *proto;
    cudaGetSymbolAddress((void**)&Xhl,   g_Xhl);
    cudaGetSymbolAddress((void**)&Whl,   g_Whl);
    cudaGetSymbolAddress((void**)&Wv,    g_Wv);
    cudaGetSymbolAddress((void**)&P,     g_P);
    cudaGetSymbolAddress((void**)&KQhl,  g_KQhl);
    cudaGetSymbolAddress((void**)&KShl,  g_KShl);
    cudaGetSymbolAddress((void**)&S,     g_S);
    cudaGetSymbolAddress((void**)&Ahl,   g_Ahl);
    cudaGetSymbolAddress((void**)&Vhl,   g_Vhl);
    cudaGetSymbolAddress((void**)&proto, g_proto);

    // 1. fused PE + hi/lo input conversion + weight conversion (one launch)
    {
        int total = CONV_T1 + CONV_T2;
        conv_inputs_kernel<<<(total + 255) / 256, 256>>>(support, queries, k_w, v_w);
    }
    // 2. fused projection: z=0 k-part (K=4096, 2-term), z=1 v-part (K=2048, hi)
    {
        dim3 grid(NK_HALF / 128, (ROWS_X + 127) / 128, 2);
        gemm_proj<<<grid, 256>>>(Xhl, Whl, Wv, P);
    }
    // 3. assemble -> KQhl/KShl (hi bf16) + vs_q + Vhl (transposed support v)
    assemble_kernel<<<N_TOTAL * L_TUP, 256>>>(k_b, v_b, ln_g, ln_b);
    // 4. scores = ks_q @ ks_s^T / sqrt(OUT_DIM)  [5600, 700], K=1152 (hi-only)
    {
        dim3 grid((ROWS_S + 127) / 128, (ROWS_Q + 127) / 128, 1);
        gemm_f32<<<grid, 256>>>(KQhl, KShl, S, ROWS_Q, ROWS_S, KSC,
                                1.0f / sqrtf((float)OUT_DIM),
                                KSC, KSC, ROWS_S);
    }
    // 5. softmax -> g_Ahl (hi-only) directly
    softmax_kernel<<<ROWS_Q, 160>>>();
    // 6. proto[w] = attn_w @ vs_w  [5600, 1152], K=160 — batched, bf16 out
    {
        dim3 grid(OUT_DIM / 128, (ROWS_Q + 127) / 128, WAY);
        gemm_bf16<<<grid, 256>>>(Ahl, Vhl, proto,
                                 ROWS_Q, OUT_DIM, KP2, 1.0f,
                                 KP2, KP2, OUT_DIM,
                                 (size_t)ROWS_Q * KP2,
                                 (size_t)OUT_DIM * KP2,
                                 (size_t)ROWS_Q * OUT_DIM);
    }
    // 7. finalize
    finalize_kernel<<<N_QUERIES, 256>>>(out);
}